// round 7
// baseline (speedup 1.0000x reference)
#include <cuda_runtime.h>
#include <cuda_bf16.h>
#include <cstdint>

// ----------------------------------------------------------------------------
// BaseGR hetero-SAGE on GB300 — R7.
// vs R6: prediction GEMM switched from bf16 3-split HMMA to int8 Ozaki-style
// 2-digit fixed point (4 digit-product IMMA m16n8k32, exact s32 accum,
// per-row scales). 256 IMMA vs 384 HMMA per tile -> ~33% faster pred.
// ----------------------------------------------------------------------------

#define NG 5000
#define NU 100000
#define NI 20000
#define H 128
#define HH (H*H)
#define E_UG 300000
#define E_UI 600000
#define E_GI 200000

// ---------------- fp32 scratch ----------------
#define OF_HU  0
#define OF_HI  (OF_HU  + NU*H)
#define OF_HU1 (OF_HI  + NI*H)
#define OF_HI1 (OF_HU1 + NU*H)
#define OF_WC  (OF_HI1 + NI*H)
#define OF_BC  (OF_WC  + 3*HH)
#define OF_REP (OF_BC  + 4*H)
#define OF_SA  (OF_REP + NG*H)
#define OF_SB  (OF_SA  + NG)
#define F_TOTAL (OF_SB + NI)
__device__ float g_f[F_TOTAL];

// ---------------- bf16 scratch (hi plane then lo plane for each) -------------
#define OB_HUe 0
#define OB_HIe (OB_HUe + 2*NU*H)
#define OB_AIU (OB_HIe + 2*NI*H)
#define OB_AUI (OB_AIU + 2*NU*H)
#define OB_AUG (OB_AUI + 2*NI*H)
#define OB_AIG (OB_AUG + 2*NG*H)
#define OB_HG1 (OB_AIG + 2*NG*H)
#define OB_BUG (OB_HG1 + 2*NG*H)
#define OB_BIG (OB_BUG + 2*NG*H)
#define OB_W   (OB_BIG + 2*NG*H)
#define B_TOTAL (OB_W + 18*HH)
__device__ __nv_bfloat16 g_bf[B_TOTAL];

// ---------------- int8 digit planes (pred GEMM) -------------------------------
#define QA1 0
#define QA0 (QA1 + NG*H)
#define QB1 (QA0 + NG*H)
#define QB0 (QB1 + NI*H)
#define Q_TOTAL (QB0 + NI*H)
__device__ int8_t g_q[Q_TOTAL];

// weight slots in OB_W (each slot: hi HH then lo HH)
#define SL_W1L3 0
#define SL_WC0  1
#define SL_W1L2 2
#define SL_WC1  3
#define SL_W1L0 4
#define SL_W1L5 5
#define SL_W2L0 6
#define SL_WC2  7
#define SL_W2L5 8

// ---------------- int scratch ----------------
#define OI_CNT_G1 0
#define OI_CNT_G2 (OI_CNT_G1 + NG)
#define OI_CNT_U  (OI_CNT_G2 + NG)
#define OI_CNT_I  (OI_CNT_U  + NU)
#define CNT_TOTAL (OI_CNT_I  + NI)
#define OI_RP_G1  CNT_TOTAL
#define OI_RP_G2  (OI_RP_G1 + NG + 1)
#define OI_RP_U   (OI_RP_G2 + NG + 1)
#define OI_RP_I   (OI_RP_U  + NU + 1)
#define OI_CUR_G1 (OI_RP_I  + NI + 1)
#define OI_CUR_G2 (OI_CUR_G1 + NG)
#define OI_CUR_U  (OI_CUR_G2 + NG)
#define OI_CUR_I  (OI_CUR_U  + NU)
#define OI_COL_G1 (OI_CUR_I  + NI)
#define OI_COL_G2 (OI_COL_G1 + E_UG)
#define OI_COL_U  (OI_COL_G2 + E_GI)
#define OI_COL_I  (OI_COL_U  + E_UI)
#define I_TOTAL   (OI_COL_I  + E_UI)
__device__ int g_i[I_TOTAL];

// ======================= helpers =============================================
__device__ __forceinline__ uint32_t smem_u32(const void* p) {
    uint32_t a;
    asm("{ .reg .u64 t; cvta.to.shared.u64 t, %1; cvt.u32.u64 %0, t; }"
        : "=r"(a) : "l"(p));
    return a;
}

#define LDSM4(r, addr) \
    asm volatile("ldmatrix.sync.aligned.m8n8.x4.shared.b16 {%0,%1,%2,%3}, [%4];" \
                 : "=r"((r)[0]), "=r"((r)[1]), "=r"((r)[2]), "=r"((r)[3]) \
                 : "r"(addr))

#define MMA_BF16(c, a, b0, b1) \
    asm volatile("mma.sync.aligned.m16n8k16.row.col.f32.bf16.bf16.f32 " \
                 "{%0,%1,%2,%3}, {%4,%5,%6,%7}, {%8,%9}, {%0,%1,%2,%3};" \
                 : "+f"((c)[0]), "+f"((c)[1]), "+f"((c)[2]), "+f"((c)[3]) \
                 : "r"((a)[0]), "r"((a)[1]), "r"((a)[2]), "r"((a)[3]), \
                   "r"(b0), "r"(b1))

#define MMA_S8(c, a, b0, b1) \
    asm volatile("mma.sync.aligned.m16n8k32.row.col.s32.s8.s8.s32 " \
                 "{%0,%1,%2,%3}, {%4,%5,%6,%7}, {%8,%9}, {%0,%1,%2,%3};" \
                 : "+r"((c)[0]), "+r"((c)[1]), "+r"((c)[2]), "+r"((c)[3]) \
                 : "r"((a)[0]), "r"((a)[1]), "r"((a)[2]), "r"((a)[3]), \
                   "r"(b0), "r"(b1))

#define CPA16(dst, src, sz) \
    asm volatile("cp.async.cg.shared.global [%0], [%1], 16, %2;" \
                 :: "r"(dst), "l"(src), "r"(sz))
#define CP_COMMIT() asm volatile("cp.async.commit_group;" ::: "memory")
#define CP_WAIT0()  asm volatile("cp.async.wait_group 0;" ::: "memory")
#define CP_WAIT1()  asm volatile("cp.async.wait_group 1;" ::: "memory")

__device__ __forceinline__ void bfsplit2(float v0, float v1, uint32_t& h, uint32_t& l)
{
    __nv_bfloat16 h0 = __float2bfloat16(v0), h1 = __float2bfloat16(v1);
    float r0 = v0 - __bfloat162float(h0);
    float r1 = v1 - __bfloat162float(h1);
    __nv_bfloat16 l0 = __float2bfloat16(r0), l1 = __float2bfloat16(r1);
    h = (uint32_t)__bfloat16_as_ushort(h0) | ((uint32_t)__bfloat16_as_ushort(h1) << 16);
    l = (uint32_t)__bfloat16_as_ushort(l0) | ((uint32_t)__bfloat16_as_ushort(l1) << 16);
}

// ======================= merged gather (fp32 + bf16 hi/lo) ===================
__global__ void k_gather2m(const float* __restrict__ emb_u, const int* __restrict__ x_u,
                           const float* __restrict__ emb_i, const int* __restrict__ x_i,
                           float* __restrict__ fb, __nv_bfloat16* __restrict__ bbuf)
{
    int t = blockIdx.x * blockDim.x + threadIdx.x;
    const float* emb; const int* x;
    float* outf; __nv_bfloat16* hb; int loOff; int r;
    if (t < NU * 32) {
        emb = emb_u; x = x_u; outf = fb + OF_HU; hb = bbuf + OB_HUe; loOff = NU * H;
        r = t >> 5;
    } else if (t < (NU + NI) * 32) {
        t -= NU * 32;
        emb = emb_i; x = x_i; outf = fb + OF_HI; hb = bbuf + OB_HIe; loOff = NI * H;
        r = t >> 5;
    } else return;
    int c = t & 31;
    float4 v = ((const float4*)emb)[(size_t)x[r] * 32 + c];
    ((float4*)outf)[(size_t)r * 32 + c] = v;
    uint32_t h0, l0, h1, l1;
    bfsplit2(v.x, v.y, h0, l0);
    bfsplit2(v.z, v.w, h1, l1);
    size_t o = ((size_t)r * H + c * 4) >> 1;
    ((uint32_t*)hb)[o]     = h0;
    ((uint32_t*)hb)[o + 1] = h1;
    ((uint32_t*)(hb + loOff))[o]     = l0;
    ((uint32_t*)(hb + loOff))[o + 1] = l1;
}

// ======================= CSR build (merged) ==================================
__global__ void k_count_all(const int* __restrict__ ug_dst, const int* __restrict__ gi_src,
                            const int* __restrict__ ui_src, const int* __restrict__ ui_dst,
                            int* __restrict__ ib)
{
    int t = blockIdx.x * blockDim.x + threadIdx.x;
    if (t < E_UG) atomicAdd(&ib[OI_CNT_G1 + ug_dst[t]], 1);
    else if (t < E_UG + E_GI) atomicAdd(&ib[OI_CNT_G2 + gi_src[t - E_UG]], 1);
    else if (t < E_UG + E_GI + E_UI) atomicAdd(&ib[OI_CNT_U + ui_src[t - E_UG - E_GI]], 1);
    else if (t < E_UG + E_GI + 2*E_UI) atomicAdd(&ib[OI_CNT_I + ui_dst[t - E_UG - E_GI - E_UI]], 1);
}

__global__ void k_scan4(int* __restrict__ ib)
{
    const int* cnt; int* rp; int* cur; int n;
    switch (blockIdx.x) {
        case 0: cnt = ib + OI_CNT_G1; rp = ib + OI_RP_G1; cur = ib + OI_CUR_G1; n = NG; break;
        case 1: cnt = ib + OI_CNT_G2; rp = ib + OI_RP_G2; cur = ib + OI_CUR_G2; n = NG; break;
        case 2: cnt = ib + OI_CNT_U;  rp = ib + OI_RP_U;  cur = ib + OI_CUR_U;  n = NU; break;
        default: cnt = ib + OI_CNT_I; rp = ib + OI_RP_I;  cur = ib + OI_CUR_I;  n = NI; break;
    }
    __shared__ int ssum[1024];
    const int t = threadIdx.x;
    const int chunk = (n + 1023) / 1024;
    int beg = t * chunk;
    int end = beg + chunk; if (end > n) end = n;
    if (beg > n) beg = n;
    int s = 0;
    for (int i = beg; i < end; i++) s += cnt[i];
    ssum[t] = s;
    __syncthreads();
    for (int off = 1; off < 1024; off <<= 1) {
        int v = (t >= off) ? ssum[t - off] : 0;
        __syncthreads();
        ssum[t] += v;
        __syncthreads();
    }
    int prefix = (t == 0) ? 0 : ssum[t - 1];
    for (int i = beg; i < end; i++) {
        rp[i]  = prefix;
        cur[i] = prefix;
        prefix += cnt[i];
    }
    if (t == 1023) rp[n] = ssum[1023];
}

__global__ void k_bucket_all(const int* __restrict__ ug_src, const int* __restrict__ ug_dst,
                             const int* __restrict__ ui_src, const int* __restrict__ ui_dst,
                             const int* __restrict__ gi_src, const int* __restrict__ gi_dst,
                             int* __restrict__ ib)
{
    int t = blockIdx.x * blockDim.x + threadIdx.x;
    if (t < E_UG) {
        int p = atomicAdd(&ib[OI_CUR_G1 + ug_dst[t]], 1);
        ib[OI_COL_G1 + p] = ug_src[t];
    } else if (t < E_UG + E_GI) {
        int e = t - E_UG;
        int p = atomicAdd(&ib[OI_CUR_G2 + gi_src[e]], 1);
        ib[OI_COL_G2 + p] = gi_dst[e];
    } else if (t < E_UG + E_GI + E_UI) {
        int e = t - E_UG - E_GI;
        int p = atomicAdd(&ib[OI_CUR_U + ui_src[e]], 1);
        ib[OI_COL_U + p] = ui_dst[e];
    } else if (t < E_UG + E_GI + 2*E_UI) {
        int e = t - E_UG - E_GI - E_UI;
        int p = atomicAdd(&ib[OI_CUR_I + ui_dst[e]], 1);
        ib[OI_COL_I + p] = ui_src[e];
    }
}

// ======================= segment mean -> bf16 hi/lo ==========================
__device__ __forceinline__ void agg_row(const int* __restrict__ rp, const int* __restrict__ col,
                                        const float* __restrict__ feat,
                                        __nv_bfloat16* __restrict__ hb, int loOff,
                                        int row, int lane)
{
    int beg = rp[row], end = rp[row + 1];
    float4 acc = make_float4(0.f, 0.f, 0.f, 0.f);
    const float4* fv = (const float4*)feat;
    int e = beg;
    for (; e + 4 <= end; e += 4) {
        int s0 = __ldg(&col[e + 0]);
        int s1 = __ldg(&col[e + 1]);
        int s2 = __ldg(&col[e + 2]);
        int s3 = __ldg(&col[e + 3]);
        float4 v0 = __ldg(&fv[(size_t)s0 * 32 + lane]);
        float4 v1 = __ldg(&fv[(size_t)s1 * 32 + lane]);
        float4 v2 = __ldg(&fv[(size_t)s2 * 32 + lane]);
        float4 v3 = __ldg(&fv[(size_t)s3 * 32 + lane]);
        acc.x += v0.x + v1.x + v2.x + v3.x;
        acc.y += v0.y + v1.y + v2.y + v3.y;
        acc.z += v0.z + v1.z + v2.z + v3.z;
        acc.w += v0.w + v1.w + v2.w + v3.w;
    }
    for (; e < end; e++) {
        int s = __ldg(&col[e]);
        float4 v = __ldg(&fv[(size_t)s * 32 + lane]);
        acc.x += v.x; acc.y += v.y; acc.z += v.z; acc.w += v.w;
    }
    float inv = (end > beg) ? 1.f / (float)(end - beg) : 0.f;
    acc.x *= inv; acc.y *= inv; acc.z *= inv; acc.w *= inv;
    uint32_t h0, l0, h1, l1;
    bfsplit2(acc.x, acc.y, h0, l0);
    bfsplit2(acc.z, acc.w, h1, l1);
    size_t o = ((size_t)row * H + lane * 4) >> 1;
    ((uint32_t*)hb)[o]     = h0;
    ((uint32_t*)hb)[o + 1] = h1;
    ((uint32_t*)(hb + loOff))[o]     = l0;
    ((uint32_t*)(hb + loOff))[o + 1] = l1;
}

__global__ void k_agg_all(const int* __restrict__ ib, const float* __restrict__ fb,
                          __nv_bfloat16* __restrict__ bb)
{
    int w = (int)((blockIdx.x * blockDim.x + threadIdx.x) >> 5);
    int lane = threadIdx.x & 31;
    if (w < NU)
        agg_row(ib + OI_RP_U, ib + OI_COL_U, fb + OF_HI, bb + OB_AIU, NU*H, w, lane);
    else if (w < NU + NI)
        agg_row(ib + OI_RP_I, ib + OI_COL_I, fb + OF_HU, bb + OB_AUI, NI*H, w - NU, lane);
    else if (w < NU + NI + NG)
        agg_row(ib + OI_RP_G1, ib + OI_COL_G1, fb + OF_HU, bb + OB_AUG, NG*H, w - NU - NI, lane);
    else if (w < NU + NI + 2*NG)
        agg_row(ib + OI_RP_G2, ib + OI_COL_G2, fb + OF_HI, bb + OB_AIG, NG*H, w - NU - NI - NG, lane);
}

__global__ void k_agg_all2(const int* __restrict__ ib, const float* __restrict__ fb,
                           __nv_bfloat16* __restrict__ bb)
{
    int w = (int)((blockIdx.x * blockDim.x + threadIdx.x) >> 5);
    int lane = threadIdx.x & 31;
    if (w < NG)
        agg_row(ib + OI_RP_G1, ib + OI_COL_G1, fb + OF_HU1, bb + OB_BUG, NG*H, w, lane);
    else if (w < 2*NG)
        agg_row(ib + OI_RP_G2, ib + OI_COL_G2, fb + OF_HI1, bb + OB_BIG, NG*H, w - NG, lane);
}

// ======================= weight prep =========================================
__global__ void k_wcomb(const float* __restrict__ W1r, const float* __restrict__ b1,
                        const float* __restrict__ W2r, const float* __restrict__ b2)
{
    int i = blockIdx.x * blockDim.x + threadIdx.x;
    float* Wc = g_f + OF_WC;
    float* bc = g_f + OF_BC;
    if (i < HH) {
        Wc[0*HH + i] = W1r[1*HH + i] + W1r[3*HH + i];
        Wc[1*HH + i] = W1r[2*HH + i] + W1r[4*HH + i];
        Wc[2*HH + i] = W2r[0*HH + i] + W2r[5*HH + i];
    }
    if (i < H) {
        bc[0*H + i] = b1[1*H + i] + b1[3*H + i];
        bc[1*H + i] = b1[2*H + i] + b1[4*H + i];
        bc[2*H + i] = b1[0*H + i] + b1[5*H + i];
        bc[3*H + i] = b2[0*H + i] + b2[5*H + i];
    }
}

__global__ void __launch_bounds__(256)
k_splitW(const float* __restrict__ W1l, const float* __restrict__ W2l,
         const float* __restrict__ Wc, __nv_bfloat16* __restrict__ dst9)
{
    const float* src;
    switch (blockIdx.z) {
        case 0: src = W1l + 3*HH; break;
        case 1: src = Wc  + 0*HH; break;
        case 2: src = W1l + 2*HH; break;
        case 3: src = Wc  + 1*HH; break;
        case 4: src = W1l + 0*HH; break;
        case 5: src = W1l + 5*HH; break;
        case 6: src = W2l + 0*HH; break;
        case 7: src = Wc  + 2*HH; break;
        default: src = W2l + 5*HH; break;
    }
    __nv_bfloat16* hi = dst9 + (size_t)blockIdx.z * 2 * HH;
    __nv_bfloat16* lo = hi + HH;
    __shared__ float t[32][33];
    int nblk = blockIdx.x * 32;
    int kblk = blockIdx.y * 32;
    int tx = threadIdx.x, ty = threadIdx.y;
#pragma unroll
    for (int i = ty; i < 32; i += 8)
        t[i][tx] = src[(size_t)(kblk + i) * H + nblk + tx];
    __syncthreads();
#pragma unroll
    for (int i = ty; i < 32; i += 8) {
        float x = t[tx][i];
        __nv_bfloat16 h = __float2bfloat16(x);
        size_t o = (size_t)(nblk + i) * H + kblk + tx;
        hi[o] = h;
        lo[o] = __float2bfloat16(x - __bfloat162float(h));
    }
}

// ======================= int8 quantization (pred operands) ===================
// REP [NG][128] fp32 -> two s8 digit planes + per-row scale. One warp per row.
__global__ void k_quantA(const float* __restrict__ rep,
                         int8_t* __restrict__ a1p, int8_t* __restrict__ a0p,
                         float* __restrict__ sA)
{
    int w = (int)((blockIdx.x * blockDim.x + threadIdx.x) >> 5);
    int lane = threadIdx.x & 31;
    if (w >= NG) return;
    float4 v = ((const float4*)(rep + (size_t)w * H))[lane];
    float mx = fmaxf(fmaxf(fabsf(v.x), fabsf(v.y)), fmaxf(fabsf(v.z), fabsf(v.w)));
#pragma unroll
    for (int off = 16; off; off >>= 1)
        mx = fmaxf(mx, __shfl_xor_sync(0xffffffffu, mx, off));
    float inv = (mx > 0.f) ? 32512.f / mx : 0.f;
    float fv[4] = { v.x, v.y, v.z, v.w };
    uint32_t p1 = 0, p0 = 0;
#pragma unroll
    for (int c = 0; c < 4; c++) {
        int a = __float2int_rn(fv[c] * inv);
        int hi8 = (a + 128) >> 8;
        int lo8 = a - (hi8 << 8);
        p1 |= (uint32_t)(hi8 & 0xff) << (8 * c);
        p0 |= (uint32_t)(lo8 & 0xff) << (8 * c);
    }
    ((uint32_t*)a1p)[(size_t)w * 32 + lane] = p1;
    ((uint32_t*)a0p)[(size_t)w * 32 + lane] = p0;
    if (lane == 0) sA[w] = (mx > 0.f) ? mx / 32512.f : 0.f;
}

// pred_W [H][NI] fp32 -> transposed s8 digit planes [NI][128] + per-col scale.
__global__ void __launch_bounds__(256)
k_quantB(const float* __restrict__ W,
         int8_t* __restrict__ b1p, int8_t* __restrict__ b0p,
         float* __restrict__ sB)
{
    __shared__ float s[128][33];
    const int tid = threadIdx.x;
    const int nblk = blockIdx.x * 32;
    for (int i = tid; i < 4096; i += 256) {
        int k = i >> 5, n = i & 31;
        s[k][n] = W[(size_t)k * NI + nblk + n];
    }
    __syncthreads();
    int wid = tid >> 5, lane = tid & 31;
    int n = wid * 4 + (lane >> 3);
    int j = lane & 7;
    float mx = 0.f;
#pragma unroll
    for (int q = 0; q < 16; q++) mx = fmaxf(mx, fabsf(s[j * 16 + q][n]));
    mx = fmaxf(mx, __shfl_xor_sync(0xffffffffu, mx, 1, 8));
    mx = fmaxf(mx, __shfl_xor_sync(0xffffffffu, mx, 2, 8));
    mx = fmaxf(mx, __shfl_xor_sync(0xffffffffu, mx, 4, 8));
    float inv = (mx > 0.f) ? 32512.f / mx : 0.f;
    int ng = nblk + n;
#pragma unroll
    for (int q = 0; q < 16; q += 4) {
        int k = j * 16 + q;
        uint32_t p1 = 0, p0 = 0;
#pragma unroll
        for (int c = 0; c < 4; c++) {
            int a = __float2int_rn(s[k + c][n] * inv);
            int hi8 = (a + 128) >> 8;
            int lo8 = a - (hi8 << 8);
            p1 |= (uint32_t)(hi8 & 0xff) << (8 * c);
            p0 |= (uint32_t)(lo8 & 0xff) << (8 * c);
        }
        *(uint32_t*)(b1p + (size_t)ng * H + k) = p1;
        *(uint32_t*)(b0p + (size_t)ng * H + k) = p0;
    }
    if (j == 0) sB[ng] = (mx > 0.f) ? mx / 32512.f : 0.f;
}

// ======================= common GEMM constants ===============================
#define PK   136
#define ROWB (PK * 2)          // 272 B per row (bf16 tiles)
#define TILEB (128 * ROWB)     // 34816 B
#define HTILE (64 * ROWB)      // 17408 B

#define GEMM_RELU 1
#define GEMM_BF16 2

// ======================= HMMA layer-2 GEMM (multi-term, small) ===============
struct GemmArgs {
    const __nv_bfloat16* Ah[3];
    const __nv_bfloat16* Al[3];
    const __nv_bfloat16* Wh[3];
    const float* bias;
    float* Cf;
    __nv_bfloat16* Cb;
    int M, nterms, flags, loOff;
};

#define SMEM_GH (4 * TILEB)    // 139264

__global__ void __launch_bounds__(256, 1)
k_gemm_h(GemmArgs g)
{
    extern __shared__ char sm[];
    const int tid  = threadIdx.x;
    const int wid  = tid >> 5;
    const int lane = tid & 31;
    const int wm   = wid >> 1;
    const int wn   = wid & 1;
    const int m0   = blockIdx.x * 128;

    const uint32_t sbase  = smem_u32(sm);
    const uint32_t a_loff = (uint32_t)(lane & 15) * ROWB + (uint32_t)(lane >> 4) * 16;
    const uint32_t b_loff = (uint32_t)(((lane >> 4) * 8) + (lane & 7)) * ROWB
                          + (uint32_t)((lane >> 3) & 1) * 16;

    float c[2][8][4];
#pragma unroll
    for (int i = 0; i < 2; i++)
#pragma unroll
        for (int j = 0; j < 8; j++)
#pragma unroll
            for (int q = 0; q < 4; q++) c[i][j][q] = 0.f;

#pragma unroll 1
    for (int t = 0; t < g.nterms; t++) {
        const uint4* wh = (const uint4*)g.Wh[t];
        const uint4* wl = (const uint4*)(g.Wh[t] + HH);
        const uint4* ah = (const uint4*)g.Ah[t];
        const uint4* al = (const uint4*)g.Al[t];
#pragma unroll 4
        for (int i = tid; i < 2048; i += 256) {
            int row = i >> 4, cq = i & 15;
            uint32_t so = (uint32_t)row * ROWB + cq * 16;
            *(uint4*)(sm + 0*TILEB + so) = __ldg(&wh[row * 16 + cq]);
            *(uint4*)(sm + 1*TILEB + so) = __ldg(&wl[row * 16 + cq]);
            uint4 va = make_uint4(0,0,0,0), vb = va;
            if (m0 + row < g.M) {
                size_t gi = (size_t)(m0 + row) * 16 + cq;
                va = __ldg(&ah[gi]);
                vb = __ldg(&al[gi]);
            }
            *(uint4*)(sm + 2*TILEB + so) = va;
            *(uint4*)(sm + 3*TILEB + so) = vb;
        }
        __syncthreads();
#pragma unroll 1
        for (int sp = 0; sp < 3; sp++) {
            uint32_t aB = sbase + (sp == 2 ? 3*TILEB : 2*TILEB)
                        + (uint32_t)wm * 32 * ROWB + a_loff;
            uint32_t bB = sbase + (sp == 1 ? 1*TILEB : 0)
                        + (uint32_t)wn * 64 * ROWB + b_loff;
#pragma unroll
            for (int ks = 0; ks < 8; ks++) {
                uint32_t a[2][4], b[4][4];
                LDSM4(a[0], aB + ks * 32);
                LDSM4(a[1], aB + ks * 32 + 16 * ROWB);
#pragma unroll
                for (int q = 0; q < 4; q++)
                    LDSM4(b[q], bB + ks * 32 + q * 16 * ROWB);
#pragma unroll
                for (int ma = 0; ma < 2; ma++)
#pragma unroll
                    for (int na = 0; na < 8; na++)
                        MMA_BF16(c[ma][na], a[ma],
                                 b[na >> 1][(na & 1) * 2], b[na >> 1][(na & 1) * 2 + 1]);
            }
        }
        __syncthreads();
    }

    const int gid = lane >> 2;
    const int tq  = (lane & 3) * 2;
    const bool relu = (g.flags & GEMM_RELU) != 0;
    const bool bfo  = (g.flags & GEMM_BF16) != 0;
#pragma unroll
    for (int ma = 0; ma < 2; ma++) {
#pragma unroll
        for (int na = 0; na < 8; na++) {
            int mrow = m0 + wm * 32 + ma * 16 + gid;
            int ncol = wn * 64 + na * 8 + tq;
            float2 bv = *(const float2*)(g.bias + ncol);
#pragma unroll
            for (int hrow = 0; hrow < 2; hrow++) {
                int mr = mrow + hrow * 8;
                if (mr >= g.M) continue;
                float v0 = c[ma][na][hrow*2 + 0] + bv.x;
                float v1 = c[ma][na][hrow*2 + 1] + bv.y;
                if (relu) { v0 = fmaxf(v0, 0.f); v1 = fmaxf(v1, 0.f); }
                if (bfo) {
                    uint32_t hw, lw;
                    bfsplit2(v0, v1, hw, lw);
                    *(uint32_t*)(g.Cb + (size_t)mr * H + ncol) = hw;
                    *(uint32_t*)(g.Cb + (size_t)g.loOff + (size_t)mr * H + ncol) = lw;
                } else {
                    *(float2*)(g.Cf + (size_t)mr * H + ncol) = make_float2(v0, v1);
                }
            }
        }
    }
}

// ======================= persistent layer-1 GEMM =============================
struct LJob {
    const __nv_bfloat16* Ah0; const __nv_bfloat16* Al0;
    const __nv_bfloat16* Ah1; const __nv_bfloat16* Al1;
    const __nv_bfloat16* Wh0; const __nv_bfloat16* Wh1;
    const float* bias;
    float* Cf;
    __nv_bfloat16* Cb;
    int loOff, M, ntiles, ctaBase, nctas, flags;
};
struct LJob3 { LJob j[3]; };

#define SMEM_GL (4 * TILEB + 4 * HTILE)   // 208896

__device__ __forceinline__ void loadA64(uint32_t dst, const uint4* ah, const uint4* al,
                                        int m0_, int M, int tid)
{
#pragma unroll 2
    for (int i = tid; i < 1024; i += 256) {
        int row = i >> 4, cq = i & 15;
        int gr = m0_ + row;
        int sz = (gr < M) ? 16 : 0;
        if (gr >= M) gr = M - 1;
        uint32_t so = dst + (uint32_t)row * ROWB + cq * 16;
        CPA16(so,         ah + (size_t)gr * 16 + cq, sz);
        CPA16(so + HTILE, al + (size_t)gr * 16 + cq, sz);
    }
}

__global__ void __launch_bounds__(256, 1)
k_gemm_l(LJob3 js)
{
    extern __shared__ char sm[];
    const int tid  = threadIdx.x;
    const int wid  = tid >> 5;
    const int lane = tid & 31;
    const int wm   = wid >> 2;
    const int wn   = wid & 3;

    int ji = (blockIdx.x >= (uint32_t)js.j[2].ctaBase) ? 2
           : (blockIdx.x >= (uint32_t)js.j[1].ctaBase) ? 1 : 0;
    const LJob g = js.j[ji];
    const int idx = blockIdx.x - g.ctaBase;
    const int beg = (int)((long long)idx * g.ntiles / g.nctas);
    const int end = (int)((long long)(idx + 1) * g.ntiles / g.nctas);
    if (beg >= end) return;

    const uint32_t sbase = smem_u32(sm);
    const uint32_t sA    = sbase + 4 * TILEB;

    {
        const uint4* wsrc0 = (const uint4*)g.Wh0;
        const uint4* wsrc1 = (const uint4*)(g.Wh0 + HH);
        const uint4* wsrc2 = (const uint4*)g.Wh1;
        const uint4* wsrc3 = (const uint4*)(g.Wh1 + HH);
#pragma unroll 4
        for (int i = tid; i < 8192; i += 256) {
            int tl = i >> 11;
            int row = (i >> 4) & 127;
            int cq = i & 15;
            const uint4* src = (tl == 0) ? wsrc0 : (tl == 1) ? wsrc1 : (tl == 2) ? wsrc2 : wsrc3;
            CPA16(sbase + (uint32_t)tl * TILEB + (uint32_t)row * ROWB + cq * 16,
                  src + (size_t)row * 16 + cq, 16);
        }
    }
    loadA64(sA, (const uint4*)g.Ah0, (const uint4*)g.Al0, beg * 64, g.M, tid);
    CP_COMMIT();

    const uint32_t a_loff = (uint32_t)(lane & 15) * ROWB + (uint32_t)(lane >> 4) * 16;
    const uint32_t b_loff = (uint32_t)(((lane >> 4) * 8) + (lane & 7)) * ROWB
                          + (uint32_t)((lane >> 3) & 1) * 16;
    const int gid = lane >> 2;
    const int tq  = (lane & 3) * 2;
    const bool relu = (g.flags & GEMM_RELU) != 0;
    const bool bfo  = (g.flags & GEMM_BF16) != 0;

    float c[2][4][4];
    const int nit = (end - beg) * 2;
    int buf = 0;

#pragma unroll 1
    for (int it = 0; it < nit; it++) {
        const int tile = beg + (it >> 1);
        const int term = it & 1;
        if (it + 1 < nit) {
            int ntile = beg + ((it + 1) >> 1);
            int nterm = (it + 1) & 1;
            const uint4* ah = (const uint4*)(nterm ? g.Ah1 : g.Ah0);
            const uint4* al = (const uint4*)(nterm ? g.Al1 : g.Al0);
            loadA64(sA + (uint32_t)(buf ^ 1) * 2 * HTILE, ah, al, ntile * 64, g.M, tid);
            CP_COMMIT();
            CP_WAIT1();
        } else {
            CP_WAIT0();
        }
        __syncthreads();

        if (term == 0) {
#pragma unroll
            for (int i = 0; i < 2; i++)
#pragma unroll
                for (int j = 0; j < 4; j++)
#pragma unroll
                    for (int q = 0; q < 4; q++) c[i][j][q] = 0.f;
        }

        const uint32_t curA = sA + (uint32_t)buf * 2 * HTILE;
        const uint32_t wBase = sbase + (uint32_t)term * 2 * TILEB;
#pragma unroll 1
        for (int sp = 0; sp < 3; sp++) {
            uint32_t aB = curA + (sp == 2 ? HTILE : 0) + (uint32_t)wm * 32 * ROWB + a_loff;
            uint32_t bB = wBase + (sp == 1 ? TILEB : 0) + (uint32_t)wn * 32 * ROWB + b_loff;
#pragma unroll
            for (int ks = 0; ks < 8; ks++) {
                uint32_t a[2][4], b[2][4];
                LDSM4(a[0], aB + ks * 32);
                LDSM4(a[1], aB + ks * 32 + 16 * ROWB);
                LDSM4(b[0], bB + ks * 32);
                LDSM4(b[1], bB + ks * 32 + 16 * ROWB);
#pragma unroll
                for (int ma = 0; ma < 2; ma++)
#pragma unroll
                    for (int na = 0; na < 4; na++)
                        MMA_BF16(c[ma][na], a[ma],
                                 b[na >> 1][(na & 1) * 2], b[na >> 1][(na & 1) * 2 + 1]);
            }
        }

        if (term == 1) {
            int m0_ = tile * 64;
#pragma unroll
            for (int ma = 0; ma < 2; ma++) {
#pragma unroll
                for (int na = 0; na < 4; na++) {
                    int mrow = m0_ + wm * 32 + ma * 16 + gid;
                    int ncol = wn * 32 + na * 8 + tq;
                    float2 bv = *(const float2*)(g.bias + ncol);
#pragma unroll
                    for (int hrow = 0; hrow < 2; hrow++) {
                        int mr = mrow + hrow * 8;
                        if (mr >= g.M) continue;
                        float v0 = c[ma][na][hrow*2 + 0] + bv.x;
                        float v1 = c[ma][na][hrow*2 + 1] + bv.y;
                        if (relu) { v0 = fmaxf(v0, 0.f); v1 = fmaxf(v1, 0.f); }
                        if (bfo) {
                            uint32_t hw, lw;
                            bfsplit2(v0, v1, hw, lw);
                            *(uint32_t*)(g.Cb + (size_t)mr * H + ncol) = hw;
                            *(uint32_t*)(g.Cb + (size_t)g.loOff + (size_t)mr * H + ncol) = lw;
                        } else {
                            *(float2*)(g.Cf + (size_t)mr * H + ncol) = make_float2(v0, v1);
                        }
                    }
                }
            }
        }
        __syncthreads();
        buf ^= 1;
    }
}

// ======================= persistent int8 pred GEMM ===========================
// out[NG,NI] = sA.sB.(65536*S11 + 256*(S10+S01) + S00) + bias
#define NTN ((NI + 127) / 128)    // 157
#define NTM ((NG + 127) / 128)    // 40
#define NT_TOT (NTN * NTM)        // 6280
#define NCTA_PRED 148

#define QROW 144                   // padded int8 row stride (128B data + 16 pad)
#define QPLANE (128 * QROW)        // 18432
#define SM_QA 0
#define SM_QB (2 * QPLANE)         // 36864
#define SMEM_PRED8 (SM_QB + 4 * QPLANE)   // 110592

__device__ __forceinline__ void loadQ(uint32_t dst, const int8_t* P1, const int8_t* P0,
                                      int r0_, int rmax, int tid)
{
#pragma unroll 4
    for (int i = tid; i < 2048; i += 256) {
        int plane = i >> 10, row = (i >> 3) & 127, c = i & 7;
        int gr = r0_ + row;
        int sz = (gr < rmax) ? 16 : 0;
        if (gr >= rmax) gr = rmax - 1;
        const int8_t* src = (plane ? P0 : P1) + (size_t)gr * H + c * 16;
        CPA16(dst + (uint32_t)plane * QPLANE + (uint32_t)row * QROW + c * 16, src, sz);
    }
}

__global__ void __launch_bounds__(256, 1)
k_pred_i8(const int8_t* __restrict__ A1, const int8_t* __restrict__ A0,
          const int8_t* __restrict__ B1, const int8_t* __restrict__ B0,
          const float* __restrict__ sA, const float* __restrict__ sB,
          const float* __restrict__ bias, float* __restrict__ out)
{
    extern __shared__ char sm[];
    const int tid  = threadIdx.x;
    const int wid  = tid >> 5;
    const int lane = tid & 31;
    const int wm   = wid >> 1;    // 0..3 (32 M-rows)
    const int wn   = wid & 1;     // 0..1 (32 N-cols per half)

    const uint32_t sbase = smem_u32(sm);

    const int beg = (int)((long long)blockIdx.x * NT_TOT / NCTA_PRED);
    const int end = (int)((long long)(blockIdx.x + 1) * NT_TOT / NCTA_PRED);

    const int arow  = lane & 15;
    const int ahi   = (lane >> 4) & 1;
    const int brow  = ((lane >> 4) << 3) + (lane & 7);
    const int bkoff = ((lane >> 3) & 1) * 16;
    const int erow  = lane >> 2;
    const int ecol  = (lane & 3) * 2;

    int cur_m = -1;
    int buf = 0;

#pragma unroll 1
    for (int t = beg; t < end; ++t) {
        int tm = t / NTN, tn = t - tm * NTN;
        if (tm != cur_m) {
            CP_WAIT0();
            __syncthreads();
            loadQ(sbase + SM_QA, A1, A0, tm * 128, NG, tid);
            loadQ(sbase + SM_QB, B1, B0, tn * 128, NI, tid);
            CP_COMMIT();
            cur_m = tm;
            buf = 0;
            if (t + 1 < end && (t + 1) / NTN == cur_m) {
                loadQ(sbase + SM_QB + 2 * QPLANE, B1, B0, (tn + 1) * 128, NI, tid);
                CP_COMMIT();
                CP_WAIT1();
            } else {
                CP_WAIT0();
            }
            __syncthreads();
        } else {
            if (t + 1 < end && (t + 1) / NTN == cur_m) {
                loadQ(sbase + SM_QB + (uint32_t)(buf ^ 1) * 2 * QPLANE, B1, B0,
                      (tn + 1) * 128, NI, tid);
                CP_COMMIT();
                CP_WAIT1();
            } else {
                CP_WAIT0();
            }
            __syncthreads();
        }

        const uint32_t aP1 = sbase + SM_QA;
        const uint32_t aP0 = aP1 + QPLANE;
        const uint32_t bBuf = sbase + SM_QB + (uint32_t)buf * 2 * QPLANE;
        const uint32_t bP1 = bBuf;
        const uint32_t bP0 = bBuf + QPLANE;

        const int m0_ = tm * 128, n0_ = tn * 128;

#pragma unroll 1
        for (int nh = 0; nh < 2; nh++) {
            int c11[2][4][4], cx[2][4][4], c00[2][4][4];
#pragma unroll
            for (int i = 0; i < 2; i++)
#pragma unroll
                for (int j = 0; j < 4; j++)
#pragma unroll
                    for (int q = 0; q < 4; q++) { c11[i][j][q] = 0; cx[i][j][q] = 0; c00[i][j][q] = 0; }

#pragma unroll
            for (int kk = 0; kk < 4; kk++) {
                uint32_t a1f[2][4], a0f[2][4];
#pragma unroll
                for (int mf = 0; mf < 2; mf++) {
                    uint32_t ao = (uint32_t)(wm * 32 + mf * 16 + arow) * QROW + kk * 32 + ahi * 16;
                    LDSM4(a1f[mf], aP1 + ao);
                    LDSM4(a0f[mf], aP0 + ao);
                }
                uint32_t b1r[2][4], b0r[2][4];
#pragma unroll
                for (int gg = 0; gg < 2; gg++) {
                    uint32_t bo = (uint32_t)(nh * 64 + wn * 32 + gg * 16 + brow) * QROW
                                + kk * 32 + bkoff;
                    LDSM4(b1r[gg], bP1 + bo);
                    LDSM4(b0r[gg], bP0 + bo);
                }
#pragma unroll
                for (int mf = 0; mf < 2; mf++)
#pragma unroll
                    for (int nf = 0; nf < 4; nf++) {
                        int gg = nf >> 1, pp = (nf & 1) * 2;
                        MMA_S8(c11[mf][nf], a1f[mf], b1r[gg][pp], b1r[gg][pp + 1]);
                        MMA_S8(cx[mf][nf],  a1f[mf], b0r[gg][pp], b0r[gg][pp + 1]);
                        MMA_S8(cx[mf][nf],  a0f[mf], b1r[gg][pp], b1r[gg][pp + 1]);
                        MMA_S8(c00[mf][nf], a0f[mf], b0r[gg][pp], b0r[gg][pp + 1]);
                    }
            }

            // epilogue for this N-half
#pragma unroll
            for (int mf = 0; mf < 2; mf++)
#pragma unroll
                for (int nf = 0; nf < 4; nf++) {
                    int n = n0_ + nh * 64 + wn * 32 + nf * 8 + ecol;
                    if (n >= NI) continue;
                    int mA = m0_ + wm * 32 + mf * 16 + erow;
                    float2 bv  = *(const float2*)(bias + n);
                    float2 sbv = *(const float2*)(sB + n);
                    if (mA < NG) {
                        float sa = __ldg(&sA[mA]);
                        float f0 = fmaf(65536.f, (float)c11[mf][nf][0],
                                   fmaf(256.f, (float)cx[mf][nf][0], (float)c00[mf][nf][0]));
                        float f1 = fmaf(65536.f, (float)c11[mf][nf][1],
                                   fmaf(256.f, (float)cx[mf][nf][1], (float)c00[mf][nf][1]));
                        float2 v = make_float2(fmaf(sa * sbv.x, f0, bv.x),
                                               fmaf(sa * sbv.y, f1, bv.y));
                        *(float2*)(out + (size_t)mA * NI + n) = v;
                    }
                    if (mA + 8 < NG) {
                        float sa = __ldg(&sA[mA + 8]);
                        float f2 = fmaf(65536.f, (float)c11[mf][nf][2],
                                   fmaf(256.f, (float)cx[mf][nf][2], (float)c00[mf][nf][2]));
                        float f3 = fmaf(65536.f, (float)c11[mf][nf][3],
                                   fmaf(256.f, (float)cx[mf][nf][3], (float)c00[mf][nf][3]));
                        float2 v = make_float2(fmaf(sa * sbv.x, f2, bv.x),
                                               fmaf(sa * sbv.y, f3, bv.y));
                        *(float2*)(out + (size_t)(mA + 8) * NI + n) = v;
                    }
                }
        }
        __syncthreads();
        buf ^= 1;
    }
}

// ---------------------------------------------------------------------------
extern "C" void kernel_launch(void* const* d_in, const int* in_sizes, int n_in,
                              void* d_out, int out_size)
{
    const int*   x_user   = (const int*)  d_in[1];
    const int*   x_item   = (const int*)  d_in[2];
    const float* emb_user = (const float*)d_in[4];
    const float* emb_item = (const float*)d_in[5];
    const float* W1l      = (const float*)d_in[6];
    const float* W1r      = (const float*)d_in[7];
    const float* b1       = (const float*)d_in[8];
    const float* W2l      = (const float*)d_in[9];
    const float* W2r      = (const float*)d_in[10];
    const float* b2       = (const float*)d_in[11];
    const float* pred_W   = (const float*)d_in[12];
    const float* pred_b   = (const float*)d_in[13];
    const int*   ug_src   = (const int*)  d_in[14];
    const int*   ug_dst   = (const int*)  d_in[15];
    const int*   ui_src   = (const int*)  d_in[16];
    const int*   ui_dst   = (const int*)  d_in[17];
    const int*   gi_src   = (const int*)  d_in[18];
    const int*   gi_dst   = (const int*)  d_in[19];
    float* out = (float*)d_out;

    float* fb = nullptr; int* ib = nullptr; __nv_bfloat16* bb = nullptr; int8_t* qb = nullptr;
    cudaGetSymbolAddress((void**)&fb, g_f);
    cudaGetSymbolAddress((void**)&ib, g_i);
    cudaGetSymbolAddress((void**)&bb, g_bf);
    cudaGetSymbolAddress((void**)&qb, g_q);

    cudaFuncSetAttribute(k_gemm_h, cudaFuncAttributeMaxDynamicSharedMemorySize, SMEM_GH);
    cudaFuncSetAttribute(k_gemm_l, cudaFuncAttributeMaxDynamicSharedMemorySize, SMEM_GL);
    cudaFuncSetAttribute(k_pred_i8, cudaFuncAttributeMaxDynamicSharedMemorySize, SMEM_PRED8);

    cudaMemsetAsync(ib + OI_CNT_G1, 0, (size_t)CNT_TOTAL * sizeof(int));

    // weight prep: quantize pred_W (int8 digit planes), combine+split layer weights
    k_quantB<<<NI / 32, 256>>>(pred_W, qb + QB1, qb + QB0, fb + OF_SB);
    k_wcomb<<<(HH + 255) / 256, 256>>>(W1r, b1, W2r, b2);
    k_splitW<<<dim3(4, 4, 9), dim3(32, 8)>>>(W1l, W2l, fb + OF_WC, bb + OB_W);

    // merged embedding gathers (fp32 + bf16 hi/lo)
    k_gather2m<<<((NU + NI) * 32 + 255) / 256, 256>>>(emb_user, x_user, emb_item, x_item,
                                                      fb, bb);

    // CSR build
    {
        int tot = E_UG + E_GI + 2 * E_UI;
        k_count_all<<<(tot + 255) / 256, 256>>>(ug_dst, gi_src, ui_src, ui_dst, ib);
        k_scan4<<<4, 1024>>>(ib);
        k_bucket_all<<<(tot + 255) / 256, 256>>>(ug_src, ug_dst, ui_src, ui_dst,
                                                 gi_src, gi_dst, ib);
    }

    // layer-1 aggregations -> bf16 hi/lo
    {
        int warps = NU + NI + 2 * NG;
        k_agg_all<<<(warps + 7) / 8, 256>>>(ib, fb, bb);
    }

    // layer-1 GEMMs: one persistent launch, 3 jobs
    {
        LJob3 js;
        js.j[0].Ah0 = bb + OB_AIU;  js.j[0].Al0 = bb + OB_AIU + NU*H;
        js.j[0].Ah1 = bb + OB_HUe;  js.j[0].Al1 = bb + OB_HUe + NU*H;
        js.j[0].Wh0 = bb + OB_W + SL_W1L3*2*HH;
        js.j[0].Wh1 = bb + OB_W + SL_WC0*2*HH;
        js.j[0].bias = fb + OF_BC + 0*H;
        js.j[0].Cf = fb + OF_HU1; js.j[0].Cb = nullptr; js.j[0].loOff = 0;
        js.j[0].M = NU; js.j[0].ntiles = (NU + 63) / 64;
        js.j[0].ctaBase = 0;   js.j[0].nctas = 118; js.j[0].flags = GEMM_RELU;
        js.j[1].Ah0 = bb + OB_AUI;  js.j[1].Al0 = bb + OB_AUI + NI*H;
        js.j[1].Ah1 = bb + OB_HIe;  js.j[1].Al1 = bb + OB_HIe + NI*H;
        js.j[1].Wh0 = bb + OB_W + SL_W1L2*2*HH;
        js.j[1].Wh1 = bb + OB_W + SL_WC1*2*HH;
        js.j[1].bias = fb + OF_BC + 1*H;
        js.j[1].Cf = fb + OF_HI1; js.j[1].Cb = nullptr; js.j[1].loOff = 0;
        js.j[1].M = NI; js.j[1].ntiles = (NI + 63) / 64;
        js.j[1].ctaBase = 118; js.j[1].nctas = 24; js.j[1].flags = GEMM_RELU;
        js.j[2].Ah0 = bb + OB_AUG;  js.j[2].Al0 = bb + OB_AUG + NG*H;
        js.j[2].Ah1 = bb + OB_AIG;  js.j[2].Al1 = bb + OB_AIG + NG*H;
        js.j[2].Wh0 = bb + OB_W + SL_W1L0*2*HH;
        js.j[2].Wh1 = bb + OB_W + SL_W1L5*2*HH;
        js.j[2].bias = fb + OF_BC + 2*H;
        js.j[2].Cf = nullptr; js.j[2].Cb = bb + OB_HG1; js.j[2].loOff = NG*H;
        js.j[2].M = NG; js.j[2].ntiles = (NG + 63) / 64;
        js.j[2].ctaBase = 142; js.j[2].nctas = 6; js.j[2].flags = GEMM_RELU | GEMM_BF16;
        k_gemm_l<<<148, 256, SMEM_GL>>>(js);
    }

    // layer-2 aggregations
    k_agg_all2<<<(2 * NG + 7) / 8, 256>>>(ib, fb, bb);

    // layer-2 group GEMM (3 terms) -> REP fp32
    {
        GemmArgs a = {};
        a.Ah[0] = bb + OB_BUG;  a.Al[0] = bb + OB_BUG + NG*H;  a.Wh[0] = bb + OB_W + SL_W2L0*2*HH;
        a.Ah[1] = bb + OB_HG1;  a.Al[1] = bb + OB_HG1 + NG*H;  a.Wh[1] = bb + OB_W + SL_WC2*2*HH;
        a.Ah[2] = bb + OB_BIG;  a.Al[2] = bb + OB_BIG + NG*H;  a.Wh[2] = bb + OB_W + SL_W2L5*2*HH;
        a.bias = fb + OF_BC + 3*H;
        a.Cf = fb + OF_REP; a.Cb = nullptr; a.loOff = 0;
        a.M = NG; a.nterms = 3; a.flags = GEMM_RELU;
        k_gemm_h<<<(NG + 127) / 128, 256, SMEM_GH>>>(a);
    }

    // quantize REP -> int8 digit planes
    k_quantA<<<(NG + 7) / 8, 256>>>(fb + OF_REP, qb + QA1, qb + QA0, fb + OF_SA);

    // persistent int8 prediction GEMM
    k_pred_i8<<<NCTA_PRED, 256, SMEM_PRED8>>>(qb + QA1, qb + QA0, qb + QB1, qb + QB0,
                                              fb + OF_SA, fb + OF_SB, pred_b, out);
    (void)in_sizes; (void)n_in; (void)out_size;
}

// round 8
// speedup vs baseline: 1.6765x; 1.6765x over previous
#include <cuda_runtime.h>
#include <cuda_bf16.h>
#include <cstdint>

// ----------------------------------------------------------------------------
// BaseGR hetero-SAGE on GB300 — R8.
// R7's int8 pred GEMM regressed 3x (legacy IMMA is ~1/4 HMMA rate on sm_103a).
// R8 = revert to R6's bf16 3-split persistent pred GEMM, plus k_wcomb folded
// into k_splitW (direct combine+split, one fewer dependent launch).
// ----------------------------------------------------------------------------

#define NG 5000
#define NU 100000
#define NI 20000
#define H 128
#define HH (H*H)
#define E_UG 300000
#define E_UI 600000
#define E_GI 200000

// ---------------- fp32 scratch ----------------
#define OF_HU  0
#define OF_HI  (OF_HU  + NU*H)
#define OF_HU1 (OF_HI  + NI*H)
#define OF_HI1 (OF_HU1 + NU*H)
#define OF_BC  (OF_HI1 + NI*H)
#define F_TOTAL (OF_BC + 4*H)
__device__ float g_f[F_TOTAL];

// ---------------- bf16 scratch (hi plane then lo plane for each) -------------
#define OB_HUe 0
#define OB_HIe (OB_HUe + 2*NU*H)
#define OB_AIU (OB_HIe + 2*NI*H)
#define OB_AUI (OB_AIU + 2*NU*H)
#define OB_AUG (OB_AUI + 2*NI*H)
#define OB_AIG (OB_AUG + 2*NG*H)
#define OB_HG1 (OB_AIG + 2*NG*H)
#define OB_BUG (OB_HG1 + 2*NG*H)
#define OB_BIG (OB_BUG + 2*NG*H)
#define OB_REP (OB_BIG + 2*NG*H)
#define OB_PW  (OB_REP + 2*NG*H)
#define OB_W   (OB_PW  + 2*NI*H)
#define B_TOTAL (OB_W + 18*HH)
__device__ __nv_bfloat16 g_bf[B_TOTAL];

// weight slots in OB_W (each slot: hi HH then lo HH)
#define SL_W1L3 0
#define SL_WC0  1
#define SL_W1L2 2
#define SL_WC1  3
#define SL_W1L0 4
#define SL_W1L5 5
#define SL_W2L0 6
#define SL_WC2  7
#define SL_W2L5 8

// ---------------- int scratch ----------------
#define OI_CNT_G1 0
#define OI_CNT_G2 (OI_CNT_G1 + NG)
#define OI_CNT_U  (OI_CNT_G2 + NG)
#define OI_CNT_I  (OI_CNT_U  + NU)
#define CNT_TOTAL (OI_CNT_I  + NI)
#define OI_RP_G1  CNT_TOTAL
#define OI_RP_G2  (OI_RP_G1 + NG + 1)
#define OI_RP_U   (OI_RP_G2 + NG + 1)
#define OI_RP_I   (OI_RP_U  + NU + 1)
#define OI_CUR_G1 (OI_RP_I  + NI + 1)
#define OI_CUR_G2 (OI_CUR_G1 + NG)
#define OI_CUR_U  (OI_CUR_G2 + NG)
#define OI_CUR_I  (OI_CUR_U  + NU)
#define OI_COL_G1 (OI_CUR_I  + NI)
#define OI_COL_G2 (OI_COL_G1 + E_UG)
#define OI_COL_U  (OI_COL_G2 + E_GI)
#define OI_COL_I  (OI_COL_U  + E_UI)
#define I_TOTAL   (OI_COL_I  + E_UI)
__device__ int g_i[I_TOTAL];

// ======================= helpers =============================================
__device__ __forceinline__ uint32_t smem_u32(const void* p) {
    uint32_t a;
    asm("{ .reg .u64 t; cvta.to.shared.u64 t, %1; cvt.u32.u64 %0, t; }"
        : "=r"(a) : "l"(p));
    return a;
}

#define LDSM4(r, addr) \
    asm volatile("ldmatrix.sync.aligned.m8n8.x4.shared.b16 {%0,%1,%2,%3}, [%4];" \
                 : "=r"((r)[0]), "=r"((r)[1]), "=r"((r)[2]), "=r"((r)[3]) \
                 : "r"(addr))

#define MMA_BF16(c, a, b0, b1) \
    asm volatile("mma.sync.aligned.m16n8k16.row.col.f32.bf16.bf16.f32 " \
                 "{%0,%1,%2,%3}, {%4,%5,%6,%7}, {%8,%9}, {%0,%1,%2,%3};" \
                 : "+f"((c)[0]), "+f"((c)[1]), "+f"((c)[2]), "+f"((c)[3]) \
                 : "r"((a)[0]), "r"((a)[1]), "r"((a)[2]), "r"((a)[3]), \
                   "r"(b0), "r"(b1))

#define CPA16(dst, src, sz) \
    asm volatile("cp.async.cg.shared.global [%0], [%1], 16, %2;" \
                 :: "r"(dst), "l"(src), "r"(sz))
#define CP_COMMIT() asm volatile("cp.async.commit_group;" ::: "memory")
#define CP_WAIT0()  asm volatile("cp.async.wait_group 0;" ::: "memory")
#define CP_WAIT1()  asm volatile("cp.async.wait_group 1;" ::: "memory")

__device__ __forceinline__ void bfsplit2(float v0, float v1, uint32_t& h, uint32_t& l)
{
    __nv_bfloat16 h0 = __float2bfloat16(v0), h1 = __float2bfloat16(v1);
    float r0 = v0 - __bfloat162float(h0);
    float r1 = v1 - __bfloat162float(h1);
    __nv_bfloat16 l0 = __float2bfloat16(r0), l1 = __float2bfloat16(r1);
    h = (uint32_t)__bfloat16_as_ushort(h0) | ((uint32_t)__bfloat16_as_ushort(h1) << 16);
    l = (uint32_t)__bfloat16_as_ushort(l0) | ((uint32_t)__bfloat16_as_ushort(l1) << 16);
}

// ======================= merged gather (fp32 + bf16 hi/lo) ===================
__global__ void k_gather2m(const float* __restrict__ emb_u, const int* __restrict__ x_u,
                           const float* __restrict__ emb_i, const int* __restrict__ x_i,
                           float* __restrict__ fb, __nv_bfloat16* __restrict__ bbuf)
{
    int t = blockIdx.x * blockDim.x + threadIdx.x;
    const float* emb; const int* x;
    float* outf; __nv_bfloat16* hb; int loOff; int r;
    if (t < NU * 32) {
        emb = emb_u; x = x_u; outf = fb + OF_HU; hb = bbuf + OB_HUe; loOff = NU * H;
        r = t >> 5;
    } else if (t < (NU + NI) * 32) {
        t -= NU * 32;
        emb = emb_i; x = x_i; outf = fb + OF_HI; hb = bbuf + OB_HIe; loOff = NI * H;
        r = t >> 5;
    } else return;
    int c = t & 31;
    float4 v = ((const float4*)emb)[(size_t)x[r] * 32 + c];
    ((float4*)outf)[(size_t)r * 32 + c] = v;
    uint32_t h0, l0, h1, l1;
    bfsplit2(v.x, v.y, h0, l0);
    bfsplit2(v.z, v.w, h1, l1);
    size_t o = ((size_t)r * H + c * 4) >> 1;
    ((uint32_t*)hb)[o]     = h0;
    ((uint32_t*)hb)[o + 1] = h1;
    ((uint32_t*)(hb + loOff))[o]     = l0;
    ((uint32_t*)(hb + loOff))[o + 1] = l1;
}

// ======================= CSR build (merged) ==================================
__global__ void k_count_all(const int* __restrict__ ug_dst, const int* __restrict__ gi_src,
                            const int* __restrict__ ui_src, const int* __restrict__ ui_dst,
                            int* __restrict__ ib)
{
    int t = blockIdx.x * blockDim.x + threadIdx.x;
    if (t < E_UG) atomicAdd(&ib[OI_CNT_G1 + ug_dst[t]], 1);
    else if (t < E_UG + E_GI) atomicAdd(&ib[OI_CNT_G2 + gi_src[t - E_UG]], 1);
    else if (t < E_UG + E_GI + E_UI) atomicAdd(&ib[OI_CNT_U + ui_src[t - E_UG - E_GI]], 1);
    else if (t < E_UG + E_GI + 2*E_UI) atomicAdd(&ib[OI_CNT_I + ui_dst[t - E_UG - E_GI - E_UI]], 1);
}

__global__ void k_scan4(int* __restrict__ ib)
{
    const int* cnt; int* rp; int* cur; int n;
    switch (blockIdx.x) {
        case 0: cnt = ib + OI_CNT_G1; rp = ib + OI_RP_G1; cur = ib + OI_CUR_G1; n = NG; break;
        case 1: cnt = ib + OI_CNT_G2; rp = ib + OI_RP_G2; cur = ib + OI_CUR_G2; n = NG; break;
        case 2: cnt = ib + OI_CNT_U;  rp = ib + OI_RP_U;  cur = ib + OI_CUR_U;  n = NU; break;
        default: cnt = ib + OI_CNT_I; rp = ib + OI_RP_I;  cur = ib + OI_CUR_I;  n = NI; break;
    }
    __shared__ int ssum[1024];
    const int t = threadIdx.x;
    const int chunk = (n + 1023) / 1024;
    int beg = t * chunk;
    int end = beg + chunk; if (end > n) end = n;
    if (beg > n) beg = n;
    int s = 0;
    for (int i = beg; i < end; i++) s += cnt[i];
    ssum[t] = s;
    __syncthreads();
    for (int off = 1; off < 1024; off <<= 1) {
        int v = (t >= off) ? ssum[t - off] : 0;
        __syncthreads();
        ssum[t] += v;
        __syncthreads();
    }
    int prefix = (t == 0) ? 0 : ssum[t - 1];
    for (int i = beg; i < end; i++) {
        rp[i]  = prefix;
        cur[i] = prefix;
        prefix += cnt[i];
    }
    if (t == 1023) rp[n] = ssum[1023];
}

__global__ void k_bucket_all(const int* __restrict__ ug_src, const int* __restrict__ ug_dst,
                             const int* __restrict__ ui_src, const int* __restrict__ ui_dst,
                             const int* __restrict__ gi_src, const int* __restrict__ gi_dst,
                             int* __restrict__ ib)
{
    int t = blockIdx.x * blockDim.x + threadIdx.x;
    if (t < E_UG) {
        int p = atomicAdd(&ib[OI_CUR_G1 + ug_dst[t]], 1);
        ib[OI_COL_G1 + p] = ug_src[t];
    } else if (t < E_UG + E_GI) {
        int e = t - E_UG;
        int p = atomicAdd(&ib[OI_CUR_G2 + gi_src[e]], 1);
        ib[OI_COL_G2 + p] = gi_dst[e];
    } else if (t < E_UG + E_GI + E_UI) {
        int e = t - E_UG - E_GI;
        int p = atomicAdd(&ib[OI_CUR_U + ui_src[e]], 1);
        ib[OI_COL_U + p] = ui_dst[e];
    } else if (t < E_UG + E_GI + 2*E_UI) {
        int e = t - E_UG - E_GI - E_UI;
        int p = atomicAdd(&ib[OI_CUR_I + ui_dst[e]], 1);
        ib[OI_COL_I + p] = ui_src[e];
    }
}

// ======================= segment mean -> bf16 hi/lo ==========================
__device__ __forceinline__ void agg_row(const int* __restrict__ rp, const int* __restrict__ col,
                                        const float* __restrict__ feat,
                                        __nv_bfloat16* __restrict__ hb, int loOff,
                                        int row, int lane)
{
    int beg = rp[row], end = rp[row + 1];
    float4 acc = make_float4(0.f, 0.f, 0.f, 0.f);
    const float4* fv = (const float4*)feat;
    int e = beg;
    for (; e + 4 <= end; e += 4) {
        int s0 = __ldg(&col[e + 0]);
        int s1 = __ldg(&col[e + 1]);
        int s2 = __ldg(&col[e + 2]);
        int s3 = __ldg(&col[e + 3]);
        float4 v0 = __ldg(&fv[(size_t)s0 * 32 + lane]);
        float4 v1 = __ldg(&fv[(size_t)s1 * 32 + lane]);
        float4 v2 = __ldg(&fv[(size_t)s2 * 32 + lane]);
        float4 v3 = __ldg(&fv[(size_t)s3 * 32 + lane]);
        acc.x += v0.x + v1.x + v2.x + v3.x;
        acc.y += v0.y + v1.y + v2.y + v3.y;
        acc.z += v0.z + v1.z + v2.z + v3.z;
        acc.w += v0.w + v1.w + v2.w + v3.w;
    }
    for (; e < end; e++) {
        int s = __ldg(&col[e]);
        float4 v = __ldg(&fv[(size_t)s * 32 + lane]);
        acc.x += v.x; acc.y += v.y; acc.z += v.z; acc.w += v.w;
    }
    float inv = (end > beg) ? 1.f / (float)(end - beg) : 0.f;
    acc.x *= inv; acc.y *= inv; acc.z *= inv; acc.w *= inv;
    uint32_t h0, l0, h1, l1;
    bfsplit2(acc.x, acc.y, h0, l0);
    bfsplit2(acc.z, acc.w, h1, l1);
    size_t o = ((size_t)row * H + lane * 4) >> 1;
    ((uint32_t*)hb)[o]     = h0;
    ((uint32_t*)hb)[o + 1] = h1;
    ((uint32_t*)(hb + loOff))[o]     = l0;
    ((uint32_t*)(hb + loOff))[o + 1] = l1;
}

__global__ void k_agg_all(const int* __restrict__ ib, const float* __restrict__ fb,
                          __nv_bfloat16* __restrict__ bb)
{
    int w = (int)((blockIdx.x * blockDim.x + threadIdx.x) >> 5);
    int lane = threadIdx.x & 31;
    if (w < NU)
        agg_row(ib + OI_RP_U, ib + OI_COL_U, fb + OF_HI, bb + OB_AIU, NU*H, w, lane);
    else if (w < NU + NI)
        agg_row(ib + OI_RP_I, ib + OI_COL_I, fb + OF_HU, bb + OB_AUI, NI*H, w - NU, lane);
    else if (w < NU + NI + NG)
        agg_row(ib + OI_RP_G1, ib + OI_COL_G1, fb + OF_HU, bb + OB_AUG, NG*H, w - NU - NI, lane);
    else if (w < NU + NI + 2*NG)
        agg_row(ib + OI_RP_G2, ib + OI_COL_G2, fb + OF_HI, bb + OB_AIG, NG*H, w - NU - NI - NG, lane);
}

__global__ void k_agg_all2(const int* __restrict__ ib, const float* __restrict__ fb,
                           __nv_bfloat16* __restrict__ bb)
{
    int w = (int)((blockIdx.x * blockDim.x + threadIdx.x) >> 5);
    int lane = threadIdx.x & 31;
    if (w < NG)
        agg_row(ib + OI_RP_G1, ib + OI_COL_G1, fb + OF_HU1, bb + OB_BUG, NG*H, w, lane);
    else if (w < 2*NG)
        agg_row(ib + OI_RP_G2, ib + OI_COL_G2, fb + OF_HI1, bb + OB_BIG, NG*H, w - NG, lane);
}

// ======================= weight prep (fused combine + transpose + split) =====
// blockIdx.z selects the slot; slots 1/3/7 sum two source matrices.
__global__ void __launch_bounds__(256)
k_splitW(const float* __restrict__ W1l, const float* __restrict__ W1r,
         const float* __restrict__ W2l, const float* __restrict__ W2r,
         __nv_bfloat16* __restrict__ dst9)
{
    const float* srcA; const float* srcB = nullptr;
    switch (blockIdx.z) {
        case 0: srcA = W1l + 3*HH; break;
        case 1: srcA = W1r + 1*HH; srcB = W1r + 3*HH; break;
        case 2: srcA = W1l + 2*HH; break;
        case 3: srcA = W1r + 2*HH; srcB = W1r + 4*HH; break;
        case 4: srcA = W1l + 0*HH; break;
        case 5: srcA = W1l + 5*HH; break;
        case 6: srcA = W2l + 0*HH; break;
        case 7: srcA = W2r + 0*HH; srcB = W2r + 5*HH; break;
        default: srcA = W2l + 5*HH; break;
    }
    __nv_bfloat16* hi = dst9 + (size_t)blockIdx.z * 2 * HH;
    __nv_bfloat16* lo = hi + HH;
    __shared__ float t[32][33];
    int nblk = blockIdx.x * 32;
    int kblk = blockIdx.y * 32;
    int tx = threadIdx.x, ty = threadIdx.y;
#pragma unroll
    for (int i = ty; i < 32; i += 8) {
        size_t gi = (size_t)(kblk + i) * H + nblk + tx;
        float v = srcA[gi];
        if (srcB) v += srcB[gi];
        t[i][tx] = v;
    }
    __syncthreads();
#pragma unroll
    for (int i = ty; i < 32; i += 8) {
        float x = t[tx][i];
        __nv_bfloat16 h = __float2bfloat16(x);
        size_t o = (size_t)(nblk + i) * H + kblk + tx;
        hi[o] = h;
        lo[o] = __float2bfloat16(x - __bfloat162float(h));
    }
}

// combined biases only (weights handled by fused k_splitW)
__global__ void k_bias(const float* __restrict__ b1, const float* __restrict__ b2)
{
    int i = blockIdx.x * blockDim.x + threadIdx.x;
    float* bc = g_f + OF_BC;
    if (i < H) {
        bc[0*H + i] = b1[1*H + i] + b1[3*H + i];
        bc[1*H + i] = b1[2*H + i] + b1[4*H + i];
        bc[2*H + i] = b1[0*H + i] + b1[5*H + i];
        bc[3*H + i] = b2[0*H + i] + b2[5*H + i];
    }
}

// pred_W [H, NI] fp32 -> [NI, H] bf16 hi/lo (transposed, K contiguous)
__global__ void __launch_bounds__(256)
k_splitB(const float* __restrict__ W,
         __nv_bfloat16* __restrict__ hi, __nv_bfloat16* __restrict__ lo)
{
    __shared__ float t[32][33];
    int nblk = blockIdx.x * 32;
    int kblk = blockIdx.y * 32;
    int tx = threadIdx.x, ty = threadIdx.y;
#pragma unroll
    for (int i = ty; i < 32; i += 8)
        t[i][tx] = W[(size_t)(kblk + i) * NI + nblk + tx];
    __syncthreads();
#pragma unroll
    for (int i = ty; i < 32; i += 8) {
        float x = t[tx][i];
        __nv_bfloat16 h = __float2bfloat16(x);
        size_t o = (size_t)(nblk + i) * H + kblk + tx;
        hi[o] = h;
        lo[o] = __float2bfloat16(x - __bfloat162float(h));
    }
}

// ======================= common GEMM constants ===============================
#define PK   136
#define ROWB (PK * 2)          // 272 B per row
#define TILEB (128 * ROWB)     // 34816 B
#define HTILE (64 * ROWB)      // 17408 B

#define GEMM_RELU 1
#define GEMM_BF16 2

// ======================= HMMA layer-2 GEMM (multi-term, small) ===============
struct GemmArgs {
    const __nv_bfloat16* Ah[3];
    const __nv_bfloat16* Al[3];
    const __nv_bfloat16* Wh[3];
    const float* bias;
    float* Cf;
    __nv_bfloat16* Cb;
    int M, nterms, flags, loOff;
};

#define SMEM_GH (4 * TILEB)    // 139264

__global__ void __launch_bounds__(256, 1)
k_gemm_h(GemmArgs g)
{
    extern __shared__ char sm[];
    const int tid  = threadIdx.x;
    const int wid  = tid >> 5;
    const int lane = tid & 31;
    const int wm   = wid >> 1;
    const int wn   = wid & 1;
    const int m0   = blockIdx.x * 128;

    const uint32_t sbase  = smem_u32(sm);
    const uint32_t a_loff = (uint32_t)(lane & 15) * ROWB + (uint32_t)(lane >> 4) * 16;
    const uint32_t b_loff = (uint32_t)(((lane >> 4) * 8) + (lane & 7)) * ROWB
                          + (uint32_t)((lane >> 3) & 1) * 16;

    float c[2][8][4];
#pragma unroll
    for (int i = 0; i < 2; i++)
#pragma unroll
        for (int j = 0; j < 8; j++)
#pragma unroll
            for (int q = 0; q < 4; q++) c[i][j][q] = 0.f;

#pragma unroll 1
    for (int t = 0; t < g.nterms; t++) {
        const uint4* wh = (const uint4*)g.Wh[t];
        const uint4* wl = (const uint4*)(g.Wh[t] + HH);
        const uint4* ah = (const uint4*)g.Ah[t];
        const uint4* al = (const uint4*)g.Al[t];
#pragma unroll 4
        for (int i = tid; i < 2048; i += 256) {
            int row = i >> 4, cq = i & 15;
            uint32_t so = (uint32_t)row * ROWB + cq * 16;
            *(uint4*)(sm + 0*TILEB + so) = __ldg(&wh[row * 16 + cq]);
            *(uint4*)(sm + 1*TILEB + so) = __ldg(&wl[row * 16 + cq]);
            uint4 va = make_uint4(0,0,0,0), vb = va;
            if (m0 + row < g.M) {
                size_t gi = (size_t)(m0 + row) * 16 + cq;
                va = __ldg(&ah[gi]);
                vb = __ldg(&al[gi]);
            }
            *(uint4*)(sm + 2*TILEB + so) = va;
            *(uint4*)(sm + 3*TILEB + so) = vb;
        }
        __syncthreads();
#pragma unroll 1
        for (int sp = 0; sp < 3; sp++) {
            uint32_t aB = sbase + (sp == 2 ? 3*TILEB : 2*TILEB)
                        + (uint32_t)wm * 32 * ROWB + a_loff;
            uint32_t bB = sbase + (sp == 1 ? 1*TILEB : 0)
                        + (uint32_t)wn * 64 * ROWB + b_loff;
#pragma unroll
            for (int ks = 0; ks < 8; ks++) {
                uint32_t a[2][4], b[4][4];
                LDSM4(a[0], aB + ks * 32);
                LDSM4(a[1], aB + ks * 32 + 16 * ROWB);
#pragma unroll
                for (int q = 0; q < 4; q++)
                    LDSM4(b[q], bB + ks * 32 + q * 16 * ROWB);
#pragma unroll
                for (int ma = 0; ma < 2; ma++)
#pragma unroll
                    for (int na = 0; na < 8; na++)
                        MMA_BF16(c[ma][na], a[ma],
                                 b[na >> 1][(na & 1) * 2], b[na >> 1][(na & 1) * 2 + 1]);
            }
        }
        __syncthreads();
    }

    const int gid = lane >> 2;
    const int tq  = (lane & 3) * 2;
    const bool relu = (g.flags & GEMM_RELU) != 0;
    const bool bfo  = (g.flags & GEMM_BF16) != 0;
#pragma unroll
    for (int ma = 0; ma < 2; ma++) {
#pragma unroll
        for (int na = 0; na < 8; na++) {
            int mrow = m0 + wm * 32 + ma * 16 + gid;
            int ncol = wn * 64 + na * 8 + tq;
            float2 bv = *(const float2*)(g.bias + ncol);
#pragma unroll
            for (int hrow = 0; hrow < 2; hrow++) {
                int mr = mrow + hrow * 8;
                if (mr >= g.M) continue;
                float v0 = c[ma][na][hrow*2 + 0] + bv.x;
                float v1 = c[ma][na][hrow*2 + 1] + bv.y;
                if (relu) { v0 = fmaxf(v0, 0.f); v1 = fmaxf(v1, 0.f); }
                if (bfo) {
                    uint32_t hw, lw;
                    bfsplit2(v0, v1, hw, lw);
                    *(uint32_t*)(g.Cb + (size_t)mr * H + ncol) = hw;
                    *(uint32_t*)(g.Cb + (size_t)g.loOff + (size_t)mr * H + ncol) = lw;
                } else {
                    *(float2*)(g.Cf + (size_t)mr * H + ncol) = make_float2(v0, v1);
                }
            }
        }
    }
}

// ======================= persistent layer-1 GEMM =============================
struct LJob {
    const __nv_bfloat16* Ah0; const __nv_bfloat16* Al0;
    const __nv_bfloat16* Ah1; const __nv_bfloat16* Al1;
    const __nv_bfloat16* Wh0; const __nv_bfloat16* Wh1;
    const float* bias;
    float* Cf;
    __nv_bfloat16* Cb;
    int loOff, M, ntiles, ctaBase, nctas, flags;
};
struct LJob3 { LJob j[3]; };

#define SMEM_GL (4 * TILEB + 4 * HTILE)   // 208896

__device__ __forceinline__ void loadA64(uint32_t dst, const uint4* ah, const uint4* al,
                                        int m0_, int M, int tid)
{
#pragma unroll 2
    for (int i = tid; i < 1024; i += 256) {
        int row = i >> 4, cq = i & 15;
        int gr = m0_ + row;
        int sz = (gr < M) ? 16 : 0;
        if (gr >= M) gr = M - 1;
        uint32_t so = dst + (uint32_t)row * ROWB + cq * 16;
        CPA16(so,         ah + (size_t)gr * 16 + cq, sz);
        CPA16(so + HTILE, al + (size_t)gr * 16 + cq, sz);
    }
}

__global__ void __launch_bounds__(256, 1)
k_gemm_l(LJob3 js)
{
    extern __shared__ char sm[];
    const int tid  = threadIdx.x;
    const int wid  = tid >> 5;
    const int lane = tid & 31;
    const int wm   = wid >> 2;
    const int wn   = wid & 3;

    int ji = (blockIdx.x >= (uint32_t)js.j[2].ctaBase) ? 2
           : (blockIdx.x >= (uint32_t)js.j[1].ctaBase) ? 1 : 0;
    const LJob g = js.j[ji];
    const int idx = blockIdx.x - g.ctaBase;
    const int beg = (int)((long long)idx * g.ntiles / g.nctas);
    const int end = (int)((long long)(idx + 1) * g.ntiles / g.nctas);
    if (beg >= end) return;

    const uint32_t sbase = smem_u32(sm);
    const uint32_t sA    = sbase + 4 * TILEB;

    {
        const uint4* wsrc0 = (const uint4*)g.Wh0;
        const uint4* wsrc1 = (const uint4*)(g.Wh0 + HH);
        const uint4* wsrc2 = (const uint4*)g.Wh1;
        const uint4* wsrc3 = (const uint4*)(g.Wh1 + HH);
#pragma unroll 4
        for (int i = tid; i < 8192; i += 256) {
            int tl = i >> 11;
            int row = (i >> 4) & 127;
            int cq = i & 15;
            const uint4* src = (tl == 0) ? wsrc0 : (tl == 1) ? wsrc1 : (tl == 2) ? wsrc2 : wsrc3;
            CPA16(sbase + (uint32_t)tl * TILEB + (uint32_t)row * ROWB + cq * 16,
                  src + (size_t)row * 16 + cq, 16);
        }
    }
    loadA64(sA, (const uint4*)g.Ah0, (const uint4*)g.Al0, beg * 64, g.M, tid);
    CP_COMMIT();

    const uint32_t a_loff = (uint32_t)(lane & 15) * ROWB + (uint32_t)(lane >> 4) * 16;
    const uint32_t b_loff = (uint32_t)(((lane >> 4) * 8) + (lane & 7)) * ROWB
                          + (uint32_t)((lane >> 3) & 1) * 16;
    const int gid = lane >> 2;
    const int tq  = (lane & 3) * 2;
    const bool relu = (g.flags & GEMM_RELU) != 0;
    const bool bfo  = (g.flags & GEMM_BF16) != 0;

    float c[2][4][4];
    const int nit = (end - beg) * 2;
    int buf = 0;

#pragma unroll 1
    for (int it = 0; it < nit; it++) {
        const int tile = beg + (it >> 1);
        const int term = it & 1;
        if (it + 1 < nit) {
            int ntile = beg + ((it + 1) >> 1);
            int nterm = (it + 1) & 1;
            const uint4* ah = (const uint4*)(nterm ? g.Ah1 : g.Ah0);
            const uint4* al = (const uint4*)(nterm ? g.Al1 : g.Al0);
            loadA64(sA + (uint32_t)(buf ^ 1) * 2 * HTILE, ah, al, ntile * 64, g.M, tid);
            CP_COMMIT();
            CP_WAIT1();
        } else {
            CP_WAIT0();
        }
        __syncthreads();

        if (term == 0) {
#pragma unroll
            for (int i = 0; i < 2; i++)
#pragma unroll
                for (int j = 0; j < 4; j++)
#pragma unroll
                    for (int q = 0; q < 4; q++) c[i][j][q] = 0.f;
        }

        const uint32_t curA = sA + (uint32_t)buf * 2 * HTILE;
        const uint32_t wBase = sbase + (uint32_t)term * 2 * TILEB;
#pragma unroll 1
        for (int sp = 0; sp < 3; sp++) {
            uint32_t aB = curA + (sp == 2 ? HTILE : 0) + (uint32_t)wm * 32 * ROWB + a_loff;
            uint32_t bB = wBase + (sp == 1 ? TILEB : 0) + (uint32_t)wn * 32 * ROWB + b_loff;
#pragma unroll
            for (int ks = 0; ks < 8; ks++) {
                uint32_t a[2][4], b[2][4];
                LDSM4(a[0], aB + ks * 32);
                LDSM4(a[1], aB + ks * 32 + 16 * ROWB);
                LDSM4(b[0], bB + ks * 32);
                LDSM4(b[1], bB + ks * 32 + 16 * ROWB);
#pragma unroll
                for (int ma = 0; ma < 2; ma++)
#pragma unroll
                    for (int na = 0; na < 4; na++)
                        MMA_BF16(c[ma][na], a[ma],
                                 b[na >> 1][(na & 1) * 2], b[na >> 1][(na & 1) * 2 + 1]);
            }
        }

        if (term == 1) {
            int m0_ = tile * 64;
#pragma unroll
            for (int ma = 0; ma < 2; ma++) {
#pragma unroll
                for (int na = 0; na < 4; na++) {
                    int mrow = m0_ + wm * 32 + ma * 16 + gid;
                    int ncol = wn * 32 + na * 8 + tq;
                    float2 bv = *(const float2*)(g.bias + ncol);
#pragma unroll
                    for (int hrow = 0; hrow < 2; hrow++) {
                        int mr = mrow + hrow * 8;
                        if (mr >= g.M) continue;
                        float v0 = c[ma][na][hrow*2 + 0] + bv.x;
                        float v1 = c[ma][na][hrow*2 + 1] + bv.y;
                        if (relu) { v0 = fmaxf(v0, 0.f); v1 = fmaxf(v1, 0.f); }
                        if (bfo) {
                            uint32_t hw, lw;
                            bfsplit2(v0, v1, hw, lw);
                            *(uint32_t*)(g.Cb + (size_t)mr * H + ncol) = hw;
                            *(uint32_t*)(g.Cb + (size_t)g.loOff + (size_t)mr * H + ncol) = lw;
                        } else {
                            *(float2*)(g.Cf + (size_t)mr * H + ncol) = make_float2(v0, v1);
                        }
                    }
                }
            }
        }
        __syncthreads();
        buf ^= 1;
    }
}

// ======================= persistent pred GEMM ================================
#define NTN ((NI + 127) / 128)    // 157
#define NTM ((NG + 127) / 128)    // 40
#define NT_TOT (NTN * NTM)        // 6280
#define NCTA_PRED 148
#define SMEM_PRED (6 * TILEB)     // 208896

__device__ __forceinline__ void pred_loadA(uint32_t dstA, const uint4* gh, const uint4* gl,
                                           int m0_, int tid)
{
#pragma unroll 4
    for (int i = tid; i < 2048; i += 256) {
        int row = i >> 4, cq = i & 15;
        int gr = m0_ + row;
        int sz = (gr < NG) ? 16 : 0;
        if (gr >= NG) gr = NG - 1;
        uint32_t so = dstA + (uint32_t)row * ROWB + cq * 16;
        CPA16(so,         gh + (size_t)gr * 16 + cq, sz);
        CPA16(so + TILEB, gl + (size_t)gr * 16 + cq, sz);
    }
}

__device__ __forceinline__ void pred_loadB(uint32_t dstB, const uint4* gh, const uint4* gl,
                                           int n0_, int tid)
{
#pragma unroll 4
    for (int i = tid; i < 2048; i += 256) {
        int row = i >> 4, cq = i & 15;
        int gr = n0_ + row;
        int sz = (gr < NI) ? 16 : 0;
        if (gr >= NI) gr = NI - 1;
        uint32_t so = dstB + (uint32_t)row * ROWB + cq * 16;
        CPA16(so,         gh + (size_t)gr * 16 + cq, sz);
        CPA16(so + TILEB, gl + (size_t)gr * 16 + cq, sz);
    }
}

__global__ void __launch_bounds__(256, 1)
k_mma_pred(const __nv_bfloat16* __restrict__ Ahi, const __nv_bfloat16* __restrict__ Alo,
           const __nv_bfloat16* __restrict__ Bhi, const __nv_bfloat16* __restrict__ Blo,
           const float* __restrict__ bias, float* __restrict__ out)
{
    extern __shared__ char sm[];
    const int tid  = threadIdx.x;
    const int wid  = tid >> 5;
    const int lane = tid & 31;
    const int wm   = wid >> 1;
    const int wn   = wid & 1;

    const uint32_t sbase = smem_u32(sm);
    const uint32_t sB    = sbase + 2 * TILEB;

    const uint4* gAh = (const uint4*)Ahi;
    const uint4* gAl = (const uint4*)Alo;
    const uint4* gBh = (const uint4*)Bhi;
    const uint4* gBl = (const uint4*)Blo;

    const int beg = (int)((long long)blockIdx.x * NT_TOT / NCTA_PRED);
    const int end = (int)((long long)(blockIdx.x + 1) * NT_TOT / NCTA_PRED);

    const uint32_t a_loff = (uint32_t)(lane & 15) * ROWB + (uint32_t)(lane >> 4) * 16;
    const uint32_t b_loff = (uint32_t)(((lane >> 4) * 8) + (lane & 7)) * ROWB
                          + (uint32_t)((lane >> 3) & 1) * 16;
    const int gid = lane >> 2;
    const int tq  = (lane & 3) * 2;

    int cur_m = -1;
    int buf = 0;

#pragma unroll 1
    for (int t = beg; t < end; ++t) {
        int tm = t / NTN, tn = t - tm * NTN;
        if (tm != cur_m) {
            CP_WAIT0();
            __syncthreads();
            pred_loadA(sbase, gAh, gAl, tm * 128, tid);
            pred_loadB(sB, gBh, gBl, tn * 128, tid);
            CP_COMMIT();
            cur_m = tm;
            buf = 0;
            if (t + 1 < end && (t + 1) / NTN == cur_m) {
                pred_loadB(sB + 2 * TILEB, gBh, gBl, (tn + 1) * 128, tid);
                CP_COMMIT();
                CP_WAIT1();
            } else {
                CP_WAIT0();
            }
            __syncthreads();
        } else {
            if (t + 1 < end && (t + 1) / NTN == cur_m) {
                pred_loadB(sB + (uint32_t)(buf ^ 1) * 2 * TILEB, gBh, gBl, (tn + 1) * 128, tid);
                CP_COMMIT();
                CP_WAIT1();
            } else {
                CP_WAIT0();
            }
            __syncthreads();
        }

        float c[2][8][4];
#pragma unroll
        for (int i = 0; i < 2; i++)
#pragma unroll
            for (int j = 0; j < 8; j++)
#pragma unroll
                for (int q = 0; q < 4; q++) c[i][j][q] = 0.f;

        uint32_t curB = sB + (uint32_t)buf * 2 * TILEB;
#pragma unroll 1
        for (int sp = 0; sp < 3; sp++) {
            uint32_t aB = sbase + (sp == 2 ? TILEB : 0) + (uint32_t)wm * 32 * ROWB + a_loff;
            uint32_t bB = curB + (sp == 1 ? TILEB : 0) + (uint32_t)wn * 64 * ROWB + b_loff;
#pragma unroll
            for (int ks = 0; ks < 8; ks++) {
                uint32_t a[2][4], b[4][4];
                LDSM4(a[0], aB + ks * 32);
                LDSM4(a[1], aB + ks * 32 + 16 * ROWB);
#pragma unroll
                for (int q = 0; q < 4; q++)
                    LDSM4(b[q], bB + ks * 32 + q * 16 * ROWB);
#pragma unroll
                for (int ma = 0; ma < 2; ma++)
#pragma unroll
                    for (int na = 0; na < 8; na++)
                        MMA_BF16(c[ma][na], a[ma],
                                 b[na >> 1][(na & 1) * 2], b[na >> 1][(na & 1) * 2 + 1]);
            }
        }

        int m0_ = tm * 128, n0_ = tn * 128;
#pragma unroll
        for (int ma = 0; ma < 2; ma++) {
#pragma unroll
            for (int na = 0; na < 8; na++) {
                int mrow = m0_ + wm * 32 + ma * 16 + gid;
                int ncol = n0_ + wn * 64 + na * 8 + tq;
                if (ncol >= NI) continue;
                float2 bv = *(const float2*)(bias + ncol);
                if (mrow < NG) {
                    float2 v = make_float2(c[ma][na][0] + bv.x, c[ma][na][1] + bv.y);
                    *(float2*)(out + (size_t)mrow * NI + ncol) = v;
                }
                if (mrow + 8 < NG) {
                    float2 v = make_float2(c[ma][na][2] + bv.x, c[ma][na][3] + bv.y);
                    *(float2*)(out + (size_t)(mrow + 8) * NI + ncol) = v;
                }
            }
        }
        __syncthreads();
        buf ^= 1;
    }
}

// ---------------------------------------------------------------------------
extern "C" void kernel_launch(void* const* d_in, const int* in_sizes, int n_in,
                              void* d_out, int out_size)
{
    const int*   x_user   = (const int*)  d_in[1];
    const int*   x_item   = (const int*)  d_in[2];
    const float* emb_user = (const float*)d_in[4];
    const float* emb_item = (const float*)d_in[5];
    const float* W1l      = (const float*)d_in[6];
    const float* W1r      = (const float*)d_in[7];
    const float* b1       = (const float*)d_in[8];
    const float* W2l      = (const float*)d_in[9];
    const float* W2r      = (const float*)d_in[10];
    const float* b2       = (const float*)d_in[11];
    const float* pred_W   = (const float*)d_in[12];
    const float* pred_b   = (const float*)d_in[13];
    const int*   ug_src   = (const int*)  d_in[14];
    const int*   ug_dst   = (const int*)  d_in[15];
    const int*   ui_src   = (const int*)  d_in[16];
    const int*   ui_dst   = (const int*)  d_in[17];
    const int*   gi_src   = (const int*)  d_in[18];
    const int*   gi_dst   = (const int*)  d_in[19];
    float* out = (float*)d_out;

    float* fb = nullptr; int* ib = nullptr; __nv_bfloat16* bb = nullptr;
    cudaGetSymbolAddress((void**)&fb, g_f);
    cudaGetSymbolAddress((void**)&ib, g_i);
    cudaGetSymbolAddress((void**)&bb, g_bf);

    cudaFuncSetAttribute(k_gemm_h, cudaFuncAttributeMaxDynamicSharedMemorySize, SMEM_GH);
    cudaFuncSetAttribute(k_gemm_l, cudaFuncAttributeMaxDynamicSharedMemorySize, SMEM_GL);
    cudaFuncSetAttribute(k_mma_pred, cudaFuncAttributeMaxDynamicSharedMemorySize, SMEM_PRED);

    cudaMemsetAsync(ib + OI_CNT_G1, 0, (size_t)CNT_TOTAL * sizeof(int));

    // weight prep (combine fused into split)
    k_splitB<<<dim3(NI / 32, H / 32), dim3(32, 8)>>>(pred_W, bb + OB_PW, bb + OB_PW + NI*H);
    k_bias<<<1, 128>>>(b1, b2);
    k_splitW<<<dim3(4, 4, 9), dim3(32, 8)>>>(W1l, W1r, W2l, W2r, bb + OB_W);

    // merged embedding gathers (fp32 + bf16 hi/lo)
    k_gather2m<<<((NU + NI) * 32 + 255) / 256, 256>>>(emb_user, x_user, emb_item, x_item,
                                                      fb, bb);

    // CSR build
    {
        int tot = E_UG + E_GI + 2 * E_UI;
        k_count_all<<<(tot + 255) / 256, 256>>>(ug_dst, gi_src, ui_src, ui_dst, ib);
        k_scan4<<<4, 1024>>>(ib);
        k_bucket_all<<<(tot + 255) / 256, 256>>>(ug_src, ug_dst, ui_src, ui_dst,
                                                 gi_src, gi_dst, ib);
    }

    // layer-1 aggregations -> bf16 hi/lo
    {
        int warps = NU + NI + 2 * NG;
        k_agg_all<<<(warps + 7) / 8, 256>>>(ib, fb, bb);
    }

    // layer-1 GEMMs: one persistent launch, 3 jobs
    {
        LJob3 js;
        js.j[0].Ah0 = bb + OB_AIU;  js.j[0].Al0 = bb + OB_AIU + NU*H;
        js.j[0].Ah1 = bb + OB_HUe;  js.j[0].Al1 = bb + OB_HUe + NU*H;
        js.j[0].Wh0 = bb + OB_W + SL_W1L3*2*HH;
        js.j[0].Wh1 = bb + OB_W + SL_WC0*2*HH;
        js.j[0].bias = fb + OF_BC + 0*H;
        js.j[0].Cf = fb + OF_HU1; js.j[0].Cb = nullptr; js.j[0].loOff = 0;
        js.j[0].M = NU; js.j[0].ntiles = (NU + 63) / 64;
        js.j[0].ctaBase = 0;   js.j[0].nctas = 118; js.j[0].flags = GEMM_RELU;
        js.j[1].Ah0 = bb + OB_AUI;  js.j[1].Al0 = bb + OB_AUI + NI*H;
        js.j[1].Ah1 = bb + OB_HIe;  js.j[1].Al1 = bb + OB_HIe + NI*H;
        js.j[1].Wh0 = bb + OB_W + SL_W1L2*2*HH;
        js.j[1].Wh1 = bb + OB_W + SL_WC1*2*HH;
        js.j[1].bias = fb + OF_BC + 1*H;
        js.j[1].Cf = fb + OF_HI1; js.j[1].Cb = nullptr; js.j[1].loOff = 0;
        js.j[1].M = NI; js.j[1].ntiles = (NI + 63) / 64;
        js.j[1].ctaBase = 118; js.j[1].nctas = 24; js.j[1].flags = GEMM_RELU;
        js.j[2].Ah0 = bb + OB_AUG;  js.j[2].Al0 = bb + OB_AUG + NG*H;
        js.j[2].Ah1 = bb + OB_AIG;  js.j[2].Al1 = bb + OB_AIG + NG*H;
        js.j[2].Wh0 = bb + OB_W + SL_W1L0*2*HH;
        js.j[2].Wh1 = bb + OB_W + SL_W1L5*2*HH;
        js.j[2].bias = fb + OF_BC + 2*H;
        js.j[2].Cf = nullptr; js.j[2].Cb = bb + OB_HG1; js.j[2].loOff = NG*H;
        js.j[2].M = NG; js.j[2].ntiles = (NG + 63) / 64;
        js.j[2].ctaBase = 142; js.j[2].nctas = 6; js.j[2].flags = GEMM_RELU | GEMM_BF16;
        k_gemm_l<<<148, 256, SMEM_GL>>>(js);
    }

    // layer-2 aggregations
    k_agg_all2<<<(2 * NG + 7) / 8, 256>>>(ib, fb, bb);

    // layer-2 group GEMM (3 terms) -> REP bf16 hi/lo
    {
        GemmArgs a = {};
        a.Ah[0] = bb + OB_BUG;  a.Al[0] = bb + OB_BUG + NG*H;  a.Wh[0] = bb + OB_W + SL_W2L0*2*HH;
        a.Ah[1] = bb + OB_HG1;  a.Al[1] = bb + OB_HG1 + NG*H;  a.Wh[1] = bb + OB_W + SL_WC2*2*HH;
        a.Ah[2] = bb + OB_BIG;  a.Al[2] = bb + OB_BIG + NG*H;  a.Wh[2] = bb + OB_W + SL_W2L5*2*HH;
        a.bias = fb + OF_BC + 3*H;
        a.Cb = bb + OB_REP; a.loOff = NG*H;
        a.M = NG; a.nterms = 3; a.flags = GEMM_RELU | GEMM_BF16;
        k_gemm_h<<<(NG + 127) / 128, 256, SMEM_GH>>>(a);
    }

    // persistent prediction GEMM (bf16 3-split)
    k_mma_pred<<<NCTA_PRED, 256, SMEM_PRED>>>(bb + OB_REP, bb + OB_REP + NG*H,
                                              bb + OB_PW,  bb + OB_PW + NI*H,
                                              pred_b, out);
    (void)in_sizes; (void)n_in; (void)out_size;
}

// round 9
// speedup vs baseline: 1.9721x; 1.1763x over previous
#include <cuda_runtime.h>
#include <cuda_bf16.h>
#include <cuda_fp16.h>
#include <cstdint>

// ----------------------------------------------------------------------------
// BaseGR hetero-SAGE on GB300 — R9.
// vs R8: (1) pred GEMM -> single-pass fp16 HMMA (calibrated error model says
// rel_err ~4.7e-4 < 1e-3), 3x fewer MMAs; (2) aggregation edge loop unroll 8.
// Layer GEMMs remain bf16 3-split.
// ----------------------------------------------------------------------------

#define NG 5000
#define NU 100000
#define NI 20000
#define H 128
#define HH (H*H)
#define E_UG 300000
#define E_UI 600000
#define E_GI 200000

// ---------------- fp32 scratch ----------------
#define OF_HU  0
#define OF_HI  (OF_HU  + NU*H)
#define OF_HU1 (OF_HI  + NI*H)
#define OF_HI1 (OF_HU1 + NU*H)
#define OF_BC  (OF_HI1 + NI*H)
#define F_TOTAL (OF_BC + 4*H)
__device__ float g_f[F_TOTAL];

// ---------------- bf16/fp16 scratch ------------------------------------------
#define OB_HUe 0
#define OB_HIe (OB_HUe + 2*NU*H)
#define OB_AIU (OB_HIe + 2*NI*H)
#define OB_AUI (OB_AIU + 2*NU*H)
#define OB_AUG (OB_AUI + 2*NI*H)
#define OB_AIG (OB_AUG + 2*NG*H)
#define OB_HG1 (OB_AIG + 2*NG*H)
#define OB_BUG (OB_HG1 + 2*NG*H)
#define OB_BIG (OB_BUG + 2*NG*H)
#define OB_REP (OB_BIG + 2*NG*H)   // fp16 REP (single plane, NG*H)
#define OB_PW  (OB_REP + 2*NG*H)   // fp16 pred_W^T (single plane, NI*H)
#define OB_W   (OB_PW  + 2*NI*H)
#define B_TOTAL (OB_W + 18*HH)
__device__ __nv_bfloat16 g_bf[B_TOTAL];

// weight slots in OB_W (each slot: hi HH then lo HH)
#define SL_W1L3 0
#define SL_WC0  1
#define SL_W1L2 2
#define SL_WC1  3
#define SL_W1L0 4
#define SL_W1L5 5
#define SL_W2L0 6
#define SL_WC2  7
#define SL_W2L5 8

// ---------------- int scratch ----------------
#define OI_CNT_G1 0
#define OI_CNT_G2 (OI_CNT_G1 + NG)
#define OI_CNT_U  (OI_CNT_G2 + NG)
#define OI_CNT_I  (OI_CNT_U  + NU)
#define CNT_TOTAL (OI_CNT_I  + NI)
#define OI_RP_G1  CNT_TOTAL
#define OI_RP_G2  (OI_RP_G1 + NG + 1)
#define OI_RP_U   (OI_RP_G2 + NG + 1)
#define OI_RP_I   (OI_RP_U  + NU + 1)
#define OI_CUR_G1 (OI_RP_I  + NI + 1)
#define OI_CUR_G2 (OI_CUR_G1 + NG)
#define OI_CUR_U  (OI_CUR_G2 + NG)
#define OI_CUR_I  (OI_CUR_U  + NU)
#define OI_COL_G1 (OI_CUR_I  + NI)
#define OI_COL_G2 (OI_COL_G1 + E_UG)
#define OI_COL_U  (OI_COL_G2 + E_GI)
#define OI_COL_I  (OI_COL_U  + E_UI)
#define I_TOTAL   (OI_COL_I  + E_UI)
__device__ int g_i[I_TOTAL];

// ======================= helpers =============================================
__device__ __forceinline__ uint32_t smem_u32(const void* p) {
    uint32_t a;
    asm("{ .reg .u64 t; cvta.to.shared.u64 t, %1; cvt.u32.u64 %0, t; }"
        : "=r"(a) : "l"(p));
    return a;
}

#define LDSM4(r, addr) \
    asm volatile("ldmatrix.sync.aligned.m8n8.x4.shared.b16 {%0,%1,%2,%3}, [%4];" \
                 : "=r"((r)[0]), "=r"((r)[1]), "=r"((r)[2]), "=r"((r)[3]) \
                 : "r"(addr))

#define MMA_BF16(c, a, b0, b1) \
    asm volatile("mma.sync.aligned.m16n8k16.row.col.f32.bf16.bf16.f32 " \
                 "{%0,%1,%2,%3}, {%4,%5,%6,%7}, {%8,%9}, {%0,%1,%2,%3};" \
                 : "+f"((c)[0]), "+f"((c)[1]), "+f"((c)[2]), "+f"((c)[3]) \
                 : "r"((a)[0]), "r"((a)[1]), "r"((a)[2]), "r"((a)[3]), \
                   "r"(b0), "r"(b1))

#define MMA_F16(c, a, b0, b1) \
    asm volatile("mma.sync.aligned.m16n8k16.row.col.f32.f16.f16.f32 " \
                 "{%0,%1,%2,%3}, {%4,%5,%6,%7}, {%8,%9}, {%0,%1,%2,%3};" \
                 : "+f"((c)[0]), "+f"((c)[1]), "+f"((c)[2]), "+f"((c)[3]) \
                 : "r"((a)[0]), "r"((a)[1]), "r"((a)[2]), "r"((a)[3]), \
                   "r"(b0), "r"(b1))

#define CPA16(dst, src, sz) \
    asm volatile("cp.async.cg.shared.global [%0], [%1], 16, %2;" \
                 :: "r"(dst), "l"(src), "r"(sz))
#define CP_COMMIT() asm volatile("cp.async.commit_group;" ::: "memory")
#define CP_WAIT0()  asm volatile("cp.async.wait_group 0;" ::: "memory")
#define CP_WAIT1()  asm volatile("cp.async.wait_group 1;" ::: "memory")

__device__ __forceinline__ void bfsplit2(float v0, float v1, uint32_t& h, uint32_t& l)
{
    __nv_bfloat16 h0 = __float2bfloat16(v0), h1 = __float2bfloat16(v1);
    float r0 = v0 - __bfloat162float(h0);
    float r1 = v1 - __bfloat162float(h1);
    __nv_bfloat16 l0 = __float2bfloat16(r0), l1 = __float2bfloat16(r1);
    h = (uint32_t)__bfloat16_as_ushort(h0) | ((uint32_t)__bfloat16_as_ushort(h1) << 16);
    l = (uint32_t)__bfloat16_as_ushort(l0) | ((uint32_t)__bfloat16_as_ushort(l1) << 16);
}

// ======================= merged gather (fp32 + bf16 hi/lo) ===================
__global__ void k_gather2m(const float* __restrict__ emb_u, const int* __restrict__ x_u,
                           const float* __restrict__ emb_i, const int* __restrict__ x_i,
                           float* __restrict__ fb, __nv_bfloat16* __restrict__ bbuf)
{
    int t = blockIdx.x * blockDim.x + threadIdx.x;
    const float* emb; const int* x;
    float* outf; __nv_bfloat16* hb; int loOff; int r;
    if (t < NU * 32) {
        emb = emb_u; x = x_u; outf = fb + OF_HU; hb = bbuf + OB_HUe; loOff = NU * H;
        r = t >> 5;
    } else if (t < (NU + NI) * 32) {
        t -= NU * 32;
        emb = emb_i; x = x_i; outf = fb + OF_HI; hb = bbuf + OB_HIe; loOff = NI * H;
        r = t >> 5;
    } else return;
    int c = t & 31;
    float4 v = ((const float4*)emb)[(size_t)x[r] * 32 + c];
    ((float4*)outf)[(size_t)r * 32 + c] = v;
    uint32_t h0, l0, h1, l1;
    bfsplit2(v.x, v.y, h0, l0);
    bfsplit2(v.z, v.w, h1, l1);
    size_t o = ((size_t)r * H + c * 4) >> 1;
    ((uint32_t*)hb)[o]     = h0;
    ((uint32_t*)hb)[o + 1] = h1;
    ((uint32_t*)(hb + loOff))[o]     = l0;
    ((uint32_t*)(hb + loOff))[o + 1] = l1;
}

// ======================= CSR build (merged) ==================================
__global__ void k_count_all(const int* __restrict__ ug_dst, const int* __restrict__ gi_src,
                            const int* __restrict__ ui_src, const int* __restrict__ ui_dst,
                            int* __restrict__ ib)
{
    int t = blockIdx.x * blockDim.x + threadIdx.x;
    if (t < E_UG) atomicAdd(&ib[OI_CNT_G1 + ug_dst[t]], 1);
    else if (t < E_UG + E_GI) atomicAdd(&ib[OI_CNT_G2 + gi_src[t - E_UG]], 1);
    else if (t < E_UG + E_GI + E_UI) atomicAdd(&ib[OI_CNT_U + ui_src[t - E_UG - E_GI]], 1);
    else if (t < E_UG + E_GI + 2*E_UI) atomicAdd(&ib[OI_CNT_I + ui_dst[t - E_UG - E_GI - E_UI]], 1);
}

__global__ void k_scan4(int* __restrict__ ib)
{
    const int* cnt; int* rp; int* cur; int n;
    switch (blockIdx.x) {
        case 0: cnt = ib + OI_CNT_G1; rp = ib + OI_RP_G1; cur = ib + OI_CUR_G1; n = NG; break;
        case 1: cnt = ib + OI_CNT_G2; rp = ib + OI_RP_G2; cur = ib + OI_CUR_G2; n = NG; break;
        case 2: cnt = ib + OI_CNT_U;  rp = ib + OI_RP_U;  cur = ib + OI_CUR_U;  n = NU; break;
        default: cnt = ib + OI_CNT_I; rp = ib + OI_RP_I;  cur = ib + OI_CUR_I;  n = NI; break;
    }
    __shared__ int ssum[1024];
    const int t = threadIdx.x;
    const int chunk = (n + 1023) / 1024;
    int beg = t * chunk;
    int end = beg + chunk; if (end > n) end = n;
    if (beg > n) beg = n;
    int s = 0;
    for (int i = beg; i < end; i++) s += cnt[i];
    ssum[t] = s;
    __syncthreads();
    for (int off = 1; off < 1024; off <<= 1) {
        int v = (t >= off) ? ssum[t - off] : 0;
        __syncthreads();
        ssum[t] += v;
        __syncthreads();
    }
    int prefix = (t == 0) ? 0 : ssum[t - 1];
    for (int i = beg; i < end; i++) {
        rp[i]  = prefix;
        cur[i] = prefix;
        prefix += cnt[i];
    }
    if (t == 1023) rp[n] = ssum[1023];
}

__global__ void k_bucket_all(const int* __restrict__ ug_src, const int* __restrict__ ug_dst,
                             const int* __restrict__ ui_src, const int* __restrict__ ui_dst,
                             const int* __restrict__ gi_src, const int* __restrict__ gi_dst,
                             int* __restrict__ ib)
{
    int t = blockIdx.x * blockDim.x + threadIdx.x;
    if (t < E_UG) {
        int p = atomicAdd(&ib[OI_CUR_G1 + ug_dst[t]], 1);
        ib[OI_COL_G1 + p] = ug_src[t];
    } else if (t < E_UG + E_GI) {
        int e = t - E_UG;
        int p = atomicAdd(&ib[OI_CUR_G2 + gi_src[e]], 1);
        ib[OI_COL_G2 + p] = gi_dst[e];
    } else if (t < E_UG + E_GI + E_UI) {
        int e = t - E_UG - E_GI;
        int p = atomicAdd(&ib[OI_CUR_U + ui_src[e]], 1);
        ib[OI_COL_U + p] = ui_dst[e];
    } else if (t < E_UG + E_GI + 2*E_UI) {
        int e = t - E_UG - E_GI - E_UI;
        int p = atomicAdd(&ib[OI_CUR_I + ui_dst[e]], 1);
        ib[OI_COL_I + p] = ui_src[e];
    }
}

// ======================= segment mean -> bf16 hi/lo (8-wide MLP) =============
__device__ __forceinline__ void agg_row(const int* __restrict__ rp, const int* __restrict__ col,
                                        const float* __restrict__ feat,
                                        __nv_bfloat16* __restrict__ hb, int loOff,
                                        int row, int lane)
{
    int beg = rp[row], end = rp[row + 1];
    float4 acc = make_float4(0.f, 0.f, 0.f, 0.f);
    const float4* fv = (const float4*)feat;
    int e = beg;
    for (; e + 8 <= end; e += 8) {
        int s[8];
#pragma unroll
        for (int q = 0; q < 8; q++) s[q] = __ldg(&col[e + q]);
        float4 v[8];
#pragma unroll
        for (int q = 0; q < 8; q++) v[q] = __ldg(&fv[(size_t)s[q] * 32 + lane]);
#pragma unroll
        for (int q = 0; q < 8; q++) {
            acc.x += v[q].x; acc.y += v[q].y; acc.z += v[q].z; acc.w += v[q].w;
        }
    }
    for (; e < end; e++) {
        int sx = __ldg(&col[e]);
        float4 v = __ldg(&fv[(size_t)sx * 32 + lane]);
        acc.x += v.x; acc.y += v.y; acc.z += v.z; acc.w += v.w;
    }
    float inv = (end > beg) ? 1.f / (float)(end - beg) : 0.f;
    acc.x *= inv; acc.y *= inv; acc.z *= inv; acc.w *= inv;
    uint32_t h0, l0, h1, l1;
    bfsplit2(acc.x, acc.y, h0, l0);
    bfsplit2(acc.z, acc.w, h1, l1);
    size_t o = ((size_t)row * H + lane * 4) >> 1;
    ((uint32_t*)hb)[o]     = h0;
    ((uint32_t*)hb)[o + 1] = h1;
    ((uint32_t*)(hb + loOff))[o]     = l0;
    ((uint32_t*)(hb + loOff))[o + 1] = l1;
}

__global__ void k_agg_all(const int* __restrict__ ib, const float* __restrict__ fb,
                          __nv_bfloat16* __restrict__ bb)
{
    int w = (int)((blockIdx.x * blockDim.x + threadIdx.x) >> 5);
    int lane = threadIdx.x & 31;
    if (w < NU)
        agg_row(ib + OI_RP_U, ib + OI_COL_U, fb + OF_HI, bb + OB_AIU, NU*H, w, lane);
    else if (w < NU + NI)
        agg_row(ib + OI_RP_I, ib + OI_COL_I, fb + OF_HU, bb + OB_AUI, NI*H, w - NU, lane);
    else if (w < NU + NI + NG)
        agg_row(ib + OI_RP_G1, ib + OI_COL_G1, fb + OF_HU, bb + OB_AUG, NG*H, w - NU - NI, lane);
    else if (w < NU + NI + 2*NG)
        agg_row(ib + OI_RP_G2, ib + OI_COL_G2, fb + OF_HI, bb + OB_AIG, NG*H, w - NU - NI - NG, lane);
}

__global__ void k_agg_all2(const int* __restrict__ ib, const float* __restrict__ fb,
                           __nv_bfloat16* __restrict__ bb)
{
    int w = (int)((blockIdx.x * blockDim.x + threadIdx.x) >> 5);
    int lane = threadIdx.x & 31;
    if (w < NG)
        agg_row(ib + OI_RP_G1, ib + OI_COL_G1, fb + OF_HU1, bb + OB_BUG, NG*H, w, lane);
    else if (w < 2*NG)
        agg_row(ib + OI_RP_G2, ib + OI_COL_G2, fb + OF_HI1, bb + OB_BIG, NG*H, w - NG, lane);
}

// ======================= weight prep (fused combine + transpose + split) =====
__global__ void __launch_bounds__(256)
k_splitW(const float* __restrict__ W1l, const float* __restrict__ W1r,
         const float* __restrict__ W2l, const float* __restrict__ W2r,
         __nv_bfloat16* __restrict__ dst9)
{
    const float* srcA; const float* srcB = nullptr;
    switch (blockIdx.z) {
        case 0: srcA = W1l + 3*HH; break;
        case 1: srcA = W1r + 1*HH; srcB = W1r + 3*HH; break;
        case 2: srcA = W1l + 2*HH; break;
        case 3: srcA = W1r + 2*HH; srcB = W1r + 4*HH; break;
        case 4: srcA = W1l + 0*HH; break;
        case 5: srcA = W1l + 5*HH; break;
        case 6: srcA = W2l + 0*HH; break;
        case 7: srcA = W2r + 0*HH; srcB = W2r + 5*HH; break;
        default: srcA = W2l + 5*HH; break;
    }
    __nv_bfloat16* hi = dst9 + (size_t)blockIdx.z * 2 * HH;
    __nv_bfloat16* lo = hi + HH;
    __shared__ float t[32][33];
    int nblk = blockIdx.x * 32;
    int kblk = blockIdx.y * 32;
    int tx = threadIdx.x, ty = threadIdx.y;
#pragma unroll
    for (int i = ty; i < 32; i += 8) {
        size_t gi = (size_t)(kblk + i) * H + nblk + tx;
        float v = srcA[gi];
        if (srcB) v += srcB[gi];
        t[i][tx] = v;
    }
    __syncthreads();
#pragma unroll
    for (int i = ty; i < 32; i += 8) {
        float x = t[tx][i];
        __nv_bfloat16 h = __float2bfloat16(x);
        size_t o = (size_t)(nblk + i) * H + kblk + tx;
        hi[o] = h;
        lo[o] = __float2bfloat16(x - __bfloat162float(h));
    }
}

__global__ void k_bias(const float* __restrict__ b1, const float* __restrict__ b2)
{
    int i = blockIdx.x * blockDim.x + threadIdx.x;
    float* bc = g_f + OF_BC;
    if (i < H) {
        bc[0*H + i] = b1[1*H + i] + b1[3*H + i];
        bc[1*H + i] = b1[2*H + i] + b1[4*H + i];
        bc[2*H + i] = b1[0*H + i] + b1[5*H + i];
        bc[3*H + i] = b2[0*H + i] + b2[5*H + i];
    }
}

// pred_W [H, NI] fp32 -> [NI, H] fp16 (transposed, K contiguous)
__global__ void __launch_bounds__(256)
k_halfB(const float* __restrict__ W, __half* __restrict__ out)
{
    __shared__ float t[32][33];
    int nblk = blockIdx.x * 32;
    int kblk = blockIdx.y * 32;
    int tx = threadIdx.x, ty = threadIdx.y;
#pragma unroll
    for (int i = ty; i < 32; i += 8)
        t[i][tx] = W[(size_t)(kblk + i) * NI + nblk + tx];
    __syncthreads();
#pragma unroll
    for (int i = ty; i < 32; i += 8)
        out[(size_t)(nblk + i) * H + kblk + tx] = __float2half(t[tx][i]);
}

// ======================= common GEMM constants ===============================
#define PK   136
#define ROWB (PK * 2)          // 272 B per row
#define TILEB (128 * ROWB)     // 34816 B
#define HTILE (64 * ROWB)      // 17408 B

#define GEMM_RELU 1
#define GEMM_BF16 2
#define GEMM_F16  4

// ======================= HMMA layer-2 GEMM (multi-term, small) ===============
struct GemmArgs {
    const __nv_bfloat16* Ah[3];
    const __nv_bfloat16* Al[3];
    const __nv_bfloat16* Wh[3];
    const float* bias;
    float* Cf;
    __nv_bfloat16* Cb;
    __half* Ch;
    int M, nterms, flags, loOff;
};

#define SMEM_GH (4 * TILEB)    // 139264

__global__ void __launch_bounds__(256, 1)
k_gemm_h(GemmArgs g)
{
    extern __shared__ char sm[];
    const int tid  = threadIdx.x;
    const int wid  = tid >> 5;
    const int lane = tid & 31;
    const int wm   = wid >> 1;
    const int wn   = wid & 1;
    const int m0   = blockIdx.x * 128;

    const uint32_t sbase  = smem_u32(sm);
    const uint32_t a_loff = (uint32_t)(lane & 15) * ROWB + (uint32_t)(lane >> 4) * 16;
    const uint32_t b_loff = (uint32_t)(((lane >> 4) * 8) + (lane & 7)) * ROWB
                          + (uint32_t)((lane >> 3) & 1) * 16;

    float c[2][8][4];
#pragma unroll
    for (int i = 0; i < 2; i++)
#pragma unroll
        for (int j = 0; j < 8; j++)
#pragma unroll
            for (int q = 0; q < 4; q++) c[i][j][q] = 0.f;

#pragma unroll 1
    for (int t = 0; t < g.nterms; t++) {
        const uint4* wh = (const uint4*)g.Wh[t];
        const uint4* wl = (const uint4*)(g.Wh[t] + HH);
        const uint4* ah = (const uint4*)g.Ah[t];
        const uint4* al = (const uint4*)g.Al[t];
#pragma unroll 4
        for (int i = tid; i < 2048; i += 256) {
            int row = i >> 4, cq = i & 15;
            uint32_t so = (uint32_t)row * ROWB + cq * 16;
            *(uint4*)(sm + 0*TILEB + so) = __ldg(&wh[row * 16 + cq]);
            *(uint4*)(sm + 1*TILEB + so) = __ldg(&wl[row * 16 + cq]);
            uint4 va = make_uint4(0,0,0,0), vb = va;
            if (m0 + row < g.M) {
                size_t gi = (size_t)(m0 + row) * 16 + cq;
                va = __ldg(&ah[gi]);
                vb = __ldg(&al[gi]);
            }
            *(uint4*)(sm + 2*TILEB + so) = va;
            *(uint4*)(sm + 3*TILEB + so) = vb;
        }
        __syncthreads();
#pragma unroll 1
        for (int sp = 0; sp < 3; sp++) {
            uint32_t aB = sbase + (sp == 2 ? 3*TILEB : 2*TILEB)
                        + (uint32_t)wm * 32 * ROWB + a_loff;
            uint32_t bB = sbase + (sp == 1 ? 1*TILEB : 0)
                        + (uint32_t)wn * 64 * ROWB + b_loff;
#pragma unroll
            for (int ks = 0; ks < 8; ks++) {
                uint32_t a[2][4], b[4][4];
                LDSM4(a[0], aB + ks * 32);
                LDSM4(a[1], aB + ks * 32 + 16 * ROWB);
#pragma unroll
                for (int q = 0; q < 4; q++)
                    LDSM4(b[q], bB + ks * 32 + q * 16 * ROWB);
#pragma unroll
                for (int ma = 0; ma < 2; ma++)
#pragma unroll
                    for (int na = 0; na < 8; na++)
                        MMA_BF16(c[ma][na], a[ma],
                                 b[na >> 1][(na & 1) * 2], b[na >> 1][(na & 1) * 2 + 1]);
            }
        }
        __syncthreads();
    }

    const int gid = lane >> 2;
    const int tq  = (lane & 3) * 2;
    const bool relu = (g.flags & GEMM_RELU) != 0;
    const bool bfo  = (g.flags & GEMM_BF16) != 0;
    const bool f16o = (g.flags & GEMM_F16) != 0;
#pragma unroll
    for (int ma = 0; ma < 2; ma++) {
#pragma unroll
        for (int na = 0; na < 8; na++) {
            int mrow = m0 + wm * 32 + ma * 16 + gid;
            int ncol = wn * 64 + na * 8 + tq;
            float2 bv = *(const float2*)(g.bias + ncol);
#pragma unroll
            for (int hrow = 0; hrow < 2; hrow++) {
                int mr = mrow + hrow * 8;
                if (mr >= g.M) continue;
                float v0 = c[ma][na][hrow*2 + 0] + bv.x;
                float v1 = c[ma][na][hrow*2 + 1] + bv.y;
                if (relu) { v0 = fmaxf(v0, 0.f); v1 = fmaxf(v1, 0.f); }
                if (f16o) {
                    __half2 hv = __floats2half2_rn(v0, v1);
                    *(__half2*)(g.Ch + (size_t)mr * H + ncol) = hv;
                } else if (bfo) {
                    uint32_t hw, lw;
                    bfsplit2(v0, v1, hw, lw);
                    *(uint32_t*)(g.Cb + (size_t)mr * H + ncol) = hw;
                    *(uint32_t*)(g.Cb + (size_t)g.loOff + (size_t)mr * H + ncol) = lw;
                } else {
                    *(float2*)(g.Cf + (size_t)mr * H + ncol) = make_float2(v0, v1);
                }
            }
        }
    }
}

// ======================= persistent layer-1 GEMM =============================
struct LJob {
    const __nv_bfloat16* Ah0; const __nv_bfloat16* Al0;
    const __nv_bfloat16* Ah1; const __nv_bfloat16* Al1;
    const __nv_bfloat16* Wh0; const __nv_bfloat16* Wh1;
    const float* bias;
    float* Cf;
    __nv_bfloat16* Cb;
    int loOff, M, ntiles, ctaBase, nctas, flags;
};
struct LJob3 { LJob j[3]; };

#define SMEM_GL (4 * TILEB + 4 * HTILE)   // 208896

__device__ __forceinline__ void loadA64(uint32_t dst, const uint4* ah, const uint4* al,
                                        int m0_, int M, int tid)
{
#pragma unroll 2
    for (int i = tid; i < 1024; i += 256) {
        int row = i >> 4, cq = i & 15;
        int gr = m0_ + row;
        int sz = (gr < M) ? 16 : 0;
        if (gr >= M) gr = M - 1;
        uint32_t so = dst + (uint32_t)row * ROWB + cq * 16;
        CPA16(so,         ah + (size_t)gr * 16 + cq, sz);
        CPA16(so + HTILE, al + (size_t)gr * 16 + cq, sz);
    }
}

__global__ void __launch_bounds__(256, 1)
k_gemm_l(LJob3 js)
{
    extern __shared__ char sm[];
    const int tid  = threadIdx.x;
    const int wid  = tid >> 5;
    const int lane = tid & 31;
    const int wm   = wid >> 2;
    const int wn   = wid & 3;

    int ji = (blockIdx.x >= (uint32_t)js.j[2].ctaBase) ? 2
           : (blockIdx.x >= (uint32_t)js.j[1].ctaBase) ? 1 : 0;
    const LJob g = js.j[ji];
    const int idx = blockIdx.x - g.ctaBase;
    const int beg = (int)((long long)idx * g.ntiles / g.nctas);
    const int end = (int)((long long)(idx + 1) * g.ntiles / g.nctas);
    if (beg >= end) return;

    const uint32_t sbase = smem_u32(sm);
    const uint32_t sA    = sbase + 4 * TILEB;

    {
        const uint4* wsrc0 = (const uint4*)g.Wh0;
        const uint4* wsrc1 = (const uint4*)(g.Wh0 + HH);
        const uint4* wsrc2 = (const uint4*)g.Wh1;
        const uint4* wsrc3 = (const uint4*)(g.Wh1 + HH);
#pragma unroll 4
        for (int i = tid; i < 8192; i += 256) {
            int tl = i >> 11;
            int row = (i >> 4) & 127;
            int cq = i & 15;
            const uint4* src = (tl == 0) ? wsrc0 : (tl == 1) ? wsrc1 : (tl == 2) ? wsrc2 : wsrc3;
            CPA16(sbase + (uint32_t)tl * TILEB + (uint32_t)row * ROWB + cq * 16,
                  src + (size_t)row * 16 + cq, 16);
        }
    }
    loadA64(sA, (const uint4*)g.Ah0, (const uint4*)g.Al0, beg * 64, g.M, tid);
    CP_COMMIT();

    const uint32_t a_loff = (uint32_t)(lane & 15) * ROWB + (uint32_t)(lane >> 4) * 16;
    const uint32_t b_loff = (uint32_t)(((lane >> 4) * 8) + (lane & 7)) * ROWB
                          + (uint32_t)((lane >> 3) & 1) * 16;
    const int gid = lane >> 2;
    const int tq  = (lane & 3) * 2;
    const bool relu = (g.flags & GEMM_RELU) != 0;
    const bool bfo  = (g.flags & GEMM_BF16) != 0;

    float c[2][4][4];
    const int nit = (end - beg) * 2;
    int buf = 0;

#pragma unroll 1
    for (int it = 0; it < nit; it++) {
        const int tile = beg + (it >> 1);
        const int term = it & 1;
        if (it + 1 < nit) {
            int ntile = beg + ((it + 1) >> 1);
            int nterm = (it + 1) & 1;
            const uint4* ah = (const uint4*)(nterm ? g.Ah1 : g.Ah0);
            const uint4* al = (const uint4*)(nterm ? g.Al1 : g.Al0);
            loadA64(sA + (uint32_t)(buf ^ 1) * 2 * HTILE, ah, al, ntile * 64, g.M, tid);
            CP_COMMIT();
            CP_WAIT1();
        } else {
            CP_WAIT0();
        }
        __syncthreads();

        if (term == 0) {
#pragma unroll
            for (int i = 0; i < 2; i++)
#pragma unroll
                for (int j = 0; j < 4; j++)
#pragma unroll
                    for (int q = 0; q < 4; q++) c[i][j][q] = 0.f;
        }

        const uint32_t curA = sA + (uint32_t)buf * 2 * HTILE;
        const uint32_t wBase = sbase + (uint32_t)term * 2 * TILEB;
#pragma unroll 1
        for (int sp = 0; sp < 3; sp++) {
            uint32_t aB = curA + (sp == 2 ? HTILE : 0) + (uint32_t)wm * 32 * ROWB + a_loff;
            uint32_t bB = wBase + (sp == 1 ? TILEB : 0) + (uint32_t)wn * 32 * ROWB + b_loff;
#pragma unroll
            for (int ks = 0; ks < 8; ks++) {
                uint32_t a[2][4], b[2][4];
                LDSM4(a[0], aB + ks * 32);
                LDSM4(a[1], aB + ks * 32 + 16 * ROWB);
                LDSM4(b[0], bB + ks * 32);
                LDSM4(b[1], bB + ks * 32 + 16 * ROWB);
#pragma unroll
                for (int ma = 0; ma < 2; ma++)
#pragma unroll
                    for (int na = 0; na < 4; na++)
                        MMA_BF16(c[ma][na], a[ma],
                                 b[na >> 1][(na & 1) * 2], b[na >> 1][(na & 1) * 2 + 1]);
            }
        }

        if (term == 1) {
            int m0_ = tile * 64;
#pragma unroll
            for (int ma = 0; ma < 2; ma++) {
#pragma unroll
                for (int na = 0; na < 4; na++) {
                    int mrow = m0_ + wm * 32 + ma * 16 + gid;
                    int ncol = wn * 32 + na * 8 + tq;
                    float2 bv = *(const float2*)(g.bias + ncol);
#pragma unroll
                    for (int hrow = 0; hrow < 2; hrow++) {
                        int mr = mrow + hrow * 8;
                        if (mr >= g.M) continue;
                        float v0 = c[ma][na][hrow*2 + 0] + bv.x;
                        float v1 = c[ma][na][hrow*2 + 1] + bv.y;
                        if (relu) { v0 = fmaxf(v0, 0.f); v1 = fmaxf(v1, 0.f); }
                        if (bfo) {
                            uint32_t hw, lw;
                            bfsplit2(v0, v1, hw, lw);
                            *(uint32_t*)(g.Cb + (size_t)mr * H + ncol) = hw;
                            *(uint32_t*)(g.Cb + (size_t)g.loOff + (size_t)mr * H + ncol) = lw;
                        } else {
                            *(float2*)(g.Cf + (size_t)mr * H + ncol) = make_float2(v0, v1);
                        }
                    }
                }
            }
        }
        __syncthreads();
        buf ^= 1;
    }
}

// ======================= persistent fp16 pred GEMM ===========================
// out[NG,NI] = REP16[NG,128] @ PW16[NI,128]^T + bias (single fp16 term).
#define NTN ((NI + 127) / 128)    // 157
#define NTM ((NG + 127) / 128)    // 40
#define NT_TOT (NTN * NTM)        // 6280
#define NCTA_PRED 148
#define SMEM_PREDH (3 * TILEB)    // A + 2 x B = 104448

__device__ __forceinline__ void pred_load1(uint32_t dst, const uint4* gp,
                                           int r0_, int rmax, int tid)
{
#pragma unroll 4
    for (int i = tid; i < 2048; i += 256) {
        int row = i >> 4, cq = i & 15;
        int gr = r0_ + row;
        int sz = (gr < rmax) ? 16 : 0;
        if (gr >= rmax) gr = rmax - 1;
        CPA16(dst + (uint32_t)row * ROWB + cq * 16, gp + (size_t)gr * 16 + cq, sz);
    }
}

__global__ void __launch_bounds__(256, 1)
k_mma_pred(const __half* __restrict__ A, const __half* __restrict__ B,
           const float* __restrict__ bias, float* __restrict__ out)
{
    extern __shared__ char sm[];
    const int tid  = threadIdx.x;
    const int wid  = tid >> 5;
    const int lane = tid & 31;
    const int wm   = wid >> 1;
    const int wn   = wid & 1;

    const uint32_t sbase = smem_u32(sm);
    const uint32_t sB    = sbase + TILEB;

    const uint4* gA = (const uint4*)A;
    const uint4* gB = (const uint4*)B;

    const int beg = (int)((long long)blockIdx.x * NT_TOT / NCTA_PRED);
    const int end = (int)((long long)(blockIdx.x + 1) * NT_TOT / NCTA_PRED);

    const uint32_t a_loff = (uint32_t)(lane & 15) * ROWB + (uint32_t)(lane >> 4) * 16;
    const uint32_t b_loff = (uint32_t)(((lane >> 4) * 8) + (lane & 7)) * ROWB
                          + (uint32_t)((lane >> 3) & 1) * 16;
    const int gid = lane >> 2;
    const int tq  = (lane & 3) * 2;

    int cur_m = -1;
    int buf = 0;

#pragma unroll 1
    for (int t = beg; t < end; ++t) {
        int tm = t / NTN, tn = t - tm * NTN;
        if (tm != cur_m) {
            CP_WAIT0();
            __syncthreads();
            pred_load1(sbase, gA, tm * 128, NG, tid);
            pred_load1(sB, gB, tn * 128, NI, tid);
            CP_COMMIT();
            cur_m = tm;
            buf = 0;
            if (t + 1 < end && (t + 1) / NTN == cur_m) {
                pred_load1(sB + TILEB, gB, (tn + 1) * 128, NI, tid);
                CP_COMMIT();
                CP_WAIT1();
            } else {
                CP_WAIT0();
            }
            __syncthreads();
        } else {
            if (t + 1 < end && (t + 1) / NTN == cur_m) {
                pred_load1(sB + (uint32_t)(buf ^ 1) * TILEB, gB, (tn + 1) * 128, NI, tid);
                CP_COMMIT();
                CP_WAIT1();
            } else {
                CP_WAIT0();
            }
            __syncthreads();
        }

        float c[2][8][4];
#pragma unroll
        for (int i = 0; i < 2; i++)
#pragma unroll
            for (int j = 0; j < 8; j++)
#pragma unroll
                for (int q = 0; q < 4; q++) c[i][j][q] = 0.f;

        uint32_t aB = sbase + (uint32_t)wm * 32 * ROWB + a_loff;
        uint32_t bB = sB + (uint32_t)buf * TILEB + (uint32_t)wn * 64 * ROWB + b_loff;
#pragma unroll
        for (int ks = 0; ks < 8; ks++) {
            uint32_t a[2][4], b[4][4];
            LDSM4(a[0], aB + ks * 32);
            LDSM4(a[1], aB + ks * 32 + 16 * ROWB);
#pragma unroll
            for (int q = 0; q < 4; q++)
                LDSM4(b[q], bB + ks * 32 + q * 16 * ROWB);
#pragma unroll
            for (int ma = 0; ma < 2; ma++)
#pragma unroll
                for (int na = 0; na < 8; na++)
                    MMA_F16(c[ma][na], a[ma],
                            b[na >> 1][(na & 1) * 2], b[na >> 1][(na & 1) * 2 + 1]);
        }

        int m0_ = tm * 128, n0_ = tn * 128;
#pragma unroll
        for (int ma = 0; ma < 2; ma++) {
#pragma unroll
            for (int na = 0; na < 8; na++) {
                int mrow = m0_ + wm * 32 + ma * 16 + gid;
                int ncol = n0_ + wn * 64 + na * 8 + tq;
                if (ncol >= NI) continue;
                float2 bv = *(const float2*)(bias + ncol);
                if (mrow < NG) {
                    float2 v = make_float2(c[ma][na][0] + bv.x, c[ma][na][1] + bv.y);
                    *(float2*)(out + (size_t)mrow * NI + ncol) = v;
                }
                if (mrow + 8 < NG) {
                    float2 v = make_float2(c[ma][na][2] + bv.x, c[ma][na][3] + bv.y);
                    *(float2*)(out + (size_t)(mrow + 8) * NI + ncol) = v;
                }
            }
        }
        __syncthreads();
        buf ^= 1;
    }
}

// ---------------------------------------------------------------------------
extern "C" void kernel_launch(void* const* d_in, const int* in_sizes, int n_in,
                              void* d_out, int out_size)
{
    const int*   x_user   = (const int*)  d_in[1];
    const int*   x_item   = (const int*)  d_in[2];
    const float* emb_user = (const float*)d_in[4];
    const float* emb_item = (const float*)d_in[5];
    const float* W1l      = (const float*)d_in[6];
    const float* W1r      = (const float*)d_in[7];
    const float* b1       = (const float*)d_in[8];
    const float* W2l      = (const float*)d_in[9];
    const float* W2r      = (const float*)d_in[10];
    const float* b2       = (const float*)d_in[11];
    const float* pred_W   = (const float*)d_in[12];
    const float* pred_b   = (const float*)d_in[13];
    const int*   ug_src   = (const int*)  d_in[14];
    const int*   ug_dst   = (const int*)  d_in[15];
    const int*   ui_src   = (const int*)  d_in[16];
    const int*   ui_dst   = (const int*)  d_in[17];
    const int*   gi_src   = (const int*)  d_in[18];
    const int*   gi_dst   = (const int*)  d_in[19];
    float* out = (float*)d_out;

    float* fb = nullptr; int* ib = nullptr; __nv_bfloat16* bb = nullptr;
    cudaGetSymbolAddress((void**)&fb, g_f);
    cudaGetSymbolAddress((void**)&ib, g_i);
    cudaGetSymbolAddress((void**)&bb, g_bf);
    __half* repH = (__half*)(bb + OB_REP);
    __half* pwH  = (__half*)(bb + OB_PW);

    cudaFuncSetAttribute(k_gemm_h, cudaFuncAttributeMaxDynamicSharedMemorySize, SMEM_GH);
    cudaFuncSetAttribute(k_gemm_l, cudaFuncAttributeMaxDynamicSharedMemorySize, SMEM_GL);
    cudaFuncSetAttribute(k_mma_pred, cudaFuncAttributeMaxDynamicSharedMemorySize, SMEM_PREDH);

    cudaMemsetAsync(ib + OI_CNT_G1, 0, (size_t)CNT_TOTAL * sizeof(int));

    // weight prep
    k_halfB<<<dim3(NI / 32, H / 32), dim3(32, 8)>>>(pred_W, pwH);
    k_bias<<<1, 128>>>(b1, b2);
    k_splitW<<<dim3(4, 4, 9), dim3(32, 8)>>>(W1l, W1r, W2l, W2r, bb + OB_W);

    // merged embedding gathers (fp32 + bf16 hi/lo)
    k_gather2m<<<((NU + NI) * 32 + 255) / 256, 256>>>(emb_user, x_user, emb_item, x_item,
                                                      fb, bb);

    // CSR build
    {
        int tot = E_UG + E_GI + 2 * E_UI;
        k_count_all<<<(tot + 255) / 256, 256>>>(ug_dst, gi_src, ui_src, ui_dst, ib);
        k_scan4<<<4, 1024>>>(ib);
        k_bucket_all<<<(tot + 255) / 256, 256>>>(ug_src, ug_dst, ui_src, ui_dst,
                                                 gi_src, gi_dst, ib);
    }

    // layer-1 aggregations -> bf16 hi/lo
    {
        int warps = NU + NI + 2 * NG;
        k_agg_all<<<(warps + 7) / 8, 256>>>(ib, fb, bb);
    }

    // layer-1 GEMMs: one persistent launch, 3 jobs
    {
        LJob3 js;
        js.j[0].Ah0 = bb + OB_AIU;  js.j[0].Al0 = bb + OB_AIU + NU*H;
        js.j[0].Ah1 = bb + OB_HUe;  js.j[0].Al1 = bb + OB_HUe + NU*H;
        js.j[0].Wh0 = bb + OB_W + SL_W1L3*2*HH;
        js.j[0].Wh1 = bb + OB_W + SL_WC0*2*HH;
        js.j[0].bias = fb + OF_BC + 0*H;
        js.j[0].Cf = fb + OF_HU1; js.j[0].Cb = nullptr; js.j[0].loOff = 0;
        js.j[0].M = NU; js.j[0].ntiles = (NU + 63) / 64;
        js.j[0].ctaBase = 0;   js.j[0].nctas = 118; js.j[0].flags = GEMM_RELU;
        js.j[1].Ah0 = bb + OB_AUI;  js.j[1].Al0 = bb + OB_AUI + NI*H;
        js.j[1].Ah1 = bb + OB_HIe;  js.j[1].Al1 = bb + OB_HIe + NI*H;
        js.j[1].Wh0 = bb + OB_W + SL_W1L2*2*HH;
        js.j[1].Wh1 = bb + OB_W + SL_WC1*2*HH;
        js.j[1].bias = fb + OF_BC + 1*H;
        js.j[1].Cf = fb + OF_HI1; js.j[1].Cb = nullptr; js.j[1].loOff = 0;
        js.j[1].M = NI; js.j[1].ntiles = (NI + 63) / 64;
        js.j[1].ctaBase = 118; js.j[1].nctas = 24; js.j[1].flags = GEMM_RELU;
        js.j[2].Ah0 = bb + OB_AUG;  js.j[2].Al0 = bb + OB_AUG + NG*H;
        js.j[2].Ah1 = bb + OB_AIG;  js.j[2].Al1 = bb + OB_AIG + NG*H;
        js.j[2].Wh0 = bb + OB_W + SL_W1L0*2*HH;
        js.j[2].Wh1 = bb + OB_W + SL_W1L5*2*HH;
        js.j[2].bias = fb + OF_BC + 2*H;
        js.j[2].Cf = nullptr; js.j[2].Cb = bb + OB_HG1; js.j[2].loOff = NG*H;
        js.j[2].M = NG; js.j[2].ntiles = (NG + 63) / 64;
        js.j[2].ctaBase = 142; js.j[2].nctas = 6; js.j[2].flags = GEMM_RELU | GEMM_BF16;
        k_gemm_l<<<148, 256, SMEM_GL>>>(js);
    }

    // layer-2 aggregations
    k_agg_all2<<<(2 * NG + 7) / 8, 256>>>(ib, fb, bb);

    // layer-2 group GEMM (3 terms) -> REP fp16
    {
        GemmArgs a = {};
        a.Ah[0] = bb + OB_BUG;  a.Al[0] = bb + OB_BUG + NG*H;  a.Wh[0] = bb + OB_W + SL_W2L0*2*HH;
        a.Ah[1] = bb + OB_HG1;  a.Al[1] = bb + OB_HG1 + NG*H;  a.Wh[1] = bb + OB_W + SL_WC2*2*HH;
        a.Ah[2] = bb + OB_BIG;  a.Al[2] = bb + OB_BIG + NG*H;  a.Wh[2] = bb + OB_W + SL_W2L5*2*HH;
        a.bias = fb + OF_BC + 3*H;
        a.Ch = repH;
        a.M = NG; a.nterms = 3; a.flags = GEMM_RELU | GEMM_F16;
        k_gemm_h<<<(NG + 127) / 128, 256, SMEM_GH>>>(a);
    }

    // persistent fp16 prediction GEMM
    k_mma_pred<<<NCTA_PRED, 256, SMEM_PREDH>>>(repH, pwH, pred_b, out);
    (void)in_sizes; (void)n_in; (void)out_size;
}

// round 10
// speedup vs baseline: 2.0282x; 1.0284x over previous
#include <cuda_runtime.h>
#include <cuda_bf16.h>
#include <cuda_fp16.h>
#include <cstdint>

// ----------------------------------------------------------------------------
// BaseGR hetero-SAGE on GB300 — R10.
// vs R9: aggregation feature tables switched fp32 -> fp16 (HU/HI from gather,
// HU1/HI1 from layer-1 GEMM epilogue). Halves the ~1.1 GB of random row-gather
// traffic that dominates aggregation. Accumulation stays fp32; GEMM numerics
// unchanged (bf16 3-split layers, fp16 pred).
// ----------------------------------------------------------------------------

#define NG 5000
#define NU 100000
#define NI 20000
#define H 128
#define HH (H*H)
#define E_UG 300000
#define E_UI 600000
#define E_GI 200000

// ---------------- fp32 scratch (biases only) ----------------
#define OF_BC  0
#define F_TOTAL (OF_BC + 4*H)
__device__ float g_f[F_TOTAL];

// ---------------- fp16 feature tables (aggregation inputs) -------------------
#define OH_HU  0
#define OH_HI  (OH_HU  + NU*H)
#define OH_HU1 (OH_HI  + NI*H)
#define OH_HI1 (OH_HU1 + NU*H)
#define H_TOTAL (OH_HI1 + NI*H)
__device__ __half g_h[H_TOTAL];

// ---------------- bf16/fp16 scratch ------------------------------------------
#define OB_HUe 0
#define OB_HIe (OB_HUe + 2*NU*H)
#define OB_AIU (OB_HIe + 2*NI*H)
#define OB_AUI (OB_AIU + 2*NU*H)
#define OB_AUG (OB_AUI + 2*NI*H)
#define OB_AIG (OB_AUG + 2*NG*H)
#define OB_HG1 (OB_AIG + 2*NG*H)
#define OB_BUG (OB_HG1 + 2*NG*H)
#define OB_BIG (OB_BUG + 2*NG*H)
#define OB_REP (OB_BIG + 2*NG*H)   // fp16 REP (aliased)
#define OB_PW  (OB_REP + 2*NG*H)   // fp16 pred_W^T (aliased)
#define OB_W   (OB_PW  + 2*NI*H)
#define B_TOTAL (OB_W + 18*HH)
__device__ __nv_bfloat16 g_bf[B_TOTAL];

// weight slots in OB_W (each slot: hi HH then lo HH)
#define SL_W1L3 0
#define SL_WC0  1
#define SL_W1L2 2
#define SL_WC1  3
#define SL_W1L0 4
#define SL_W1L5 5
#define SL_W2L0 6
#define SL_WC2  7
#define SL_W2L5 8

// ---------------- int scratch ----------------
#define OI_CNT_G1 0
#define OI_CNT_G2 (OI_CNT_G1 + NG)
#define OI_CNT_U  (OI_CNT_G2 + NG)
#define OI_CNT_I  (OI_CNT_U  + NU)
#define CNT_TOTAL (OI_CNT_I  + NI)
#define OI_RP_G1  CNT_TOTAL
#define OI_RP_G2  (OI_RP_G1 + NG + 1)
#define OI_RP_U   (OI_RP_G2 + NG + 1)
#define OI_RP_I   (OI_RP_U  + NU + 1)
#define OI_CUR_G1 (OI_RP_I  + NI + 1)
#define OI_CUR_G2 (OI_CUR_G1 + NG)
#define OI_CUR_U  (OI_CUR_G2 + NG)
#define OI_CUR_I  (OI_CUR_U  + NU)
#define OI_COL_G1 (OI_CUR_I  + NI)
#define OI_COL_G2 (OI_COL_G1 + E_UG)
#define OI_COL_U  (OI_COL_G2 + E_GI)
#define OI_COL_I  (OI_COL_U  + E_UI)
#define I_TOTAL   (OI_COL_I  + E_UI)
__device__ int g_i[I_TOTAL];

// ======================= helpers =============================================
__device__ __forceinline__ uint32_t smem_u32(const void* p) {
    uint32_t a;
    asm("{ .reg .u64 t; cvta.to.shared.u64 t, %1; cvt.u32.u64 %0, t; }"
        : "=r"(a) : "l"(p));
    return a;
}

#define LDSM4(r, addr) \
    asm volatile("ldmatrix.sync.aligned.m8n8.x4.shared.b16 {%0,%1,%2,%3}, [%4];" \
                 : "=r"((r)[0]), "=r"((r)[1]), "=r"((r)[2]), "=r"((r)[3]) \
                 : "r"(addr))

#define MMA_BF16(c, a, b0, b1) \
    asm volatile("mma.sync.aligned.m16n8k16.row.col.f32.bf16.bf16.f32 " \
                 "{%0,%1,%2,%3}, {%4,%5,%6,%7}, {%8,%9}, {%0,%1,%2,%3};" \
                 : "+f"((c)[0]), "+f"((c)[1]), "+f"((c)[2]), "+f"((c)[3]) \
                 : "r"((a)[0]), "r"((a)[1]), "r"((a)[2]), "r"((a)[3]), \
                   "r"(b0), "r"(b1))

#define MMA_F16(c, a, b0, b1) \
    asm volatile("mma.sync.aligned.m16n8k16.row.col.f32.f16.f16.f32 " \
                 "{%0,%1,%2,%3}, {%4,%5,%6,%7}, {%8,%9}, {%0,%1,%2,%3};" \
                 : "+f"((c)[0]), "+f"((c)[1]), "+f"((c)[2]), "+f"((c)[3]) \
                 : "r"((a)[0]), "r"((a)[1]), "r"((a)[2]), "r"((a)[3]), \
                   "r"(b0), "r"(b1))

#define CPA16(dst, src, sz) \
    asm volatile("cp.async.cg.shared.global [%0], [%1], 16, %2;" \
                 :: "r"(dst), "l"(src), "r"(sz))
#define CP_COMMIT() asm volatile("cp.async.commit_group;" ::: "memory")
#define CP_WAIT0()  asm volatile("cp.async.wait_group 0;" ::: "memory")
#define CP_WAIT1()  asm volatile("cp.async.wait_group 1;" ::: "memory")

__device__ __forceinline__ void bfsplit2(float v0, float v1, uint32_t& h, uint32_t& l)
{
    __nv_bfloat16 h0 = __float2bfloat16(v0), h1 = __float2bfloat16(v1);
    float r0 = v0 - __bfloat162float(h0);
    float r1 = v1 - __bfloat162float(h1);
    __nv_bfloat16 l0 = __float2bfloat16(r0), l1 = __float2bfloat16(r1);
    h = (uint32_t)__bfloat16_as_ushort(h0) | ((uint32_t)__bfloat16_as_ushort(h1) << 16);
    l = (uint32_t)__bfloat16_as_ushort(l0) | ((uint32_t)__bfloat16_as_ushort(l1) << 16);
}

// ======================= merged gather (fp16 + bf16 hi/lo) ===================
__global__ void k_gather2m(const float* __restrict__ emb_u, const int* __restrict__ x_u,
                           const float* __restrict__ emb_i, const int* __restrict__ x_i,
                           __half* __restrict__ hh, __nv_bfloat16* __restrict__ bbuf)
{
    int t = blockIdx.x * blockDim.x + threadIdx.x;
    const float* emb; const int* x;
    __half* outh; __nv_bfloat16* hb; int loOff; int r;
    if (t < NU * 32) {
        emb = emb_u; x = x_u; outh = hh + OH_HU; hb = bbuf + OB_HUe; loOff = NU * H;
        r = t >> 5;
    } else if (t < (NU + NI) * 32) {
        t -= NU * 32;
        emb = emb_i; x = x_i; outh = hh + OH_HI; hb = bbuf + OB_HIe; loOff = NI * H;
        r = t >> 5;
    } else return;
    int c = t & 31;
    float4 v = ((const float4*)emb)[(size_t)x[r] * 32 + c];
    __half2 p0 = __floats2half2_rn(v.x, v.y);
    __half2 p1 = __floats2half2_rn(v.z, v.w);
    uint2 hv;
    hv.x = *(uint32_t*)&p0;
    hv.y = *(uint32_t*)&p1;
    ((uint2*)outh)[(size_t)r * 32 + c] = hv;
    uint32_t h0, l0, h1, l1;
    bfsplit2(v.x, v.y, h0, l0);
    bfsplit2(v.z, v.w, h1, l1);
    size_t o = ((size_t)r * H + c * 4) >> 1;
    ((uint32_t*)hb)[o]     = h0;
    ((uint32_t*)hb)[o + 1] = h1;
    ((uint32_t*)(hb + loOff))[o]     = l0;
    ((uint32_t*)(hb + loOff))[o + 1] = l1;
}

// ======================= CSR build (merged) ==================================
__global__ void k_count_all(const int* __restrict__ ug_dst, const int* __restrict__ gi_src,
                            const int* __restrict__ ui_src, const int* __restrict__ ui_dst,
                            int* __restrict__ ib)
{
    int t = blockIdx.x * blockDim.x + threadIdx.x;
    if (t < E_UG) atomicAdd(&ib[OI_CNT_G1 + ug_dst[t]], 1);
    else if (t < E_UG + E_GI) atomicAdd(&ib[OI_CNT_G2 + gi_src[t - E_UG]], 1);
    else if (t < E_UG + E_GI + E_UI) atomicAdd(&ib[OI_CNT_U + ui_src[t - E_UG - E_GI]], 1);
    else if (t < E_UG + E_GI + 2*E_UI) atomicAdd(&ib[OI_CNT_I + ui_dst[t - E_UG - E_GI - E_UI]], 1);
}

__global__ void k_scan4(int* __restrict__ ib)
{
    const int* cnt; int* rp; int* cur; int n;
    switch (blockIdx.x) {
        case 0: cnt = ib + OI_CNT_G1; rp = ib + OI_RP_G1; cur = ib + OI_CUR_G1; n = NG; break;
        case 1: cnt = ib + OI_CNT_G2; rp = ib + OI_RP_G2; cur = ib + OI_CUR_G2; n = NG; break;
        case 2: cnt = ib + OI_CNT_U;  rp = ib + OI_RP_U;  cur = ib + OI_CUR_U;  n = NU; break;
        default: cnt = ib + OI_CNT_I; rp = ib + OI_RP_I;  cur = ib + OI_CUR_I;  n = NI; break;
    }
    __shared__ int ssum[1024];
    const int t = threadIdx.x;
    const int chunk = (n + 1023) / 1024;
    int beg = t * chunk;
    int end = beg + chunk; if (end > n) end = n;
    if (beg > n) beg = n;
    int s = 0;
    for (int i = beg; i < end; i++) s += cnt[i];
    ssum[t] = s;
    __syncthreads();
    for (int off = 1; off < 1024; off <<= 1) {
        int v = (t >= off) ? ssum[t - off] : 0;
        __syncthreads();
        ssum[t] += v;
        __syncthreads();
    }
    int prefix = (t == 0) ? 0 : ssum[t - 1];
    for (int i = beg; i < end; i++) {
        rp[i]  = prefix;
        cur[i] = prefix;
        prefix += cnt[i];
    }
    if (t == 1023) rp[n] = ssum[1023];
}

__global__ void k_bucket_all(const int* __restrict__ ug_src, const int* __restrict__ ug_dst,
                             const int* __restrict__ ui_src, const int* __restrict__ ui_dst,
                             const int* __restrict__ gi_src, const int* __restrict__ gi_dst,
                             int* __restrict__ ib)
{
    int t = blockIdx.x * blockDim.x + threadIdx.x;
    if (t < E_UG) {
        int p = atomicAdd(&ib[OI_CUR_G1 + ug_dst[t]], 1);
        ib[OI_COL_G1 + p] = ug_src[t];
    } else if (t < E_UG + E_GI) {
        int e = t - E_UG;
        int p = atomicAdd(&ib[OI_CUR_G2 + gi_src[e]], 1);
        ib[OI_COL_G2 + p] = gi_dst[e];
    } else if (t < E_UG + E_GI + E_UI) {
        int e = t - E_UG - E_GI;
        int p = atomicAdd(&ib[OI_CUR_U + ui_src[e]], 1);
        ib[OI_COL_U + p] = ui_dst[e];
    } else if (t < E_UG + E_GI + 2*E_UI) {
        int e = t - E_UG - E_GI - E_UI;
        int p = atomicAdd(&ib[OI_CUR_I + ui_dst[e]], 1);
        ib[OI_COL_I + p] = ui_src[e];
    }
}

// ======================= segment mean (fp16 in) -> bf16 hi/lo ================
__device__ __forceinline__ void agg_row(const int* __restrict__ rp, const int* __restrict__ col,
                                        const __half* __restrict__ feat,
                                        __nv_bfloat16* __restrict__ hb, int loOff,
                                        int row, int lane)
{
    int beg = rp[row], end = rp[row + 1];
    float4 acc = make_float4(0.f, 0.f, 0.f, 0.f);
    const uint2* fv = (const uint2*)feat;   // 4 fp16 per uint2; row = 32 uint2
    int e = beg;
    for (; e + 8 <= end; e += 8) {
        int s[8];
#pragma unroll
        for (int q = 0; q < 8; q++) s[q] = __ldg(&col[e + q]);
        uint2 v[8];
#pragma unroll
        for (int q = 0; q < 8; q++) v[q] = __ldg(&fv[(size_t)s[q] * 32 + lane]);
#pragma unroll
        for (int q = 0; q < 8; q++) {
            float2 f0 = __half22float2(*(__half2*)&v[q].x);
            float2 f1 = __half22float2(*(__half2*)&v[q].y);
            acc.x += f0.x; acc.y += f0.y; acc.z += f1.x; acc.w += f1.y;
        }
    }
    for (; e < end; e++) {
        int sx = __ldg(&col[e]);
        uint2 v = __ldg(&fv[(size_t)sx * 32 + lane]);
        float2 f0 = __half22float2(*(__half2*)&v.x);
        float2 f1 = __half22float2(*(__half2*)&v.y);
        acc.x += f0.x; acc.y += f0.y; acc.z += f1.x; acc.w += f1.y;
    }
    float inv = (end > beg) ? 1.f / (float)(end - beg) : 0.f;
    acc.x *= inv; acc.y *= inv; acc.z *= inv; acc.w *= inv;
    uint32_t h0, l0, h1, l1;
    bfsplit2(acc.x, acc.y, h0, l0);
    bfsplit2(acc.z, acc.w, h1, l1);
    size_t o = ((size_t)row * H + lane * 4) >> 1;
    ((uint32_t*)hb)[o]     = h0;
    ((uint32_t*)hb)[o + 1] = h1;
    ((uint32_t*)(hb + loOff))[o]     = l0;
    ((uint32_t*)(hb + loOff))[o + 1] = l1;
}

__global__ void k_agg_all(const int* __restrict__ ib, const __half* __restrict__ hh,
                          __nv_bfloat16* __restrict__ bb)
{
    int w = (int)((blockIdx.x * blockDim.x + threadIdx.x) >> 5);
    int lane = threadIdx.x & 31;
    if (w < NU)
        agg_row(ib + OI_RP_U, ib + OI_COL_U, hh + OH_HI, bb + OB_AIU, NU*H, w, lane);
    else if (w < NU + NI)
        agg_row(ib + OI_RP_I, ib + OI_COL_I, hh + OH_HU, bb + OB_AUI, NI*H, w - NU, lane);
    else if (w < NU + NI + NG)
        agg_row(ib + OI_RP_G1, ib + OI_COL_G1, hh + OH_HU, bb + OB_AUG, NG*H, w - NU - NI, lane);
    else if (w < NU + NI + 2*NG)
        agg_row(ib + OI_RP_G2, ib + OI_COL_G2, hh + OH_HI, bb + OB_AIG, NG*H, w - NU - NI - NG, lane);
}

__global__ void k_agg_all2(const int* __restrict__ ib, const __half* __restrict__ hh,
                           __nv_bfloat16* __restrict__ bb)
{
    int w = (int)((blockIdx.x * blockDim.x + threadIdx.x) >> 5);
    int lane = threadIdx.x & 31;
    if (w < NG)
        agg_row(ib + OI_RP_G1, ib + OI_COL_G1, hh + OH_HU1, bb + OB_BUG, NG*H, w, lane);
    else if (w < 2*NG)
        agg_row(ib + OI_RP_G2, ib + OI_COL_G2, hh + OH_HI1, bb + OB_BIG, NG*H, w - NG, lane);
}

// ======================= weight prep (fused combine + transpose + split) =====
__global__ void __launch_bounds__(256)
k_splitW(const float* __restrict__ W1l, const float* __restrict__ W1r,
         const float* __restrict__ W2l, const float* __restrict__ W2r,
         __nv_bfloat16* __restrict__ dst9)
{
    const float* srcA; const float* srcB = nullptr;
    switch (blockIdx.z) {
        case 0: srcA = W1l + 3*HH; break;
        case 1: srcA = W1r + 1*HH; srcB = W1r + 3*HH; break;
        case 2: srcA = W1l + 2*HH; break;
        case 3: srcA = W1r + 2*HH; srcB = W1r + 4*HH; break;
        case 4: srcA = W1l + 0*HH; break;
        case 5: srcA = W1l + 5*HH; break;
        case 6: srcA = W2l + 0*HH; break;
        case 7: srcA = W2r + 0*HH; srcB = W2r + 5*HH; break;
        default: srcA = W2l + 5*HH; break;
    }
    __nv_bfloat16* hi = dst9 + (size_t)blockIdx.z * 2 * HH;
    __nv_bfloat16* lo = hi + HH;
    __shared__ float t[32][33];
    int nblk = blockIdx.x * 32;
    int kblk = blockIdx.y * 32;
    int tx = threadIdx.x, ty = threadIdx.y;
#pragma unroll
    for (int i = ty; i < 32; i += 8) {
        size_t gi = (size_t)(kblk + i) * H + nblk + tx;
        float v = srcA[gi];
        if (srcB) v += srcB[gi];
        t[i][tx] = v;
    }
    __syncthreads();
#pragma unroll
    for (int i = ty; i < 32; i += 8) {
        float x = t[tx][i];
        __nv_bfloat16 h = __float2bfloat16(x);
        size_t o = (size_t)(nblk + i) * H + kblk + tx;
        hi[o] = h;
        lo[o] = __float2bfloat16(x - __bfloat162float(h));
    }
}

__global__ void k_bias(const float* __restrict__ b1, const float* __restrict__ b2)
{
    int i = blockIdx.x * blockDim.x + threadIdx.x;
    float* bc = g_f + OF_BC;
    if (i < H) {
        bc[0*H + i] = b1[1*H + i] + b1[3*H + i];
        bc[1*H + i] = b1[2*H + i] + b1[4*H + i];
        bc[2*H + i] = b1[0*H + i] + b1[5*H + i];
        bc[3*H + i] = b2[0*H + i] + b2[5*H + i];
    }
}

// pred_W [H, NI] fp32 -> [NI, H] fp16 (transposed, K contiguous)
__global__ void __launch_bounds__(256)
k_halfB(const float* __restrict__ W, __half* __restrict__ out)
{
    __shared__ float t[32][33];
    int nblk = blockIdx.x * 32;
    int kblk = blockIdx.y * 32;
    int tx = threadIdx.x, ty = threadIdx.y;
#pragma unroll
    for (int i = ty; i < 32; i += 8)
        t[i][tx] = W[(size_t)(kblk + i) * NI + nblk + tx];
    __syncthreads();
#pragma unroll
    for (int i = ty; i < 32; i += 8)
        out[(size_t)(nblk + i) * H + kblk + tx] = __float2half(t[tx][i]);
}

// ======================= common GEMM constants ===============================
#define PK   136
#define ROWB (PK * 2)          // 272 B per row
#define TILEB (128 * ROWB)     // 34816 B
#define HTILE (64 * ROWB)      // 17408 B

#define GEMM_RELU 1
#define GEMM_BF16 2
#define GEMM_F16  4

// ======================= HMMA layer-2 GEMM (multi-term, small) ===============
struct GemmArgs {
    const __nv_bfloat16* Ah[3];
    const __nv_bfloat16* Al[3];
    const __nv_bfloat16* Wh[3];
    const float* bias;
    float* Cf;
    __nv_bfloat16* Cb;
    __half* Ch;
    int M, nterms, flags, loOff;
};

#define SMEM_GH (4 * TILEB)    // 139264

__global__ void __launch_bounds__(256, 1)
k_gemm_h(GemmArgs g)
{
    extern __shared__ char sm[];
    const int tid  = threadIdx.x;
    const int wid  = tid >> 5;
    const int lane = tid & 31;
    const int wm   = wid >> 1;
    const int wn   = wid & 1;
    const int m0   = blockIdx.x * 128;

    const uint32_t sbase  = smem_u32(sm);
    const uint32_t a_loff = (uint32_t)(lane & 15) * ROWB + (uint32_t)(lane >> 4) * 16;
    const uint32_t b_loff = (uint32_t)(((lane >> 4) * 8) + (lane & 7)) * ROWB
                          + (uint32_t)((lane >> 3) & 1) * 16;

    float c[2][8][4];
#pragma unroll
    for (int i = 0; i < 2; i++)
#pragma unroll
        for (int j = 0; j < 8; j++)
#pragma unroll
            for (int q = 0; q < 4; q++) c[i][j][q] = 0.f;

#pragma unroll 1
    for (int t = 0; t < g.nterms; t++) {
        const uint4* wh = (const uint4*)g.Wh[t];
        const uint4* wl = (const uint4*)(g.Wh[t] + HH);
        const uint4* ah = (const uint4*)g.Ah[t];
        const uint4* al = (const uint4*)g.Al[t];
#pragma unroll 4
        for (int i = tid; i < 2048; i += 256) {
            int row = i >> 4, cq = i & 15;
            uint32_t so = (uint32_t)row * ROWB + cq * 16;
            *(uint4*)(sm + 0*TILEB + so) = __ldg(&wh[row * 16 + cq]);
            *(uint4*)(sm + 1*TILEB + so) = __ldg(&wl[row * 16 + cq]);
            uint4 va = make_uint4(0,0,0,0), vb = va;
            if (m0 + row < g.M) {
                size_t gi = (size_t)(m0 + row) * 16 + cq;
                va = __ldg(&ah[gi]);
                vb = __ldg(&al[gi]);
            }
            *(uint4*)(sm + 2*TILEB + so) = va;
            *(uint4*)(sm + 3*TILEB + so) = vb;
        }
        __syncthreads();
#pragma unroll 1
        for (int sp = 0; sp < 3; sp++) {
            uint32_t aB = sbase + (sp == 2 ? 3*TILEB : 2*TILEB)
                        + (uint32_t)wm * 32 * ROWB + a_loff;
            uint32_t bB = sbase + (sp == 1 ? 1*TILEB : 0)
                        + (uint32_t)wn * 64 * ROWB + b_loff;
#pragma unroll
            for (int ks = 0; ks < 8; ks++) {
                uint32_t a[2][4], b[4][4];
                LDSM4(a[0], aB + ks * 32);
                LDSM4(a[1], aB + ks * 32 + 16 * ROWB);
#pragma unroll
                for (int q = 0; q < 4; q++)
                    LDSM4(b[q], bB + ks * 32 + q * 16 * ROWB);
#pragma unroll
                for (int ma = 0; ma < 2; ma++)
#pragma unroll
                    for (int na = 0; na < 8; na++)
                        MMA_BF16(c[ma][na], a[ma],
                                 b[na >> 1][(na & 1) * 2], b[na >> 1][(na & 1) * 2 + 1]);
            }
        }
        __syncthreads();
    }

    const int gid = lane >> 2;
    const int tq  = (lane & 3) * 2;
    const bool relu = (g.flags & GEMM_RELU) != 0;
    const bool bfo  = (g.flags & GEMM_BF16) != 0;
    const bool f16o = (g.flags & GEMM_F16) != 0;
#pragma unroll
    for (int ma = 0; ma < 2; ma++) {
#pragma unroll
        for (int na = 0; na < 8; na++) {
            int mrow = m0 + wm * 32 + ma * 16 + gid;
            int ncol = wn * 64 + na * 8 + tq;
            float2 bv = *(const float2*)(g.bias + ncol);
#pragma unroll
            for (int hrow = 0; hrow < 2; hrow++) {
                int mr = mrow + hrow * 8;
                if (mr >= g.M) continue;
                float v0 = c[ma][na][hrow*2 + 0] + bv.x;
                float v1 = c[ma][na][hrow*2 + 1] + bv.y;
                if (relu) { v0 = fmaxf(v0, 0.f); v1 = fmaxf(v1, 0.f); }
                if (f16o) {
                    __half2 hv = __floats2half2_rn(v0, v1);
                    *(__half2*)(g.Ch + (size_t)mr * H + ncol) = hv;
                } else if (bfo) {
                    uint32_t hw, lw;
                    bfsplit2(v0, v1, hw, lw);
                    *(uint32_t*)(g.Cb + (size_t)mr * H + ncol) = hw;
                    *(uint32_t*)(g.Cb + (size_t)g.loOff + (size_t)mr * H + ncol) = lw;
                } else {
                    *(float2*)(g.Cf + (size_t)mr * H + ncol) = make_float2(v0, v1);
                }
            }
        }
    }
}

// ======================= persistent layer-1 GEMM =============================
struct LJob {
    const __nv_bfloat16* Ah0; const __nv_bfloat16* Al0;
    const __nv_bfloat16* Ah1; const __nv_bfloat16* Al1;
    const __nv_bfloat16* Wh0; const __nv_bfloat16* Wh1;
    const float* bias;
    __half* Ch;
    __nv_bfloat16* Cb;
    int loOff, M, ntiles, ctaBase, nctas, flags;
};
struct LJob3 { LJob j[3]; };

#define SMEM_GL (4 * TILEB + 4 * HTILE)   // 208896

__device__ __forceinline__ void loadA64(uint32_t dst, const uint4* ah, const uint4* al,
                                        int m0_, int M, int tid)
{
#pragma unroll 2
    for (int i = tid; i < 1024; i += 256) {
        int row = i >> 4, cq = i & 15;
        int gr = m0_ + row;
        int sz = (gr < M) ? 16 : 0;
        if (gr >= M) gr = M - 1;
        uint32_t so = dst + (uint32_t)row * ROWB + cq * 16;
        CPA16(so,         ah + (size_t)gr * 16 + cq, sz);
        CPA16(so + HTILE, al + (size_t)gr * 16 + cq, sz);
    }
}

__global__ void __launch_bounds__(256, 1)
k_gemm_l(LJob3 js)
{
    extern __shared__ char sm[];
    const int tid  = threadIdx.x;
    const int wid  = tid >> 5;
    const int lane = tid & 31;
    const int wm   = wid >> 2;
    const int wn   = wid & 3;

    int ji = (blockIdx.x >= (uint32_t)js.j[2].ctaBase) ? 2
           : (blockIdx.x >= (uint32_t)js.j[1].ctaBase) ? 1 : 0;
    const LJob g = js.j[ji];
    const int idx = blockIdx.x - g.ctaBase;
    const int beg = (int)((long long)idx * g.ntiles / g.nctas);
    const int end = (int)((long long)(idx + 1) * g.ntiles / g.nctas);
    if (beg >= end) return;

    const uint32_t sbase = smem_u32(sm);
    const uint32_t sA    = sbase + 4 * TILEB;

    {
        const uint4* wsrc0 = (const uint4*)g.Wh0;
        const uint4* wsrc1 = (const uint4*)(g.Wh0 + HH);
        const uint4* wsrc2 = (const uint4*)g.Wh1;
        const uint4* wsrc3 = (const uint4*)(g.Wh1 + HH);
#pragma unroll 4
        for (int i = tid; i < 8192; i += 256) {
            int tl = i >> 11;
            int row = (i >> 4) & 127;
            int cq = i & 15;
            const uint4* src = (tl == 0) ? wsrc0 : (tl == 1) ? wsrc1 : (tl == 2) ? wsrc2 : wsrc3;
            CPA16(sbase + (uint32_t)tl * TILEB + (uint32_t)row * ROWB + cq * 16,
                  src + (size_t)row * 16 + cq, 16);
        }
    }
    loadA64(sA, (const uint4*)g.Ah0, (const uint4*)g.Al0, beg * 64, g.M, tid);
    CP_COMMIT();

    const uint32_t a_loff = (uint32_t)(lane & 15) * ROWB + (uint32_t)(lane >> 4) * 16;
    const uint32_t b_loff = (uint32_t)(((lane >> 4) * 8) + (lane & 7)) * ROWB
                          + (uint32_t)((lane >> 3) & 1) * 16;
    const int gid = lane >> 2;
    const int tq  = (lane & 3) * 2;
    const bool relu = (g.flags & GEMM_RELU) != 0;
    const bool bfo  = (g.flags & GEMM_BF16) != 0;
    const bool f16o = (g.flags & GEMM_F16) != 0;

    float c[2][4][4];
    const int nit = (end - beg) * 2;
    int buf = 0;

#pragma unroll 1
    for (int it = 0; it < nit; it++) {
        const int tile = beg + (it >> 1);
        const int term = it & 1;
        if (it + 1 < nit) {
            int ntile = beg + ((it + 1) >> 1);
            int nterm = (it + 1) & 1;
            const uint4* ah = (const uint4*)(nterm ? g.Ah1 : g.Ah0);
            const uint4* al = (const uint4*)(nterm ? g.Al1 : g.Al0);
            loadA64(sA + (uint32_t)(buf ^ 1) * 2 * HTILE, ah, al, ntile * 64, g.M, tid);
            CP_COMMIT();
            CP_WAIT1();
        } else {
            CP_WAIT0();
        }
        __syncthreads();

        if (term == 0) {
#pragma unroll
            for (int i = 0; i < 2; i++)
#pragma unroll
                for (int j = 0; j < 4; j++)
#pragma unroll
                    for (int q = 0; q < 4; q++) c[i][j][q] = 0.f;
        }

        const uint32_t curA = sA + (uint32_t)buf * 2 * HTILE;
        const uint32_t wBase = sbase + (uint32_t)term * 2 * TILEB;
#pragma unroll 1
        for (int sp = 0; sp < 3; sp++) {
            uint32_t aB = curA + (sp == 2 ? HTILE : 0) + (uint32_t)wm * 32 * ROWB + a_loff;
            uint32_t bB = wBase + (sp == 1 ? TILEB : 0) + (uint32_t)wn * 32 * ROWB + b_loff;
#pragma unroll
            for (int ks = 0; ks < 8; ks++) {
                uint32_t a[2][4], b[2][4];
                LDSM4(a[0], aB + ks * 32);
                LDSM4(a[1], aB + ks * 32 + 16 * ROWB);
                LDSM4(b[0], bB + ks * 32);
                LDSM4(b[1], bB + ks * 32 + 16 * ROWB);
#pragma unroll
                for (int ma = 0; ma < 2; ma++)
#pragma unroll
                    for (int na = 0; na < 4; na++)
                        MMA_BF16(c[ma][na], a[ma],
                                 b[na >> 1][(na & 1) * 2], b[na >> 1][(na & 1) * 2 + 1]);
            }
        }

        if (term == 1) {
            int m0_ = tile * 64;
#pragma unroll
            for (int ma = 0; ma < 2; ma++) {
#pragma unroll
                for (int na = 0; na < 4; na++) {
                    int mrow = m0_ + wm * 32 + ma * 16 + gid;
                    int ncol = wn * 32 + na * 8 + tq;
                    float2 bv = *(const float2*)(g.bias + ncol);
#pragma unroll
                    for (int hrow = 0; hrow < 2; hrow++) {
                        int mr = mrow + hrow * 8;
                        if (mr >= g.M) continue;
                        float v0 = c[ma][na][hrow*2 + 0] + bv.x;
                        float v1 = c[ma][na][hrow*2 + 1] + bv.y;
                        if (relu) { v0 = fmaxf(v0, 0.f); v1 = fmaxf(v1, 0.f); }
                        if (f16o) {
                            __half2 hv = __floats2half2_rn(v0, v1);
                            *(__half2*)(g.Ch + (size_t)mr * H + ncol) = hv;
                        } else if (bfo) {
                            uint32_t hw, lw;
                            bfsplit2(v0, v1, hw, lw);
                            *(uint32_t*)(g.Cb + (size_t)mr * H + ncol) = hw;
                            *(uint32_t*)(g.Cb + (size_t)g.loOff + (size_t)mr * H + ncol) = lw;
                        }
                    }
                }
            }
        }
        __syncthreads();
        buf ^= 1;
    }
}

// ======================= persistent fp16 pred GEMM ===========================
#define NTN ((NI + 127) / 128)    // 157
#define NTM ((NG + 127) / 128)    // 40
#define NT_TOT (NTN * NTM)        // 6280
#define NCTA_PRED 148
#define SMEM_PREDH (3 * TILEB)    // 104448

__device__ __forceinline__ void pred_load1(uint32_t dst, const uint4* gp,
                                           int r0_, int rmax, int tid)
{
#pragma unroll 4
    for (int i = tid; i < 2048; i += 256) {
        int row = i >> 4, cq = i & 15;
        int gr = r0_ + row;
        int sz = (gr < rmax) ? 16 : 0;
        if (gr >= rmax) gr = rmax - 1;
        CPA16(dst + (uint32_t)row * ROWB + cq * 16, gp + (size_t)gr * 16 + cq, sz);
    }
}

__global__ void __launch_bounds__(256, 1)
k_mma_pred(const __half* __restrict__ A, const __half* __restrict__ B,
           const float* __restrict__ bias, float* __restrict__ out)
{
    extern __shared__ char sm[];
    const int tid  = threadIdx.x;
    const int wid  = tid >> 5;
    const int lane = tid & 31;
    const int wm   = wid >> 1;
    const int wn   = wid & 1;

    const uint32_t sbase = smem_u32(sm);
    const uint32_t sB    = sbase + TILEB;

    const uint4* gA = (const uint4*)A;
    const uint4* gB = (const uint4*)B;

    const int beg = (int)((long long)blockIdx.x * NT_TOT / NCTA_PRED);
    const int end = (int)((long long)(blockIdx.x + 1) * NT_TOT / NCTA_PRED);

    const uint32_t a_loff = (uint32_t)(lane & 15) * ROWB + (uint32_t)(lane >> 4) * 16;
    const uint32_t b_loff = (uint32_t)(((lane >> 4) * 8) + (lane & 7)) * ROWB
                          + (uint32_t)((lane >> 3) & 1) * 16;
    const int gid = lane >> 2;
    const int tq  = (lane & 3) * 2;

    int cur_m = -1;
    int buf = 0;

#pragma unroll 1
    for (int t = beg; t < end; ++t) {
        int tm = t / NTN, tn = t - tm * NTN;
        if (tm != cur_m) {
            CP_WAIT0();
            __syncthreads();
            pred_load1(sbase, gA, tm * 128, NG, tid);
            pred_load1(sB, gB, tn * 128, NI, tid);
            CP_COMMIT();
            cur_m = tm;
            buf = 0;
            if (t + 1 < end && (t + 1) / NTN == cur_m) {
                pred_load1(sB + TILEB, gB, (tn + 1) * 128, NI, tid);
                CP_COMMIT();
                CP_WAIT1();
            } else {
                CP_WAIT0();
            }
            __syncthreads();
        } else {
            if (t + 1 < end && (t + 1) / NTN == cur_m) {
                pred_load1(sB + (uint32_t)(buf ^ 1) * TILEB, gB, (tn + 1) * 128, NI, tid);
                CP_COMMIT();
                CP_WAIT1();
            } else {
                CP_WAIT0();
            }
            __syncthreads();
        }

        float c[2][8][4];
#pragma unroll
        for (int i = 0; i < 2; i++)
#pragma unroll
            for (int j = 0; j < 8; j++)
#pragma unroll
                for (int q = 0; q < 4; q++) c[i][j][q] = 0.f;

        uint32_t aB = sbase + (uint32_t)wm * 32 * ROWB + a_loff;
        uint32_t bB = sB + (uint32_t)buf * TILEB + (uint32_t)wn * 64 * ROWB + b_loff;
#pragma unroll
        for (int ks = 0; ks < 8; ks++) {
            uint32_t a[2][4], b[4][4];
            LDSM4(a[0], aB + ks * 32);
            LDSM4(a[1], aB + ks * 32 + 16 * ROWB);
#pragma unroll
            for (int q = 0; q < 4; q++)
                LDSM4(b[q], bB + ks * 32 + q * 16 * ROWB);
#pragma unroll
            for (int ma = 0; ma < 2; ma++)
#pragma unroll
                for (int na = 0; na < 8; na++)
                    MMA_F16(c[ma][na], a[ma],
                            b[na >> 1][(na & 1) * 2], b[na >> 1][(na & 1) * 2 + 1]);
        }

        int m0_ = tm * 128, n0_ = tn * 128;
#pragma unroll
        for (int ma = 0; ma < 2; ma++) {
#pragma unroll
            for (int na = 0; na < 8; na++) {
                int mrow = m0_ + wm * 32 + ma * 16 + gid;
                int ncol = n0_ + wn * 64 + na * 8 + tq;
                if (ncol >= NI) continue;
                float2 bv = *(const float2*)(bias + ncol);
                if (mrow < NG) {
                    float2 v = make_float2(c[ma][na][0] + bv.x, c[ma][na][1] + bv.y);
                    *(float2*)(out + (size_t)mrow * NI + ncol) = v;
                }
                if (mrow + 8 < NG) {
                    float2 v = make_float2(c[ma][na][2] + bv.x, c[ma][na][3] + bv.y);
                    *(float2*)(out + (size_t)(mrow + 8) * NI + ncol) = v;
                }
            }
        }
        __syncthreads();
        buf ^= 1;
    }
}

// ---------------------------------------------------------------------------
extern "C" void kernel_launch(void* const* d_in, const int* in_sizes, int n_in,
                              void* d_out, int out_size)
{
    const int*   x_user   = (const int*)  d_in[1];
    const int*   x_item   = (const int*)  d_in[2];
    const float* emb_user = (const float*)d_in[4];
    const float* emb_item = (const float*)d_in[5];
    const float* W1l      = (const float*)d_in[6];
    const float* W1r      = (const float*)d_in[7];
    const float* b1       = (const float*)d_in[8];
    const float* W2l      = (const float*)d_in[9];
    const float* W2r      = (const float*)d_in[10];
    const float* b2       = (const float*)d_in[11];
    const float* pred_W   = (const float*)d_in[12];
    const float* pred_b   = (const float*)d_in[13];
    const int*   ug_src   = (const int*)  d_in[14];
    const int*   ug_dst   = (const int*)  d_in[15];
    const int*   ui_src   = (const int*)  d_in[16];
    const int*   ui_dst   = (const int*)  d_in[17];
    const int*   gi_src   = (const int*)  d_in[18];
    const int*   gi_dst   = (const int*)  d_in[19];
    float* out = (float*)d_out;

    float* fb = nullptr; int* ib = nullptr; __nv_bfloat16* bb = nullptr; __half* hh = nullptr;
    cudaGetSymbolAddress((void**)&fb, g_f);
    cudaGetSymbolAddress((void**)&ib, g_i);
    cudaGetSymbolAddress((void**)&bb, g_bf);
    cudaGetSymbolAddress((void**)&hh, g_h);
    __half* repH = (__half*)(bb + OB_REP);
    __half* pwH  = (__half*)(bb + OB_PW);

    cudaFuncSetAttribute(k_gemm_h, cudaFuncAttributeMaxDynamicSharedMemorySize, SMEM_GH);
    cudaFuncSetAttribute(k_gemm_l, cudaFuncAttributeMaxDynamicSharedMemorySize, SMEM_GL);
    cudaFuncSetAttribute(k_mma_pred, cudaFuncAttributeMaxDynamicSharedMemorySize, SMEM_PREDH);

    cudaMemsetAsync(ib + OI_CNT_G1, 0, (size_t)CNT_TOTAL * sizeof(int));

    // weight prep
    k_halfB<<<dim3(NI / 32, H / 32), dim3(32, 8)>>>(pred_W, pwH);
    k_bias<<<1, 128>>>(b1, b2);
    k_splitW<<<dim3(4, 4, 9), dim3(32, 8)>>>(W1l, W1r, W2l, W2r, bb + OB_W);

    // merged embedding gathers (fp16 + bf16 hi/lo)
    k_gather2m<<<((NU + NI) * 32 + 255) / 256, 256>>>(emb_user, x_user, emb_item, x_item,
                                                      hh, bb);

    // CSR build
    {
        int tot = E_UG + E_GI + 2 * E_UI;
        k_count_all<<<(tot + 255) / 256, 256>>>(ug_dst, gi_src, ui_src, ui_dst, ib);
        k_scan4<<<4, 1024>>>(ib);
        k_bucket_all<<<(tot + 255) / 256, 256>>>(ug_src, ug_dst, ui_src, ui_dst,
                                                 gi_src, gi_dst, ib);
    }

    // layer-1 aggregations (fp16 features) -> bf16 hi/lo
    {
        int warps = NU + NI + 2 * NG;
        k_agg_all<<<(warps + 7) / 8, 256>>>(ib, hh, bb);
    }

    // layer-1 GEMMs: one persistent launch, 3 jobs
    {
        LJob3 js;
        js.j[0].Ah0 = bb + OB_AIU;  js.j[0].Al0 = bb + OB_AIU + NU*H;
        js.j[0].Ah1 = bb + OB_HUe;  js.j[0].Al1 = bb + OB_HUe + NU*H;
        js.j[0].Wh0 = bb + OB_W + SL_W1L3*2*HH;
        js.j[0].Wh1 = bb + OB_W + SL_WC0*2*HH;
        js.j[0].bias = fb + OF_BC + 0*H;
        js.j[0].Ch = hh + OH_HU1; js.j[0].Cb = nullptr; js.j[0].loOff = 0;
        js.j[0].M = NU; js.j[0].ntiles = (NU + 63) / 64;
        js.j[0].ctaBase = 0;   js.j[0].nctas = 118; js.j[0].flags = GEMM_RELU | GEMM_F16;
        js.j[1].Ah0 = bb + OB_AUI;  js.j[1].Al0 = bb + OB_AUI + NI*H;
        js.j[1].Ah1 = bb + OB_HIe;  js.j[1].Al1 = bb + OB_HIe + NI*H;
        js.j[1].Wh0 = bb + OB_W + SL_W1L2*2*HH;
        js.j[1].Wh1 = bb + OB_W + SL_WC1*2*HH;
        js.j[1].bias = fb + OF_BC + 1*H;
        js.j[1].Ch = hh + OH_HI1; js.j[1].Cb = nullptr; js.j[1].loOff = 0;
        js.j[1].M = NI; js.j[1].ntiles = (NI + 63) / 64;
        js.j[1].ctaBase = 118; js.j[1].nctas = 24; js.j[1].flags = GEMM_RELU | GEMM_F16;
        js.j[2].Ah0 = bb + OB_AUG;  js.j[2].Al0 = bb + OB_AUG + NG*H;
        js.j[2].Ah1 = bb + OB_AIG;  js.j[2].Al1 = bb + OB_AIG + NG*H;
        js.j[2].Wh0 = bb + OB_W + SL_W1L0*2*HH;
        js.j[2].Wh1 = bb + OB_W + SL_W1L5*2*HH;
        js.j[2].bias = fb + OF_BC + 2*H;
        js.j[2].Ch = nullptr; js.j[2].Cb = bb + OB_HG1; js.j[2].loOff = NG*H;
        js.j[2].M = NG; js.j[2].ntiles = (NG + 63) / 64;
        js.j[2].ctaBase = 142; js.j[2].nctas = 6; js.j[2].flags = GEMM_RELU | GEMM_BF16;
        k_gemm_l<<<148, 256, SMEM_GL>>>(js);
    }

    // layer-2 aggregations (fp16 features)
    k_agg_all2<<<(2 * NG + 7) / 8, 256>>>(ib, hh, bb);

    // layer-2 group GEMM (3 terms) -> REP fp16
    {
        GemmArgs a = {};
        a.Ah[0] = bb + OB_BUG;  a.Al[0] = bb + OB_BUG + NG*H;  a.Wh[0] = bb + OB_W + SL_W2L0*2*HH;
        a.Ah[1] = bb + OB_HG1;  a.Al[1] = bb + OB_HG1 + NG*H;  a.Wh[1] = bb + OB_W + SL_WC2*2*HH;
        a.Ah[2] = bb + OB_BIG;  a.Al[2] = bb + OB_BIG + NG*H;  a.Wh[2] = bb + OB_W + SL_W2L5*2*HH;
        a.bias = fb + OF_BC + 3*H;
        a.Ch = repH;
        a.M = NG; a.nterms = 3; a.flags = GEMM_RELU | GEMM_F16;
        k_gemm_h<<<(NG + 127) / 128, 256, SMEM_GH>>>(a);
    }

    // persistent fp16 prediction GEMM
    k_mma_pred<<<NCTA_PRED, 256, SMEM_PREDH>>>(repH, pwH, pred_b, out);
    (void)in_sizes; (void)n_in; (void)out_size;
}

// round 11
// speedup vs baseline: 2.3159x; 1.1418x over previous
#include <cuda_runtime.h>
#include <cuda_fp16.h>
#include <cstdint>

// ----------------------------------------------------------------------------
// BaseGR hetero-SAGE on GB300 — R11.
// vs R10: entire pipeline unified to single-pass fp16 (gather tables, agg
// outputs, all weights, all GEMMs) — 3x fewer MMAs in layer GEMMs, half the
// split/store ALU work, fewer planes. gather+count merged (k_front); bias
// merged into k_halfW. Launch order puts k_agg_all at ncu capture slot 5.
// ----------------------------------------------------------------------------

#define NG 5000
#define NU 100000
#define NI 20000
#define H 128
#define HH (H*H)
#define E_UG 300000
#define E_UI 600000
#define E_GI 200000

// ---------------- fp32: combined biases ----------------
__device__ float g_f[4 * H];

// ---------------- fp16 tables -------------------------------------------------
#define OH_HU  0
#define OH_HI  (OH_HU  + NU*H)
#define OH_HU1 (OH_HI  + NI*H)
#define OH_HI1 (OH_HU1 + NU*H)
#define OH_AIU (OH_HI1 + NI*H)
#define OH_AUI (OH_AIU + NU*H)
#define OH_AUG (OH_AUI + NI*H)
#define OH_AIG (OH_AUG + NG*H)
#define OH_HG1 (OH_AIG + NG*H)
#define OH_BUG (OH_HG1 + NG*H)
#define OH_BIG (OH_BUG + NG*H)
#define OH_REP (OH_BIG + NG*H)
#define OH_PW  (OH_REP + NG*H)
#define OH_W   (OH_PW  + NI*H)
#define H_TOTAL (OH_W + 9*HH)
__device__ __half g_h[H_TOTAL];

// weight slots (fp16, HH each)
#define SL_W1L3 0
#define SL_WC0  1
#define SL_W1L2 2
#define SL_WC1  3
#define SL_W1L0 4
#define SL_W1L5 5
#define SL_W2L0 6
#define SL_WC2  7
#define SL_W2L5 8

// ---------------- int scratch ----------------
#define OI_CNT_G1 0
#define OI_CNT_G2 (OI_CNT_G1 + NG)
#define OI_CNT_U  (OI_CNT_G2 + NG)
#define OI_CNT_I  (OI_CNT_U  + NU)
#define CNT_TOTAL (OI_CNT_I  + NI)
#define OI_RP_G1  CNT_TOTAL
#define OI_RP_G2  (OI_RP_G1 + NG + 1)
#define OI_RP_U   (OI_RP_G2 + NG + 1)
#define OI_RP_I   (OI_RP_U  + NU + 1)
#define OI_CUR_G1 (OI_RP_I  + NI + 1)
#define OI_CUR_G2 (OI_CUR_G1 + NG)
#define OI_CUR_U  (OI_CUR_G2 + NG)
#define OI_CUR_I  (OI_CUR_U  + NU)
#define OI_COL_G1 (OI_CUR_I  + NI)
#define OI_COL_G2 (OI_COL_G1 + E_UG)
#define OI_COL_U  (OI_COL_G2 + E_GI)
#define OI_COL_I  (OI_COL_U  + E_UI)
#define I_TOTAL   (OI_COL_I  + E_UI)
__device__ int g_i[I_TOTAL];

// ======================= helpers =============================================
__device__ __forceinline__ uint32_t smem_u32(const void* p) {
    uint32_t a;
    asm("{ .reg .u64 t; cvta.to.shared.u64 t, %1; cvt.u32.u64 %0, t; }"
        : "=r"(a) : "l"(p));
    return a;
}

#define LDSM4(r, addr) \
    asm volatile("ldmatrix.sync.aligned.m8n8.x4.shared.b16 {%0,%1,%2,%3}, [%4];" \
                 : "=r"((r)[0]), "=r"((r)[1]), "=r"((r)[2]), "=r"((r)[3]) \
                 : "r"(addr))

#define MMA_F16(c, a, b0, b1) \
    asm volatile("mma.sync.aligned.m16n8k16.row.col.f32.f16.f16.f32 " \
                 "{%0,%1,%2,%3}, {%4,%5,%6,%7}, {%8,%9}, {%0,%1,%2,%3};" \
                 : "+f"((c)[0]), "+f"((c)[1]), "+f"((c)[2]), "+f"((c)[3]) \
                 : "r"((a)[0]), "r"((a)[1]), "r"((a)[2]), "r"((a)[3]), \
                   "r"(b0), "r"(b1))

#define CPA16(dst, src, sz) \
    asm volatile("cp.async.cg.shared.global [%0], [%1], 16, %2;" \
                 :: "r"(dst), "l"(src), "r"(sz))
#define CP_COMMIT() asm volatile("cp.async.commit_group;" ::: "memory")
#define CP_WAIT0()  asm volatile("cp.async.wait_group 0;" ::: "memory")
#define CP_WAIT1()  asm volatile("cp.async.wait_group 1;" ::: "memory")

// ======================= front: gather (fp16) + degree counts ================
__global__ void k_front(const float* __restrict__ emb_u, const int* __restrict__ x_u,
                        const float* __restrict__ emb_i, const int* __restrict__ x_i,
                        const int* __restrict__ ug_dst, const int* __restrict__ gi_src,
                        const int* __restrict__ ui_src, const int* __restrict__ ui_dst,
                        __half* __restrict__ hh, int* __restrict__ ib)
{
    const int t0 = blockIdx.x * blockDim.x + threadIdx.x;
    if (t0 < (NU + NI) * 32) {
        const float* emb; const int* x; __half* outh; int u;
        if (t0 < NU * 32) { emb = emb_u; x = x_u; outh = hh + OH_HU; u = t0; }
        else { emb = emb_i; x = x_i; outh = hh + OH_HI; u = t0 - NU * 32; }
        int r = u >> 5, c = u & 31;
        float4 v = ((const float4*)emb)[(size_t)x[r] * 32 + c];
        __half2 p0 = __floats2half2_rn(v.x, v.y);
        __half2 p1 = __floats2half2_rn(v.z, v.w);
        uint2 hv;
        hv.x = *(uint32_t*)&p0;
        hv.y = *(uint32_t*)&p1;
        ((uint2*)outh)[(size_t)r * 32 + c] = hv;
    }
    if (t0 < E_UG) atomicAdd(&ib[OI_CNT_G1 + ug_dst[t0]], 1);
    else if (t0 < E_UG + E_GI) atomicAdd(&ib[OI_CNT_G2 + gi_src[t0 - E_UG]], 1);
    else if (t0 < E_UG + E_GI + E_UI) atomicAdd(&ib[OI_CNT_U + ui_src[t0 - E_UG - E_GI]], 1);
    else if (t0 < E_UG + E_GI + 2*E_UI) atomicAdd(&ib[OI_CNT_I + ui_dst[t0 - E_UG - E_GI - E_UI]], 1);
}

// ======================= CSR scan + bucket ===================================
__global__ void k_scan4(int* __restrict__ ib)
{
    const int* cnt; int* rp; int* cur; int n;
    switch (blockIdx.x) {
        case 0: cnt = ib + OI_CNT_G1; rp = ib + OI_RP_G1; cur = ib + OI_CUR_G1; n = NG; break;
        case 1: cnt = ib + OI_CNT_G2; rp = ib + OI_RP_G2; cur = ib + OI_CUR_G2; n = NG; break;
        case 2: cnt = ib + OI_CNT_U;  rp = ib + OI_RP_U;  cur = ib + OI_CUR_U;  n = NU; break;
        default: cnt = ib + OI_CNT_I; rp = ib + OI_RP_I;  cur = ib + OI_CUR_I;  n = NI; break;
    }
    __shared__ int ssum[1024];
    const int t = threadIdx.x;
    const int chunk = (n + 1023) / 1024;
    int beg = t * chunk;
    int end = beg + chunk; if (end > n) end = n;
    if (beg > n) beg = n;
    int s = 0;
    for (int i = beg; i < end; i++) s += cnt[i];
    ssum[t] = s;
    __syncthreads();
    for (int off = 1; off < 1024; off <<= 1) {
        int v = (t >= off) ? ssum[t - off] : 0;
        __syncthreads();
        ssum[t] += v;
        __syncthreads();
    }
    int prefix = (t == 0) ? 0 : ssum[t - 1];
    for (int i = beg; i < end; i++) {
        rp[i]  = prefix;
        cur[i] = prefix;
        prefix += cnt[i];
    }
    if (t == 1023) rp[n] = ssum[1023];
}

__global__ void k_bucket_all(const int* __restrict__ ug_src, const int* __restrict__ ug_dst,
                             const int* __restrict__ ui_src, const int* __restrict__ ui_dst,
                             const int* __restrict__ gi_src, const int* __restrict__ gi_dst,
                             int* __restrict__ ib)
{
    int t = blockIdx.x * blockDim.x + threadIdx.x;
    if (t < E_UG) {
        int p = atomicAdd(&ib[OI_CUR_G1 + ug_dst[t]], 1);
        ib[OI_COL_G1 + p] = ug_src[t];
    } else if (t < E_UG + E_GI) {
        int e = t - E_UG;
        int p = atomicAdd(&ib[OI_CUR_G2 + gi_src[e]], 1);
        ib[OI_COL_G2 + p] = gi_dst[e];
    } else if (t < E_UG + E_GI + E_UI) {
        int e = t - E_UG - E_GI;
        int p = atomicAdd(&ib[OI_CUR_U + ui_src[e]], 1);
        ib[OI_COL_U + p] = ui_dst[e];
    } else if (t < E_UG + E_GI + 2*E_UI) {
        int e = t - E_UG - E_GI - E_UI;
        int p = atomicAdd(&ib[OI_CUR_I + ui_dst[e]], 1);
        ib[OI_COL_I + p] = ui_src[e];
    }
}

// ======================= segment mean (fp16 in -> fp16 out) ==================
__device__ __forceinline__ void agg_row(const int* __restrict__ rp, const int* __restrict__ col,
                                        const __half* __restrict__ feat,
                                        __half* __restrict__ outp, int row, int lane)
{
    int beg = rp[row], end = rp[row + 1];
    float4 acc = make_float4(0.f, 0.f, 0.f, 0.f);
    const uint2* fv = (const uint2*)feat;
    int e = beg;
    for (; e + 8 <= end; e += 8) {
        int s[8];
#pragma unroll
        for (int q = 0; q < 8; q++) s[q] = __ldg(&col[e + q]);
        uint2 v[8];
#pragma unroll
        for (int q = 0; q < 8; q++) v[q] = __ldg(&fv[(size_t)s[q] * 32 + lane]);
#pragma unroll
        for (int q = 0; q < 8; q++) {
            float2 f0 = __half22float2(*(__half2*)&v[q].x);
            float2 f1 = __half22float2(*(__half2*)&v[q].y);
            acc.x += f0.x; acc.y += f0.y; acc.z += f1.x; acc.w += f1.y;
        }
    }
    for (; e < end; e++) {
        int sx = __ldg(&col[e]);
        uint2 v = __ldg(&fv[(size_t)sx * 32 + lane]);
        float2 f0 = __half22float2(*(__half2*)&v.x);
        float2 f1 = __half22float2(*(__half2*)&v.y);
        acc.x += f0.x; acc.y += f0.y; acc.z += f1.x; acc.w += f1.y;
    }
    float inv = (end > beg) ? 1.f / (float)(end - beg) : 0.f;
    __half2 p0 = __floats2half2_rn(acc.x * inv, acc.y * inv);
    __half2 p1 = __floats2half2_rn(acc.z * inv, acc.w * inv);
    uint2 o;
    o.x = *(uint32_t*)&p0;
    o.y = *(uint32_t*)&p1;
    ((uint2*)outp)[(size_t)row * 32 + lane] = o;
}

__global__ void k_agg_all(const int* __restrict__ ib, __half* __restrict__ hh)
{
    int w = (int)((blockIdx.x * blockDim.x + threadIdx.x) >> 5);
    int lane = threadIdx.x & 31;
    if (w < NU)
        agg_row(ib + OI_RP_U, ib + OI_COL_U, hh + OH_HI, hh + OH_AIU, w, lane);
    else if (w < NU + NI)
        agg_row(ib + OI_RP_I, ib + OI_COL_I, hh + OH_HU, hh + OH_AUI, w - NU, lane);
    else if (w < NU + NI + NG)
        agg_row(ib + OI_RP_G1, ib + OI_COL_G1, hh + OH_HU, hh + OH_AUG, w - NU - NI, lane);
    else if (w < NU + NI + 2*NG)
        agg_row(ib + OI_RP_G2, ib + OI_COL_G2, hh + OH_HI, hh + OH_AIG, w - NU - NI - NG, lane);
}

__global__ void k_agg_all2(const int* __restrict__ ib, __half* __restrict__ hh)
{
    int w = (int)((blockIdx.x * blockDim.x + threadIdx.x) >> 5);
    int lane = threadIdx.x & 31;
    if (w < NG)
        agg_row(ib + OI_RP_G1, ib + OI_COL_G1, hh + OH_HU1, hh + OH_BUG, w, lane);
    else if (w < 2*NG)
        agg_row(ib + OI_RP_G2, ib + OI_COL_G2, hh + OH_HI1, hh + OH_BIG, w - NG, lane);
}

// ======================= weight prep: combine + transpose -> fp16 + biases ===
__global__ void __launch_bounds__(256)
k_halfW(const float* __restrict__ W1l, const float* __restrict__ W1r,
        const float* __restrict__ W2l, const float* __restrict__ W2r,
        const float* __restrict__ b1, const float* __restrict__ b2,
        __half* __restrict__ dst9)
{
    const float* srcA; const float* srcB = nullptr;
    switch (blockIdx.z) {
        case 0: srcA = W1l + 3*HH; break;
        case 1: srcA = W1r + 1*HH; srcB = W1r + 3*HH; break;
        case 2: srcA = W1l + 2*HH; break;
        case 3: srcA = W1r + 2*HH; srcB = W1r + 4*HH; break;
        case 4: srcA = W1l + 0*HH; break;
        case 5: srcA = W1l + 5*HH; break;
        case 6: srcA = W2l + 0*HH; break;
        case 7: srcA = W2r + 0*HH; srcB = W2r + 5*HH; break;
        default: srcA = W2l + 5*HH; break;
    }
    __half* dst = dst9 + (size_t)blockIdx.z * HH;
    __shared__ float t[32][33];
    int nblk = blockIdx.x * 32;
    int kblk = blockIdx.y * 32;
    int tx = threadIdx.x, ty = threadIdx.y;
#pragma unroll
    for (int i = ty; i < 32; i += 8) {
        size_t gi = (size_t)(kblk + i) * H + nblk + tx;
        float v = srcA[gi];
        if (srcB) v += srcB[gi];
        t[i][tx] = v;
    }
    __syncthreads();
#pragma unroll
    for (int i = ty; i < 32; i += 8)
        dst[(size_t)(nblk + i) * H + kblk + tx] = __float2half(t[tx][i]);
    // combined biases (one block handles all 4 rows)
    if (blockIdx.z == 0 && blockIdx.x == 0 && blockIdx.y == 0 && ty == 0) {
#pragma unroll
        for (int q = 0; q < 4; q++) {
            int i = q * 32 + tx;
            g_f[0*H + i] = b1[1*H + i] + b1[3*H + i];
            g_f[1*H + i] = b1[2*H + i] + b1[4*H + i];
            g_f[2*H + i] = b1[0*H + i] + b1[5*H + i];
            g_f[3*H + i] = b2[0*H + i] + b2[5*H + i];
        }
    }
}

// pred_W [H, NI] fp32 -> [NI, H] fp16 (transposed)
__global__ void __launch_bounds__(256)
k_halfB(const float* __restrict__ W, __half* __restrict__ out)
{
    __shared__ float t[32][33];
    int nblk = blockIdx.x * 32;
    int kblk = blockIdx.y * 32;
    int tx = threadIdx.x, ty = threadIdx.y;
#pragma unroll
    for (int i = ty; i < 32; i += 8)
        t[i][tx] = W[(size_t)(kblk + i) * NI + nblk + tx];
    __syncthreads();
#pragma unroll
    for (int i = ty; i < 32; i += 8)
        out[(size_t)(nblk + i) * H + kblk + tx] = __float2half(t[tx][i]);
}

// ======================= common GEMM constants ===============================
#define PK   136
#define ROWB (PK * 2)          // 272 B per row
#define TILEB (128 * ROWB)     // 34816 B
#define HTILE (64 * ROWB)      // 17408 B

// ======================= layer-2 GEMM (3 fp16 terms) =========================
struct GemmArgs {
    const __half* A[3];
    const __half* W[3];
    const float* bias;
    __half* Ch;
    int M, nterms;
};

#define SMEM_GH (2 * TILEB)    // 69632

__global__ void __launch_bounds__(256, 1)
k_gemm_h(GemmArgs g)
{
    extern __shared__ char sm[];
    const int tid  = threadIdx.x;
    const int wid  = tid >> 5;
    const int lane = tid & 31;
    const int wm   = wid >> 1;
    const int wn   = wid & 1;
    const int m0   = blockIdx.x * 128;

    const uint32_t sbase  = smem_u32(sm);
    const uint32_t a_loff = (uint32_t)(lane & 15) * ROWB + (uint32_t)(lane >> 4) * 16;
    const uint32_t b_loff = (uint32_t)(((lane >> 4) * 8) + (lane & 7)) * ROWB
                          + (uint32_t)((lane >> 3) & 1) * 16;

    float c[2][8][4];
#pragma unroll
    for (int i = 0; i < 2; i++)
#pragma unroll
        for (int j = 0; j < 8; j++)
#pragma unroll
            for (int q = 0; q < 4; q++) c[i][j][q] = 0.f;

#pragma unroll 1
    for (int t = 0; t < g.nterms; t++) {
        const uint4* wsrc = (const uint4*)g.W[t];
        const uint4* asrc = (const uint4*)g.A[t];
#pragma unroll 4
        for (int i = tid; i < 2048; i += 256) {
            int row = i >> 4, cq = i & 15;
            uint32_t so = (uint32_t)row * ROWB + cq * 16;
            *(uint4*)(sm + so) = __ldg(&wsrc[row * 16 + cq]);
            uint4 va = make_uint4(0, 0, 0, 0);
            if (m0 + row < g.M) va = __ldg(&asrc[(size_t)(m0 + row) * 16 + cq]);
            *(uint4*)(sm + TILEB + so) = va;
        }
        __syncthreads();
        uint32_t aB = sbase + TILEB + (uint32_t)wm * 32 * ROWB + a_loff;
        uint32_t bB = sbase + (uint32_t)wn * 64 * ROWB + b_loff;
#pragma unroll
        for (int ks = 0; ks < 8; ks++) {
            uint32_t a[2][4], b[4][4];
            LDSM4(a[0], aB + ks * 32);
            LDSM4(a[1], aB + ks * 32 + 16 * ROWB);
#pragma unroll
            for (int q = 0; q < 4; q++)
                LDSM4(b[q], bB + ks * 32 + q * 16 * ROWB);
#pragma unroll
            for (int ma = 0; ma < 2; ma++)
#pragma unroll
                for (int na = 0; na < 8; na++)
                    MMA_F16(c[ma][na], a[ma],
                            b[na >> 1][(na & 1) * 2], b[na >> 1][(na & 1) * 2 + 1]);
        }
        __syncthreads();
    }

    const int gid = lane >> 2;
    const int tq  = (lane & 3) * 2;
#pragma unroll
    for (int ma = 0; ma < 2; ma++) {
#pragma unroll
        for (int na = 0; na < 8; na++) {
            int mrow = m0 + wm * 32 + ma * 16 + gid;
            int ncol = wn * 64 + na * 8 + tq;
            float2 bv = *(const float2*)(g.bias + ncol);
#pragma unroll
            for (int hrow = 0; hrow < 2; hrow++) {
                int mr = mrow + hrow * 8;
                if (mr >= g.M) continue;
                float v0 = fmaxf(c[ma][na][hrow*2 + 0] + bv.x, 0.f);
                float v1 = fmaxf(c[ma][na][hrow*2 + 1] + bv.y, 0.f);
                __half2 hv = __floats2half2_rn(v0, v1);
                *(__half2*)(g.Ch + (size_t)mr * H + ncol) = hv;
            }
        }
    }
}

// ======================= persistent layer-1 GEMM (fp16) ======================
struct LJob {
    const __half* Ah0; const __half* Ah1;
    const __half* W0;  const __half* W1;
    const float* bias;
    __half* Ch;
    int M, ntiles, ctaBase, nctas;
};
struct LJob3 { LJob j[3]; };

#define SMEM_GL (2 * TILEB + 2 * HTILE)   // 104448

__device__ __forceinline__ void loadA64(uint32_t dst, const uint4* ap,
                                        int m0_, int M, int tid)
{
#pragma unroll 2
    for (int i = tid; i < 1024; i += 256) {
        int row = i >> 4, cq = i & 15;
        int gr = m0_ + row;
        int sz = (gr < M) ? 16 : 0;
        if (gr >= M) gr = M - 1;
        CPA16(dst + (uint32_t)row * ROWB + cq * 16, ap + (size_t)gr * 16 + cq, sz);
    }
}

__global__ void __launch_bounds__(256, 1)
k_gemm_l(LJob3 js)
{
    extern __shared__ char sm[];
    const int tid  = threadIdx.x;
    const int wid  = tid >> 5;
    const int lane = tid & 31;
    const int wm   = wid >> 2;            // 0..1
    const int wn   = wid & 3;             // 0..3

    int ji = (blockIdx.x >= (uint32_t)js.j[2].ctaBase) ? 2
           : (blockIdx.x >= (uint32_t)js.j[1].ctaBase) ? 1 : 0;
    const LJob g = js.j[ji];
    const int idx = blockIdx.x - g.ctaBase;
    const int beg = (int)((long long)idx * g.ntiles / g.nctas);
    const int end = (int)((long long)(idx + 1) * g.ntiles / g.nctas);
    if (beg >= end) return;

    const uint32_t sbase = smem_u32(sm);
    const uint32_t sA    = sbase + 2 * TILEB;

    // resident W load: 2 fp16 tiles
    {
        const uint4* w0 = (const uint4*)g.W0;
        const uint4* w1 = (const uint4*)g.W1;
#pragma unroll 4
        for (int i = tid; i < 4096; i += 256) {
            int tl = i >> 11;
            int row = (i >> 4) & 127;
            int cq = i & 15;
            const uint4* src = tl ? w1 : w0;
            CPA16(sbase + (uint32_t)tl * TILEB + (uint32_t)row * ROWB + cq * 16,
                  src + (size_t)row * 16 + cq, 16);
        }
    }
    loadA64(sA, (const uint4*)g.Ah0, beg * 64, g.M, tid);
    CP_COMMIT();

    const uint32_t a_loff = (uint32_t)(lane & 15) * ROWB + (uint32_t)(lane >> 4) * 16;
    const uint32_t b_loff = (uint32_t)(((lane >> 4) * 8) + (lane & 7)) * ROWB
                          + (uint32_t)((lane >> 3) & 1) * 16;
    const int gid = lane >> 2;
    const int tq  = (lane & 3) * 2;

    float c[2][4][4];
    const int nit = (end - beg) * 2;
    int buf = 0;

#pragma unroll 1
    for (int it = 0; it < nit; it++) {
        const int tile = beg + (it >> 1);
        const int term = it & 1;
        if (it + 1 < nit) {
            int ntile = beg + ((it + 1) >> 1);
            int nterm = (it + 1) & 1;
            const uint4* ap = (const uint4*)(nterm ? g.Ah1 : g.Ah0);
            loadA64(sA + (uint32_t)(buf ^ 1) * HTILE, ap, ntile * 64, g.M, tid);
            CP_COMMIT();
            CP_WAIT1();
        } else {
            CP_WAIT0();
        }
        __syncthreads();

        if (term == 0) {
#pragma unroll
            for (int i = 0; i < 2; i++)
#pragma unroll
                for (int j = 0; j < 4; j++)
#pragma unroll
                    for (int q = 0; q < 4; q++) c[i][j][q] = 0.f;
        }

        uint32_t aB = sA + (uint32_t)buf * HTILE + (uint32_t)wm * 32 * ROWB + a_loff;
        uint32_t bB = sbase + (uint32_t)term * TILEB + (uint32_t)wn * 32 * ROWB + b_loff;
#pragma unroll
        for (int ks = 0; ks < 8; ks++) {
            uint32_t a[2][4], b[2][4];
            LDSM4(a[0], aB + ks * 32);
            LDSM4(a[1], aB + ks * 32 + 16 * ROWB);
            LDSM4(b[0], bB + ks * 32);
            LDSM4(b[1], bB + ks * 32 + 16 * ROWB);
#pragma unroll
            for (int ma = 0; ma < 2; ma++)
#pragma unroll
                for (int na = 0; na < 4; na++)
                    MMA_F16(c[ma][na], a[ma],
                            b[na >> 1][(na & 1) * 2], b[na >> 1][(na & 1) * 2 + 1]);
        }

        if (term == 1) {
            int m0_ = tile * 64;
#pragma unroll
            for (int ma = 0; ma < 2; ma++) {
#pragma unroll
                for (int na = 0; na < 4; na++) {
                    int mrow = m0_ + wm * 32 + ma * 16 + gid;
                    int ncol = wn * 32 + na * 8 + tq;
                    float2 bv = *(const float2*)(g.bias + ncol);
#pragma unroll
                    for (int hrow = 0; hrow < 2; hrow++) {
                        int mr = mrow + hrow * 8;
                        if (mr >= g.M) continue;
                        float v0 = fmaxf(c[ma][na][hrow*2 + 0] + bv.x, 0.f);
                        float v1 = fmaxf(c[ma][na][hrow*2 + 1] + bv.y, 0.f);
                        __half2 hv = __floats2half2_rn(v0, v1);
                        *(__half2*)(g.Ch + (size_t)mr * H + ncol) = hv;
                    }
                }
            }
        }
        __syncthreads();
        buf ^= 1;
    }
}

// ======================= persistent fp16 pred GEMM ===========================
#define NTN ((NI + 127) / 128)    // 157
#define NTM ((NG + 127) / 128)    // 40
#define NT_TOT (NTN * NTM)        // 6280
#define NCTA_PRED 148
#define SMEM_PREDH (3 * TILEB)    // 104448

__device__ __forceinline__ void pred_load1(uint32_t dst, const uint4* gp,
                                           int r0_, int rmax, int tid)
{
#pragma unroll 4
    for (int i = tid; i < 2048; i += 256) {
        int row = i >> 4, cq = i & 15;
        int gr = r0_ + row;
        int sz = (gr < rmax) ? 16 : 0;
        if (gr >= rmax) gr = rmax - 1;
        CPA16(dst + (uint32_t)row * ROWB + cq * 16, gp + (size_t)gr * 16 + cq, sz);
    }
}

__global__ void __launch_bounds__(256, 1)
k_mma_pred(const __half* __restrict__ A, const __half* __restrict__ B,
           const float* __restrict__ bias, float* __restrict__ out)
{
    extern __shared__ char sm[];
    const int tid  = threadIdx.x;
    const int wid  = tid >> 5;
    const int lane = tid & 31;
    const int wm   = wid >> 1;
    const int wn   = wid & 1;

    const uint32_t sbase = smem_u32(sm);
    const uint32_t sB    = sbase + TILEB;

    const uint4* gA = (const uint4*)A;
    const uint4* gB = (const uint4*)B;

    const int beg = (int)((long long)blockIdx.x * NT_TOT / NCTA_PRED);
    const int end = (int)((long long)(blockIdx.x + 1) * NT_TOT / NCTA_PRED);

    const uint32_t a_loff = (uint32_t)(lane & 15) * ROWB + (uint32_t)(lane >> 4) * 16;
    const uint32_t b_loff = (uint32_t)(((lane >> 4) * 8) + (lane & 7)) * ROWB
                          + (uint32_t)((lane >> 3) & 1) * 16;
    const int gid = lane >> 2;
    const int tq  = (lane & 3) * 2;

    int cur_m = -1;
    int buf = 0;

#pragma unroll 1
    for (int t = beg; t < end; ++t) {
        int tm = t / NTN, tn = t - tm * NTN;
        if (tm != cur_m) {
            CP_WAIT0();
            __syncthreads();
            pred_load1(sbase, gA, tm * 128, NG, tid);
            pred_load1(sB, gB, tn * 128, NI, tid);
            CP_COMMIT();
            cur_m = tm;
            buf = 0;
            if (t + 1 < end && (t + 1) / NTN == cur_m) {
                pred_load1(sB + TILEB, gB, (tn + 1) * 128, NI, tid);
                CP_COMMIT();
                CP_WAIT1();
            } else {
                CP_WAIT0();
            }
            __syncthreads();
        } else {
            if (t + 1 < end && (t + 1) / NTN == cur_m) {
                pred_load1(sB + (uint32_t)(buf ^ 1) * TILEB, gB, (tn + 1) * 128, NI, tid);
                CP_COMMIT();
                CP_WAIT1();
            } else {
                CP_WAIT0();
            }
            __syncthreads();
        }

        float c[2][8][4];
#pragma unroll
        for (int i = 0; i < 2; i++)
#pragma unroll
            for (int j = 0; j < 8; j++)
#pragma unroll
                for (int q = 0; q < 4; q++) c[i][j][q] = 0.f;

        uint32_t aB = sbase + (uint32_t)wm * 32 * ROWB + a_loff;
        uint32_t bB = sB + (uint32_t)buf * TILEB + (uint32_t)wn * 64 * ROWB + b_loff;
#pragma unroll
        for (int ks = 0; ks < 8; ks++) {
            uint32_t a[2][4], b[4][4];
            LDSM4(a[0], aB + ks * 32);
            LDSM4(a[1], aB + ks * 32 + 16 * ROWB);
#pragma unroll
            for (int q = 0; q < 4; q++)
                LDSM4(b[q], bB + ks * 32 + q * 16 * ROWB);
#pragma unroll
            for (int ma = 0; ma < 2; ma++)
#pragma unroll
                for (int na = 0; na < 8; na++)
                    MMA_F16(c[ma][na], a[ma],
                            b[na >> 1][(na & 1) * 2], b[na >> 1][(na & 1) * 2 + 1]);
        }

        int m0_ = tm * 128, n0_ = tn * 128;
#pragma unroll
        for (int ma = 0; ma < 2; ma++) {
#pragma unroll
            for (int na = 0; na < 8; na++) {
                int mrow = m0_ + wm * 32 + ma * 16 + gid;
                int ncol = n0_ + wn * 64 + na * 8 + tq;
                if (ncol >= NI) continue;
                float2 bv = *(const float2*)(bias + ncol);
                if (mrow < NG) {
                    float2 v = make_float2(c[ma][na][0] + bv.x, c[ma][na][1] + bv.y);
                    *(float2*)(out + (size_t)mrow * NI + ncol) = v;
                }
                if (mrow + 8 < NG) {
                    float2 v = make_float2(c[ma][na][2] + bv.x, c[ma][na][3] + bv.y);
                    *(float2*)(out + (size_t)(mrow + 8) * NI + ncol) = v;
                }
            }
        }
        __syncthreads();
        buf ^= 1;
    }
}

// ---------------------------------------------------------------------------
extern "C" void kernel_launch(void* const* d_in, const int* in_sizes, int n_in,
                              void* d_out, int out_size)
{
    const int*   x_user   = (const int*)  d_in[1];
    const int*   x_item   = (const int*)  d_in[2];
    const float* emb_user = (const float*)d_in[4];
    const float* emb_item = (const float*)d_in[5];
    const float* W1l      = (const float*)d_in[6];
    const float* W1r      = (const float*)d_in[7];
    const float* b1       = (const float*)d_in[8];
    const float* W2l      = (const float*)d_in[9];
    const float* W2r      = (const float*)d_in[10];
    const float* b2       = (const float*)d_in[11];
    const float* pred_W   = (const float*)d_in[12];
    const float* pred_b   = (const float*)d_in[13];
    const int*   ug_src   = (const int*)  d_in[14];
    const int*   ug_dst   = (const int*)  d_in[15];
    const int*   ui_src   = (const int*)  d_in[16];
    const int*   ui_dst   = (const int*)  d_in[17];
    const int*   gi_src   = (const int*)  d_in[18];
    const int*   gi_dst   = (const int*)  d_in[19];
    float* out = (float*)d_out;

    float* fb = nullptr; int* ib = nullptr; __half* hh = nullptr;
    cudaGetSymbolAddress((void**)&fb, g_f);
    cudaGetSymbolAddress((void**)&ib, g_i);
    cudaGetSymbolAddress((void**)&hh, g_h);

    cudaFuncSetAttribute(k_gemm_h, cudaFuncAttributeMaxDynamicSharedMemorySize, SMEM_GH);
    cudaFuncSetAttribute(k_gemm_l, cudaFuncAttributeMaxDynamicSharedMemorySize, SMEM_GL);
    cudaFuncSetAttribute(k_mma_pred, cudaFuncAttributeMaxDynamicSharedMemorySize, SMEM_PREDH);

    // (1) zero degree counts
    cudaMemsetAsync(ib + OI_CNT_G1, 0, (size_t)CNT_TOTAL * sizeof(int));

    // (2) gather fp16 + degree counts (merged)
    {
        int tot = (NU + NI) * 32;   // > edge total, covers both
        k_front<<<(tot + 255) / 256, 256>>>(emb_user, x_user, emb_item, x_item,
                                            ug_dst, gi_src, ui_src, ui_dst, hh, ib);
    }

    // (3) CSR row pointers, (4) bucket
    k_scan4<<<4, 1024>>>(ib);
    {
        int tot = E_UG + E_GI + 2 * E_UI;
        k_bucket_all<<<(tot + 255) / 256, 256>>>(ug_src, ug_dst, ui_src, ui_dst,
                                                 gi_src, gi_dst, ib);
    }

    // (5) layer-1 aggregations  <-- ncu capture slot
    {
        int warps = NU + NI + 2 * NG;
        k_agg_all<<<(warps + 7) / 8, 256>>>(ib, hh);
    }

    // (6) weight prep: combine+transpose fp16 + biases; (7) pred_W fp16
    k_halfW<<<dim3(4, 4, 9), dim3(32, 8)>>>(W1l, W1r, W2l, W2r, b1, b2, hh + OH_W);
    k_halfB<<<dim3(NI / 32, H / 32), dim3(32, 8)>>>(pred_W, hh + OH_PW);

    // (8) layer-1 GEMMs: one persistent launch, 3 jobs (fp16 single pass)
    {
        LJob3 js;
        js.j[0].Ah0 = hh + OH_AIU; js.j[0].Ah1 = hh + OH_HU;
        js.j[0].W0 = hh + OH_W + SL_W1L3*HH; js.j[0].W1 = hh + OH_W + SL_WC0*HH;
        js.j[0].bias = fb + 0*H; js.j[0].Ch = hh + OH_HU1;
        js.j[0].M = NU; js.j[0].ntiles = (NU + 63) / 64;
        js.j[0].ctaBase = 0;   js.j[0].nctas = 118;
        js.j[1].Ah0 = hh + OH_AUI; js.j[1].Ah1 = hh + OH_HI;
        js.j[1].W0 = hh + OH_W + SL_W1L2*HH; js.j[1].W1 = hh + OH_W + SL_WC1*HH;
        js.j[1].bias = fb + 1*H; js.j[1].Ch = hh + OH_HI1;
        js.j[1].M = NI; js.j[1].ntiles = (NI + 63) / 64;
        js.j[1].ctaBase = 118; js.j[1].nctas = 24;
        js.j[2].Ah0 = hh + OH_AUG; js.j[2].Ah1 = hh + OH_AIG;
        js.j[2].W0 = hh + OH_W + SL_W1L0*HH; js.j[2].W1 = hh + OH_W + SL_W1L5*HH;
        js.j[2].bias = fb + 2*H; js.j[2].Ch = hh + OH_HG1;
        js.j[2].M = NG; js.j[2].ntiles = (NG + 63) / 64;
        js.j[2].ctaBase = 142; js.j[2].nctas = 6;
        k_gemm_l<<<148, 256, SMEM_GL>>>(js);
    }

    // (9) layer-2 aggregations
    k_agg_all2<<<(2 * NG + 7) / 8, 256>>>(ib, hh);

    // (10) layer-2 group GEMM (3 fp16 terms) -> REP fp16
    {
        GemmArgs a;
        a.A[0] = hh + OH_BUG; a.W[0] = hh + OH_W + SL_W2L0*HH;
        a.A[1] = hh + OH_HG1; a.W[1] = hh + OH_W + SL_WC2*HH;
        a.A[2] = hh + OH_BIG; a.W[2] = hh + OH_W + SL_W2L5*HH;
        a.bias = fb + 3*H;
        a.Ch = hh + OH_REP;
        a.M = NG; a.nterms = 3;
        k_gemm_h<<<(NG + 127) / 128, 256, SMEM_GH>>>(a);
    }

    // (11) persistent fp16 prediction GEMM
    k_mma_pred<<<NCTA_PRED, 256, SMEM_PREDH>>>(hh + OH_REP, hh + OH_PW, pred_b, out);
    (void)in_sizes; (void)n_in; (void)out_size;
}